// round 4
// baseline (speedup 1.0000x reference)
#include <cuda_runtime.h>
#include <cuda_bf16.h>
#include <cstdint>

#define NT   8192
#define DD   1024
#define GHA  512
#define GHB  256
#define NE   8
#define HH   2048
#define MAX_MTILES 136

typedef __nv_bfloat16 bf16;

// ---------------- scratch ---------------------------------------------------
__device__ bf16  g_xhi[NT * DD],  g_xlo[NT * DD];
__device__ bf16  g_h1hi[NT * GHA], g_h1lo[NT * GHA];
__device__ float g_h2[NT * GHB];
__device__ bf16  g_w1hi[GHA * DD], g_w1lo[GHA * DD];
__device__ bf16  g_w2hi[GHB * GHA], g_w2lo[GHB * GHA];
__device__ float g_wval[NT * 2];
__device__ int   g_cnt[NE];
__device__ int   g_list[NE * NT];
__device__ float g_pair[(size_t)NT * 2 * HH];

// int8 limb data
__device__ int8_t g_xq0[NT * DD],  g_xq1[NT * DD];
__device__ float  g_sx[NT];
__device__ int8_t g_ewq0[(size_t)NE * HH * DD], g_ewq1[(size_t)NE * HH * DD]; // [E][H][D]
__device__ float  g_sew[NE * HH];
__device__ int8_t g_owq0[(size_t)DD * HH], g_owq1[(size_t)DD * HH];           // [D][H]
__device__ float  g_sow[DD];
__device__ int8_t g_mq0[(size_t)NT * HH], g_mq1[(size_t)NT * HH];             // [T][H]
__device__ float  g_sm[NT];

// ---------------- PTX helpers (sm_80+ baseline only) ------------------------
__device__ __forceinline__ uint32_t smem_u32(const void* p) {
    uint32_t a;
    asm("{ .reg .u64 t; cvta.to.shared.u64 t, %1; cvt.u32.u64 %0, t; }" : "=r"(a) : "l"(p));
    return a;
}
__device__ __forceinline__ void cp16(uint32_t s, const void* g) {
    asm volatile("cp.async.cg.shared.global [%0], [%1], 16;" :: "r"(s), "l"(g));
}
#define CP_COMMIT() asm volatile("cp.async.commit_group;" ::: "memory")
#define CP_WAIT1()  asm volatile("cp.async.wait_group 1;" ::: "memory")
#define CP_WAIT0()  asm volatile("cp.async.wait_group 0;" ::: "memory")

__device__ __forceinline__ void ldsm_x4(uint32_t* r, uint32_t a) {
    asm volatile("ldmatrix.sync.aligned.m8n8.x4.shared.b16 {%0,%1,%2,%3}, [%4];"
        : "=r"(r[0]), "=r"(r[1]), "=r"(r[2]), "=r"(r[3]) : "r"(a));
}
__device__ __forceinline__ void ldsm_x2(uint32_t* r, uint32_t a) {
    asm volatile("ldmatrix.sync.aligned.m8n8.x2.shared.b16 {%0,%1}, [%2];"
        : "=r"(r[0]), "=r"(r[1]) : "r"(a));
}
__device__ __forceinline__ void mma_bf16(float* c, const uint32_t* a, const uint32_t* b) {
    asm volatile("mma.sync.aligned.m16n8k16.row.col.f32.bf16.bf16.f32 "
        "{%0,%1,%2,%3}, {%4,%5,%6,%7}, {%8,%9}, {%0,%1,%2,%3};"
        : "+f"(c[0]), "+f"(c[1]), "+f"(c[2]), "+f"(c[3])
        : "r"(a[0]), "r"(a[1]), "r"(a[2]), "r"(a[3]), "r"(b[0]), "r"(b[1]));
}
__device__ __forceinline__ void mma_s8(int* c, const uint32_t* a, const uint32_t* b) {
    asm volatile("mma.sync.aligned.m16n8k32.row.col.s32.s8.s8.s32 "
        "{%0,%1,%2,%3}, {%4,%5,%6,%7}, {%8,%9}, {%0,%1,%2,%3};"
        : "+r"(c[0]), "+r"(c[1]), "+r"(c[2]), "+r"(c[3])
        : "r"(a[0]), "r"(a[1]), "r"(a[2]), "r"(a[3]), "r"(b[0]), "r"(b[1]));
}

// ---------------- small kernels ---------------------------------------------
__global__ void zero_cnt_kernel() { if (threadIdx.x < NE) g_cnt[threadIdx.x] = 0; }

__global__ void split_x_kernel(const float* __restrict__ x) {
    int i = blockIdx.x * blockDim.x + threadIdx.x;
    float v = x[i];
    bf16 h = __float2bfloat16(v);
    g_xhi[i] = h;
    g_xlo[i] = __float2bfloat16(v - __bfloat162float(h));
}

// in [R][C] fp32 (+z) -> out [C][R] bf16 hi/lo (for gating weights only)
__global__ void tsplit_kernel(const float* __restrict__ in, bf16* __restrict__ ohi,
                              bf16* __restrict__ olo, int R, int C) {
    __shared__ float t[32][33];
    size_t zoff = (size_t)blockIdx.z * R * C;
    in += zoff; ohi += zoff; olo += zoff;
    int c0 = blockIdx.x * 32, r0 = blockIdx.y * 32;
    for (int i = threadIdx.y; i < 32; i += 8)
        t[i][threadIdx.x] = in[(size_t)(r0 + i) * C + c0 + threadIdx.x];
    __syncthreads();
    for (int i = threadIdx.y; i < 32; i += 8) {
        float v = t[threadIdx.x][i];
        bf16 h = __float2bfloat16(v);
        size_t o = (size_t)(c0 + i) * R + r0 + threadIdx.x;
        ohi[o] = h;
        olo[o] = __float2bfloat16(v - __bfloat162float(h));
    }
}

// ---------------- int8 2-limb quantization -----------------------------------
__device__ __forceinline__ void quant2(float v, float s, float inv, int8_t& a, int8_t& b) {
    float q = rintf(v * inv);
    a = (int8_t)q;
    float r = v - s * q;
    b = (int8_t)fminf(127.f, fmaxf(-127.f, rintf(r * inv * 256.f)));
}

// row-major rows: quantize each row of length K
__global__ void quant_row_kernel(const float* __restrict__ in, int8_t* __restrict__ q0,
                                 int8_t* __restrict__ q1, float* __restrict__ scale, int K) {
    int row = blockIdx.x;
    const float* r = in + (size_t)row * K;
    __shared__ float red[256];
    float mx = 0.f;
    for (int i = threadIdx.x; i < K / 4; i += 256) {
        float4 v = ((const float4*)r)[i];
        mx = fmaxf(mx, fmaxf(fmaxf(fabsf(v.x), fabsf(v.y)), fmaxf(fabsf(v.z), fabsf(v.w))));
    }
    red[threadIdx.x] = mx; __syncthreads();
    for (int s = 128; s; s >>= 1) {
        if (threadIdx.x < s) red[threadIdx.x] = fmaxf(red[threadIdx.x], red[threadIdx.x + s]);
        __syncthreads();
    }
    float m = red[0];
    float s = (m > 0.f) ? m * (1.f / 127.f) : 1.f;
    float inv = 1.f / s;
    if (threadIdx.x == 0) scale[row] = s;
    for (int i = threadIdx.x; i < K / 4; i += 256) {
        float4 v = ((const float4*)r)[i];
        char4 a, b;
        quant2(v.x, s, inv, (int8_t&)a.x, (int8_t&)b.x);
        quant2(v.y, s, inv, (int8_t&)a.y, (int8_t&)b.y);
        quant2(v.z, s, inv, (int8_t&)a.z, (int8_t&)b.z);
        quant2(v.w, s, inv, (int8_t&)a.w, (int8_t&)b.w);
        ((char4*)q0)[(size_t)row * (K / 4) + i] = a;
        ((char4*)q1)[(size_t)row * (K / 4) + i] = b;
    }
}

// column max of in[z][r][c] over r -> scale[z*C+c]
__global__ void colmax_kernel(const float* __restrict__ in, float* __restrict__ scale,
                              int R, int C) {
    int z = blockIdx.y;
    int c = blockIdx.x * 256 + threadIdx.x;
    const float* p = in + (size_t)z * R * C + c;
    float mx = 0.f;
    for (int r = 0; r < R; r++) mx = fmaxf(mx, fabsf(p[(size_t)r * C]));
    scale[z * C + c] = (mx > 0.f) ? mx * (1.f / 127.f) : 1.f;
}

// transpose + quantize: in[z][r][c] -> q[z][c][r], per-output-row scale[z*C+c]
__global__ void quantT_kernel(const float* __restrict__ in, int8_t* __restrict__ q0,
                              int8_t* __restrict__ q1, const float* __restrict__ scale,
                              int R, int C) {
    __shared__ float t[32][33];
    int z = blockIdx.z;
    const float* inz = in + (size_t)z * R * C;
    size_t qoff = (size_t)z * R * C;
    int c0 = blockIdx.x * 32, r0 = blockIdx.y * 32;
    for (int i = threadIdx.y; i < 32; i += 8)
        t[i][threadIdx.x] = inz[(size_t)(r0 + i) * C + c0 + threadIdx.x];
    __syncthreads();
    for (int i = threadIdx.y; i < 32; i += 8) {
        float v = t[threadIdx.x][i];
        float s = scale[z * C + c0 + i];
        float inv = 1.f / s;
        size_t o = qoff + (size_t)(c0 + i) * R + r0 + threadIdx.x;
        int8_t a, b;
        quant2(v, s, inv, a, b);
        q0[o] = a; q1[o] = b;
    }
}

// ---------------- gating: logits -> top2 -> routing --------------------------
__global__ void gating_kernel(const int* __restrict__ ftypes,
                              const float* __restrict__ gw3, const float* __restrict__ gb3,
                              const float* __restrict__ temb, const float* __restrict__ tw,
                              const float* __restrict__ tb) {
    int gwarp = (blockIdx.x * blockDim.x + threadIdx.x) >> 5;
    int lane = threadIdx.x & 31;
    if (gwarp >= NT) return;
    const int t = gwarp;
    float acc[NE] = {};
    const float* hrow = g_h2 + (size_t)t * GHB;
    for (int j = lane; j < GHB; j += 32) {
        float hv = hrow[j];
        const float* g = gw3 + j * NE;
        #pragma unroll
        for (int e = 0; e < NE; e++) acc[e] = fmaf(hv, g[e], acc[e]);
    }
    int ftv = ftypes[t];
    const float* te = temb + ftv * 128;
    for (int j = lane; j < 128; j += 32) {
        float tv = te[j];
        const float* w = tw + j * NE;
        #pragma unroll
        for (int e = 0; e < NE; e++) acc[e] = fmaf(tv, w[e], acc[e]);
    }
    #pragma unroll
    for (int off = 16; off; off >>= 1)
        #pragma unroll
        for (int e = 0; e < NE; e++) acc[e] += __shfl_xor_sync(0xffffffffu, acc[e], off);
    if (lane == 0) {
        float logits[NE];
        #pragma unroll
        for (int e = 0; e < NE; e++) logits[e] = acc[e] + gb3[e] + tb[e];
        int i0 = 0;
        #pragma unroll
        for (int e = 1; e < NE; e++) if (logits[e] > logits[i0]) i0 = e;
        int i1 = (i0 == 0) ? 1 : 0;
        #pragma unroll
        for (int e = 0; e < NE; e++) {
            if (e == i0 || e == i1) continue;
            if (logits[e] > logits[i1]) i1 = e;
        }
        float r = expf(logits[i1] - logits[i0]);
        float inv = 1.f / (1.f + r);
        g_wval[t * 2 + 0] = inv;
        g_wval[t * 2 + 1] = r * inv;
        int s0 = atomicAdd(&g_cnt[i0], 1); g_list[i0 * NT + s0] = t * 2 + 0;
        int s1 = atomicAdd(&g_cnt[i1], 1); g_list[i1 * NT + s1] = t * 2 + 1;
    }
}

// ---------------- bf16-split MMA GEMM (gating only) --------------------------
#define EPI_RELU_SPLIT 0
#define EPI_RELU_F32   1

#define ROWB      80
#define TILES_OFF 1024
#define STAGE_SZ  40960
#define OA_HI 0
#define OA_LO 10240
#define OB_HI 20480
#define OB_LO 30720
#define SMEM_BF16 (TILES_OFF + 2 * STAGE_SZ)

template<int MODE>
__global__ void __launch_bounds__(256, 1) mma_gemm(
    const bf16* __restrict__ Ahi, const bf16* __restrict__ Alo,
    const bf16* __restrict__ Bhi, const bf16* __restrict__ Blo,
    const float* __restrict__ bias,
    float* __restrict__ outf, bf16* __restrict__ outhi, bf16* __restrict__ outlo,
    int N, int K) {
    extern __shared__ char smem[];
    const int tid = threadIdx.x, lane = tid & 31, wid = tid >> 5;
    const int wm = wid >> 2, wn = wid & 3;
    const int nb = blockIdx.x;
    const int mtile = blockIdx.y;

    const uint32_t sb = smem_u32(smem) + TILES_OFF;

    const int seg = tid & 3;
    const int r0 = tid >> 2;
    const int r1 = r0 + 64;
    size_t ar0 = (size_t)mtile * 128 + r0;
    size_t ar1 = (size_t)mtile * 128 + r1;
    size_t br0 = (size_t)nb * 128 + r0;
    size_t br1 = (size_t)nb * 128 + r1;
    const bf16* pAh0 = Ahi + ar0 * K + seg * 8;
    const bf16* pAh1 = Ahi + ar1 * K + seg * 8;
    const bf16* pAl0 = Alo + ar0 * K + seg * 8;
    const bf16* pAl1 = Alo + ar1 * K + seg * 8;
    const bf16* pBh0 = Bhi + br0 * K + seg * 8;
    const bf16* pBh1 = Bhi + br1 * K + seg * 8;
    const bf16* pBl0 = Blo + br0 * K + seg * 8;
    const bf16* pBl1 = Blo + br1 * K + seg * 8;
    const uint32_t so0 = r0 * ROWB + seg * 16;
    const uint32_t so1 = r1 * ROWB + seg * 16;

    float acc[4][4][4] = {};
    const int niter = K >> 5;

    {
        cp16(sb + OA_HI + so0, pAh0); cp16(sb + OA_HI + so1, pAh1);
        cp16(sb + OA_LO + so0, pAl0); cp16(sb + OA_LO + so1, pAl1);
        cp16(sb + OB_HI + so0, pBh0); cp16(sb + OB_HI + so1, pBh1);
        cp16(sb + OB_LO + so0, pBl0); cp16(sb + OB_LO + so1, pBl1);
        CP_COMMIT();
    }

    for (int it = 0; it < niter; it++) {
        if (it + 1 < niter) {
            const uint32_t st = sb + ((it + 1) & 1) * STAGE_SZ;
            const int ko = (it + 1) << 5;
            cp16(st + OA_HI + so0, pAh0 + ko); cp16(st + OA_HI + so1, pAh1 + ko);
            cp16(st + OA_LO + so0, pAl0 + ko); cp16(st + OA_LO + so1, pAl1 + ko);
            cp16(st + OB_HI + so0, pBh0 + ko); cp16(st + OB_HI + so1, pBh1 + ko);
            cp16(st + OB_LO + so0, pBl0 + ko); cp16(st + OB_LO + so1, pBl1 + ko);
            CP_COMMIT();
            CP_WAIT1();
        } else {
            CP_WAIT0();
        }
        __syncthreads();

        const uint32_t st = sb + (it & 1) * STAGE_SZ;
        #pragma unroll
        for (int ks = 0; ks < 2; ks++) {
            uint32_t ah[4][4], al[4][4], bh[4][2], bl[4][2];
            const int acol = (ks * 16 + (lane >> 4) * 8) * 2;
            const int arow = wm * 64 + (lane & 15);
            #pragma unroll
            for (int mt = 0; mt < 4; mt++) {
                uint32_t ad = st + (arow + mt * 16) * ROWB + acol;
                ldsm_x4(ah[mt], ad + OA_HI);
                ldsm_x4(al[mt], ad + OA_LO);
            }
            const int bcol = (ks * 16 + ((lane >> 3) & 1) * 8) * 2;
            const int brow = wn * 32 + (lane & 7);
            #pragma unroll
            for (int nt = 0; nt < 4; nt++) {
                uint32_t bd = st + (brow + nt * 8) * ROWB + bcol;
                ldsm_x2(bh[nt], bd + OB_HI);
                ldsm_x2(bl[nt], bd + OB_LO);
            }
            #pragma unroll
            for (int mt = 0; mt < 4; mt++)
                #pragma unroll
                for (int nt = 0; nt < 4; nt++) {
                    mma_bf16(acc[mt][nt], ah[mt], bh[nt]);
                    mma_bf16(acc[mt][nt], ah[mt], bl[nt]);
                    mma_bf16(acc[mt][nt], al[mt], bh[nt]);
                }
        }
        __syncthreads();
    }

    #pragma unroll
    for (int mt = 0; mt < 4; mt++) {
        const int mloc0 = wm * 64 + mt * 16 + (lane >> 2);
        #pragma unroll
        for (int half = 0; half < 2; half++) {
            const int mloc = mloc0 + half * 8;
            #pragma unroll
            for (int nt = 0; nt < 4; nt++) {
                const int c0 = nb * 128 + wn * 32 + nt * 8 + (lane & 3) * 2;
                float v0 = acc[mt][nt][half * 2 + 0] + bias[c0];
                float v1 = acc[mt][nt][half * 2 + 1] + bias[c0 + 1];
                size_t base = (size_t)(mtile * 128 + mloc) * N + c0;
                v0 = fmaxf(v0, 0.f); v1 = fmaxf(v1, 0.f);
                if (MODE == EPI_RELU_SPLIT) {
                    bf16 h0 = __float2bfloat16(v0), h1 = __float2bfloat16(v1);
                    outhi[base] = h0; outhi[base + 1] = h1;
                    outlo[base] = __float2bfloat16(v0 - __bfloat162float(h0));
                    outlo[base + 1] = __float2bfloat16(v1 - __bfloat162float(h1));
                } else {
                    outf[base] = v0; outf[base + 1] = v1;
                }
            }
        }
    }
}

// ---------------- int8 2-limb IMMA GEMM (expert + out-proj) ------------------
// C = sA(m)*sB(n)*(Q0a.Q0b + (Q0a.Q1b + Q1a.Q0b)/256) + bias
// A: [M,K] int8 K-major; B: [N,K] int8 K-major. K-chunk = 64 per stage.
#define IEPI_SCATTER 0
#define IEPI_F32     1

#define ITILES_OFF 2048
#define ISTAGE_SZ  40960
#define IOA0 0
#define IOA1 10240
#define IOB0 20480
#define IOB1 30720
#define SMEM_I8 (ITILES_OFF + 2 * ISTAGE_SZ)

template<int MODE, bool GATHER>
__global__ void __launch_bounds__(256, 1) imma_gemm(
    const int8_t* __restrict__ Aq0, const int8_t* __restrict__ Aq1,
    const float* __restrict__ sA,
    const int8_t* __restrict__ Bq0, const int8_t* __restrict__ Bq1,
    const float* __restrict__ sB,
    const float* __restrict__ bias,
    float* __restrict__ outf, int N, int K) {
    extern __shared__ char smem[];
    int*   s_pid = (int*)smem;                 // 512
    int*   s_tok = (int*)(smem + 512);         // 512
    float* s_sa  = (float*)(smem + 1024);      // 512
    float* s_sb  = (float*)(smem + 1536);      // 512
    const int tid = threadIdx.x, lane = tid & 31, wid = tid >> 5;
    const int wm = wid >> 2, wn = wid & 3;
    const int nb = blockIdx.x;

    int mtile = blockIdx.y, e = 0;
    if (GATHER) {
        int flat = blockIdx.y, base = 0, cnt = 0;
        bool found = false;
        #pragma unroll
        for (int i = 0; i < NE; i++) {
            int c = g_cnt[i];
            int tiles = (c + 127) >> 7;
            if (!found && flat < base + tiles) { e = i; mtile = flat - base; cnt = c; found = true; }
            base += tiles;
        }
        if (!found) return;
        if (tid < 128) {
            int idx = mtile * 128 + tid;
            int pid = (idx < cnt) ? g_list[e * NT + idx] : -1;
            s_pid[tid] = pid;
            s_tok[tid] = (pid >= 0) ? (pid >> 1) : 0;
        }
        Bq0 += (size_t)e * HH * DD;
        Bq1 += (size_t)e * HH * DD;
        sB  += (size_t)e * HH;
        bias += (size_t)e * HH;
        __syncthreads();
    }
    if (tid < 128) {
        s_sa[tid] = GATHER ? sA[s_tok[tid]] : sA[mtile * 128 + tid];
        s_sb[tid] = sB[nb * 128 + tid];
    }

    const uint32_t sb = smem_u32(smem) + ITILES_OFF;

    const int seg = tid & 3;
    const int r0 = tid >> 2;
    const int r1 = r0 + 64;
    size_t ar0 = GATHER ? (size_t)s_tok[r0] : ((size_t)mtile * 128 + r0);
    size_t ar1 = GATHER ? (size_t)s_tok[r1] : ((size_t)mtile * 128 + r1);
    size_t br0 = (size_t)nb * 128 + r0;
    size_t br1 = (size_t)nb * 128 + r1;
    const int8_t* pA00 = Aq0 + ar0 * K + seg * 16;
    const int8_t* pA01 = Aq0 + ar1 * K + seg * 16;
    const int8_t* pA10 = Aq1 + ar0 * K + seg * 16;
    const int8_t* pA11 = Aq1 + ar1 * K + seg * 16;
    const int8_t* pB00 = Bq0 + br0 * K + seg * 16;
    const int8_t* pB01 = Bq0 + br1 * K + seg * 16;
    const int8_t* pB10 = Bq1 + br0 * K + seg * 16;
    const int8_t* pB11 = Bq1 + br1 * K + seg * 16;
    const uint32_t so0 = r0 * ROWB + seg * 16;
    const uint32_t so1 = r1 * ROWB + seg * 16;

    int acc0[4][4][4] = {};
    int accX[4][4][4] = {};
    const int niter = K >> 6;

    {
        cp16(sb + IOA0 + so0, pA00); cp16(sb + IOA0 + so1, pA01);
        cp16(sb + IOA1 + so0, pA10); cp16(sb + IOA1 + so1, pA11);
        cp16(sb + IOB0 + so0, pB00); cp16(sb + IOB0 + so1, pB01);
        cp16(sb + IOB1 + so0, pB10); cp16(sb + IOB1 + so1, pB11);
        CP_COMMIT();
    }

    for (int it = 0; it < niter; it++) {
        if (it + 1 < niter) {
            const uint32_t st = sb + ((it + 1) & 1) * ISTAGE_SZ;
            const int ko = (it + 1) << 6;
            cp16(st + IOA0 + so0, pA00 + ko); cp16(st + IOA0 + so1, pA01 + ko);
            cp16(st + IOA1 + so0, pA10 + ko); cp16(st + IOA1 + so1, pA11 + ko);
            cp16(st + IOB0 + so0, pB00 + ko); cp16(st + IOB0 + so1, pB01 + ko);
            cp16(st + IOB1 + so0, pB10 + ko); cp16(st + IOB1 + so1, pB11 + ko);
            CP_COMMIT();
            CP_WAIT1();
        } else {
            CP_WAIT0();
        }
        __syncthreads();

        const uint32_t st = sb + (it & 1) * ISTAGE_SZ;
        #pragma unroll
        for (int ks = 0; ks < 2; ks++) {
            uint32_t a0[4][4], a1[4][4], b0[4][2], b1[4][2];
            const int acol = ks * 32 + (lane >> 4) * 16;
            const int arow = wm * 64 + (lane & 15);
            #pragma unroll
            for (int mt = 0; mt < 4; mt++) {
                uint32_t ad = st + (arow + mt * 16) * ROWB + acol;
                ldsm_x4(a0[mt], ad + IOA0);
                ldsm_x4(a1[mt], ad + IOA1);
            }
            const int bcol = ks * 32 + ((lane >> 3) & 1) * 16;
            const int brow = wn * 32 + (lane & 7);
            #pragma unroll
            for (int nt = 0; nt < 4; nt++) {
                uint32_t bd = st + (brow + nt * 8) * ROWB + bcol;
                ldsm_x2(b0[nt], bd + IOB0);
                ldsm_x2(b1[nt], bd + IOB1);
            }
            #pragma unroll
            for (int mt = 0; mt < 4; mt++)
                #pragma unroll
                for (int nt = 0; nt < 4; nt++) {
                    mma_s8(acc0[mt][nt], a0[mt], b0[nt]);
                    mma_s8(accX[mt][nt], a0[mt], b1[nt]);
                    mma_s8(accX[mt][nt], a1[mt], b0[nt]);
                }
        }
        __syncthreads();
    }

    #pragma unroll
    for (int mt = 0; mt < 4; mt++) {
        const int mloc0 = wm * 64 + mt * 16 + (lane >> 2);
        #pragma unroll
        for (int half = 0; half < 2; half++) {
            const int mloc = mloc0 + half * 8;
            int pid = 0;
            if (GATHER) { pid = s_pid[mloc]; if (pid < 0) continue; }
            const float sa = s_sa[mloc];
            #pragma unroll
            for (int nt = 0; nt < 4; nt++) {
                const int cl = wn * 32 + nt * 8 + (lane & 3) * 2;
                const int c0 = nb * 128 + cl;
                float sb0 = sa * s_sb[cl], sb1 = sa * s_sb[cl + 1];
                float v0 = sb0 * ((float)acc0[mt][nt][half * 2 + 0]
                                  + (float)accX[mt][nt][half * 2 + 0] * (1.f / 256.f)) + bias[c0];
                float v1 = sb1 * ((float)acc0[mt][nt][half * 2 + 1]
                                  + (float)accX[mt][nt][half * 2 + 1] * (1.f / 256.f)) + bias[c0 + 1];
                if (MODE == IEPI_SCATTER) {
                    float* dst = outf + (size_t)pid * HH + c0;
                    dst[0] = v0; dst[1] = v1;
                } else {
                    size_t base = (size_t)(mtile * 128 + mloc) * N + c0;
                    outf[base] = v0; outf[base + 1] = v1;
                }
            }
        }
    }
}

// ---------------- combine + fused per-token quantization ---------------------
// one block per token: moe = relu(w0*pair0 + w1*pair1) -> int8 limbs + scale
__global__ void combine_quant_kernel() {
    const int t = blockIdx.x;
    const float w0 = g_wval[2 * t], w1 = g_wval[2 * t + 1];
    const float* p0 = g_pair + (size_t)(2 * t) * HH;
    const float* p1 = g_pair + (size_t)(2 * t + 1) * HH;
    float vals[8];
    float mx = 0.f;
    #pragma unroll
    for (int i = 0; i < 8; i++) {
        int h = threadIdx.x + i * 256;
        float v = fmaxf(fmaf(w0, p0[h], w1 * p1[h]), 0.f);
        vals[i] = v;
        mx = fmaxf(mx, v);
    }
    __shared__ float red[256];
    red[threadIdx.x] = mx; __syncthreads();
    for (int s = 128; s; s >>= 1) {
        if (threadIdx.x < s) red[threadIdx.x] = fmaxf(red[threadIdx.x], red[threadIdx.x + s]);
        __syncthreads();
    }
    float m = red[0];
    float s = (m > 0.f) ? m * (1.f / 127.f) : 1.f;
    float inv = 1.f / s;
    if (threadIdx.x == 0) g_sm[t] = s;
    #pragma unroll
    for (int i = 0; i < 8; i++) {
        int h = threadIdx.x + i * 256;
        int8_t a, b;
        quant2(vals[i], s, inv, a, b);
        g_mq0[(size_t)t * HH + h] = a;
        g_mq1[(size_t)t * HH + h] = b;
    }
}

// ---------------- launch ------------------------------------------------------
extern "C" void kernel_launch(void* const* d_in, const int* in_sizes, int n_in,
                              void* d_out, int out_size) {
    const float* x    = (const float*)d_in[0];
    const int*   ft   = (const int*)  d_in[1];
    const float* gw1  = (const float*)d_in[2];
    const float* gb1  = (const float*)d_in[3];
    const float* gw2  = (const float*)d_in[4];
    const float* gb2  = (const float*)d_in[5];
    const float* gw3  = (const float*)d_in[6];
    const float* gb3  = (const float*)d_in[7];
    const float* temb = (const float*)d_in[8];
    const float* tw   = (const float*)d_in[9];
    const float* tb   = (const float*)d_in[10];
    const float* ew   = (const float*)d_in[11];
    const float* eb   = (const float*)d_in[12];
    const float* ow   = (const float*)d_in[13];
    const float* ob   = (const float*)d_in[14];
    float* out = (float*)d_out;

    bf16 *xhi, *xlo, *h1hi, *h1lo, *w1hi, *w1lo, *w2hi, *w2lo;
    float *h2, *pair;
    int8_t *xq0, *xq1, *ewq0, *ewq1, *owq0, *owq1, *mq0, *mq1;
    float *sx, *sew, *sow, *sm;
    cudaGetSymbolAddress((void**)&xhi, g_xhi);   cudaGetSymbolAddress((void**)&xlo, g_xlo);
    cudaGetSymbolAddress((void**)&h1hi, g_h1hi); cudaGetSymbolAddress((void**)&h1lo, g_h1lo);
    cudaGetSymbolAddress((void**)&w1hi, g_w1hi); cudaGetSymbolAddress((void**)&w1lo, g_w1lo);
    cudaGetSymbolAddress((void**)&w2hi, g_w2hi); cudaGetSymbolAddress((void**)&w2lo, g_w2lo);
    cudaGetSymbolAddress((void**)&h2, g_h2);     cudaGetSymbolAddress((void**)&pair, g_pair);
    cudaGetSymbolAddress((void**)&xq0, g_xq0);   cudaGetSymbolAddress((void**)&xq1, g_xq1);
    cudaGetSymbolAddress((void**)&ewq0, g_ewq0); cudaGetSymbolAddress((void**)&ewq1, g_ewq1);
    cudaGetSymbolAddress((void**)&owq0, g_owq0); cudaGetSymbolAddress((void**)&owq1, g_owq1);
    cudaGetSymbolAddress((void**)&mq0, g_mq0);   cudaGetSymbolAddress((void**)&mq1, g_mq1);
    cudaGetSymbolAddress((void**)&sx, g_sx);     cudaGetSymbolAddress((void**)&sew, g_sew);
    cudaGetSymbolAddress((void**)&sow, g_sow);   cudaGetSymbolAddress((void**)&sm, g_sm);

    cudaFuncSetAttribute(mma_gemm<EPI_RELU_SPLIT>, cudaFuncAttributeMaxDynamicSharedMemorySize, SMEM_BF16);
    cudaFuncSetAttribute(mma_gemm<EPI_RELU_F32>,   cudaFuncAttributeMaxDynamicSharedMemorySize, SMEM_BF16);
    cudaFuncSetAttribute(imma_gemm<IEPI_SCATTER, true>,  cudaFuncAttributeMaxDynamicSharedMemorySize, SMEM_I8);
    cudaFuncSetAttribute(imma_gemm<IEPI_F32,     false>, cudaFuncAttributeMaxDynamicSharedMemorySize, SMEM_I8);

    zero_cnt_kernel<<<1, 32>>>();

    // conversions
    split_x_kernel<<<(NT * DD) / 256, 256>>>(x);
    tsplit_kernel<<<dim3(GHA / 32, DD / 32, 1), dim3(32, 8)>>>(gw1, w1hi, w1lo, DD, GHA);
    tsplit_kernel<<<dim3(GHB / 32, GHA / 32, 1), dim3(32, 8)>>>(gw2, w2hi, w2lo, GHA, GHB);
    quant_row_kernel<<<NT, 256>>>(x, xq0, xq1, sx, DD);
    colmax_kernel<<<dim3(HH / 256, NE), 256>>>(ew, sew, DD, HH);
    quantT_kernel<<<dim3(HH / 32, DD / 32, NE), dim3(32, 8)>>>(ew, ewq0, ewq1, sew, DD, HH);
    colmax_kernel<<<dim3(DD / 256, 1), 256>>>(ow, sow, HH, DD);
    quantT_kernel<<<dim3(DD / 32, HH / 32, 1), dim3(32, 8)>>>(ow, owq0, owq1, sow, HH, DD);

    // gating MLP (bf16 3-term, high precision for routing)
    mma_gemm<EPI_RELU_SPLIT><<<dim3(GHA / 128, NT / 128), 256, SMEM_BF16>>>(
        xhi, xlo, w1hi, w1lo, gb1, nullptr, h1hi, h1lo, GHA, DD);
    mma_gemm<EPI_RELU_F32><<<dim3(GHB / 128, NT / 128), 256, SMEM_BF16>>>(
        h1hi, h1lo, w2hi, w2lo, gb2, h2, nullptr, nullptr, GHB, GHA);

    // routing
    gating_kernel<<<NT / 8, 256>>>(ft, gw3, gb3, temb, tw, tb);

    // expert grouped GEMM: int8 limbs, gathered A, scattered C
    imma_gemm<IEPI_SCATTER, true><<<dim3(HH / 128, MAX_MTILES), 256, SMEM_I8>>>(
        xq0, xq1, sx, ewq0, ewq1, sew, eb, pair, HH, DD);

    // combine + relu + quantize
    combine_quant_kernel<<<NT, 256>>>();

    // output projection: int8 limbs
    imma_gemm<IEPI_F32, false><<<dim3(DD / 128, NT / 128), 256, SMEM_I8>>>(
        mq0, mq1, sm, owq0, owq1, sow, ob, out, DD, HH);
}

// round 5
// speedup vs baseline: 2.4252x; 2.4252x over previous
#include <cuda_runtime.h>
#include <cuda_bf16.h>
#include <cstdint>

#define NT   8192
#define DD   1024
#define GHA  512
#define GHB  256
#define NE   8
#define HH   2048
#define MAX_MTILES 136

typedef __nv_bfloat16 bf16;

// ---------------- scratch ---------------------------------------------------
__device__ bf16  g_xhi[NT * DD],  g_xlo[NT * DD];
__device__ bf16  g_h1hi[NT * GHA], g_h1lo[NT * GHA];
__device__ float g_h2[NT * GHB];
__device__ bf16  g_w1hi[GHA * DD], g_w1lo[GHA * DD];       // [GHA][DD]
__device__ bf16  g_w2hi[GHB * GHA], g_w2lo[GHB * GHA];     // [GHB][GHA]
__device__ bf16  g_ewhi[(size_t)NE * HH * DD], g_ewlo[(size_t)NE * HH * DD]; // [E][H][D]
__device__ bf16  g_owhi[DD * HH], g_owlo[DD * HH];         // [DD][HH]
__device__ float g_wval[NT * 2];
__device__ int   g_cnt[NE];
__device__ int   g_list[NE * NT];
__device__ float g_pair[(size_t)NT * 2 * HH];
__device__ bf16  g_moehi[(size_t)NT * HH], g_moelo[(size_t)NT * HH];

// ---------------- PTX helpers (sm_80+ baseline only) ------------------------
__device__ __forceinline__ uint32_t smem_u32(const void* p) {
    uint32_t a;
    asm("{ .reg .u64 t; cvta.to.shared.u64 t, %1; cvt.u32.u64 %0, t; }" : "=r"(a) : "l"(p));
    return a;
}
__device__ __forceinline__ void cp16(uint32_t s, const void* g) {
    asm volatile("cp.async.cg.shared.global [%0], [%1], 16;" :: "r"(s), "l"(g));
}
#define CP_COMMIT() asm volatile("cp.async.commit_group;" ::: "memory")
#define CP_WAIT2()  asm volatile("cp.async.wait_group 2;" ::: "memory")

__device__ __forceinline__ void ldsm_x4(uint32_t* r, uint32_t a) {
    asm volatile("ldmatrix.sync.aligned.m8n8.x4.shared.b16 {%0,%1,%2,%3}, [%4];"
        : "=r"(r[0]), "=r"(r[1]), "=r"(r[2]), "=r"(r[3]) : "r"(a));
}
__device__ __forceinline__ void mma_bf16(float* c, const uint32_t* a, const uint32_t* b) {
    asm volatile("mma.sync.aligned.m16n8k16.row.col.f32.bf16.bf16.f32 "
        "{%0,%1,%2,%3}, {%4,%5,%6,%7}, {%8,%9}, {%0,%1,%2,%3};"
        : "+f"(c[0]), "+f"(c[1]), "+f"(c[2]), "+f"(c[3])
        : "r"(a[0]), "r"(a[1]), "r"(a[2]), "r"(a[3]), "r"(b[0]), "r"(b[1]));
}

// ---------------- small kernels ---------------------------------------------
__global__ void zero_cnt_kernel() { if (threadIdx.x < NE) g_cnt[threadIdx.x] = 0; }

__global__ void split_x_kernel(const float* __restrict__ x) {
    int i = blockIdx.x * blockDim.x + threadIdx.x;
    float v = x[i];
    bf16 h = __float2bfloat16(v);
    g_xhi[i] = h;
    g_xlo[i] = __float2bfloat16(v - __bfloat162float(h));
}

// in [R][C] fp32 (+z batch) -> out [C][R] bf16 hi/lo
__global__ void tsplit_kernel(const float* __restrict__ in, bf16* __restrict__ ohi,
                              bf16* __restrict__ olo, int R, int C) {
    __shared__ float t[32][33];
    size_t zoff = (size_t)blockIdx.z * R * C;
    in += zoff; ohi += zoff; olo += zoff;
    int c0 = blockIdx.x * 32, r0 = blockIdx.y * 32;
    for (int i = threadIdx.y; i < 32; i += 8)
        t[i][threadIdx.x] = in[(size_t)(r0 + i) * C + c0 + threadIdx.x];
    __syncthreads();
    for (int i = threadIdx.y; i < 32; i += 8) {
        float v = t[threadIdx.x][i];
        bf16 h = __float2bfloat16(v);
        size_t o = (size_t)(c0 + i) * R + r0 + threadIdx.x;
        ohi[o] = h;
        olo[o] = __float2bfloat16(v - __bfloat162float(h));
    }
}

// ---------------- gating: logits -> top2 -> routing --------------------------
__global__ void gating_kernel(const int* __restrict__ ftypes,
                              const float* __restrict__ gw3, const float* __restrict__ gb3,
                              const float* __restrict__ temb, const float* __restrict__ tw,
                              const float* __restrict__ tb) {
    int gwarp = (blockIdx.x * blockDim.x + threadIdx.x) >> 5;
    int lane = threadIdx.x & 31;
    if (gwarp >= NT) return;
    const int t = gwarp;
    float acc[NE] = {};
    const float* hrow = g_h2 + (size_t)t * GHB;
    for (int j = lane; j < GHB; j += 32) {
        float hv = hrow[j];
        const float* g = gw3 + j * NE;
        #pragma unroll
        for (int e = 0; e < NE; e++) acc[e] = fmaf(hv, g[e], acc[e]);
    }
    int ftv = ftypes[t];
    const float* te = temb + ftv * 128;
    for (int j = lane; j < 128; j += 32) {
        float tv = te[j];
        const float* w = tw + j * NE;
        #pragma unroll
        for (int e = 0; e < NE; e++) acc[e] = fmaf(tv, w[e], acc[e]);
    }
    #pragma unroll
    for (int off = 16; off; off >>= 1)
        #pragma unroll
        for (int e = 0; e < NE; e++) acc[e] += __shfl_xor_sync(0xffffffffu, acc[e], off);
    if (lane == 0) {
        float logits[NE];
        #pragma unroll
        for (int e = 0; e < NE; e++) logits[e] = acc[e] + gb3[e] + tb[e];
        int i0 = 0;
        #pragma unroll
        for (int e = 1; e < NE; e++) if (logits[e] > logits[i0]) i0 = e;
        int i1 = (i0 == 0) ? 1 : 0;
        #pragma unroll
        for (int e = 0; e < NE; e++) {
            if (e == i0 || e == i1) continue;
            if (logits[e] > logits[i1]) i1 = e;
        }
        float r = expf(logits[i1] - logits[i0]);
        float inv = 1.f / (1.f + r);
        g_wval[t * 2 + 0] = inv;
        g_wval[t * 2 + 1] = r * inv;
        int s0 = atomicAdd(&g_cnt[i0], 1); g_list[i0 * NT + s0] = t * 2 + 0;
        int s1 = atomicAdd(&g_cnt[i1], 1); g_list[i1 * NT + s1] = t * 2 + 1;
    }
}

// ---------------- bf16-split MMA GEMM, 512 threads, 4-stage pipeline ---------
// C[128,128] = (Ahi+Alo)(Bhi+Blo)^T (3-term). A:[M,K], B:[N,K], both K-major.
// 16 warps (4x4); warp tile 32x32 (2 mtiles x 4 n8-tiles).
#define EPI_RELU_SPLIT 0
#define EPI_RELU_F32   1
#define EPI_F32        2
#define EPI_SCATTER    3

#define ROWB      80
#define TILES_OFF 2048
#define STAGE_SZ  40960
#define NSTAGE    4
#define OA_HI 0
#define OA_LO 10240
#define OB_HI 20480
#define OB_LO 30720
#define SMEM_GEMM (TILES_OFF + NSTAGE * STAGE_SZ)   // 165888

template<int MODE, bool GATHER>
__global__ void __launch_bounds__(512, 1) mma_gemm(
    const bf16* __restrict__ Ahi, const bf16* __restrict__ Alo,
    const bf16* __restrict__ Bhi, const bf16* __restrict__ Blo,
    const float* __restrict__ bias,
    float* __restrict__ outf, bf16* __restrict__ outhi, bf16* __restrict__ outlo,
    int N, int K) {
    extern __shared__ char smem[];
    int* s_pid = (int*)smem;
    int* s_tok = (int*)(smem + 512);
    const int tid = threadIdx.x, lane = tid & 31, wid = tid >> 5;
    const int wm = wid >> 2, wn = wid & 3;
    const int nb = blockIdx.x;

    int mtile = blockIdx.y, e = 0;
    if (GATHER) {
        int flat = blockIdx.y, base = 0, cnt = 0;
        bool found = false;
        #pragma unroll
        for (int i = 0; i < NE; i++) {
            int c = g_cnt[i];
            int tiles = (c + 127) >> 7;
            if (!found && flat < base + tiles) { e = i; mtile = flat - base; cnt = c; found = true; }
            base += tiles;
        }
        if (!found) return;
        if (tid < 128) {
            int idx = mtile * 128 + tid;
            int pid = (idx < cnt) ? g_list[e * NT + idx] : -1;
            s_pid[tid] = pid;
            s_tok[tid] = (pid >= 0) ? (pid >> 1) : 0;
        }
        Bhi += (size_t)e * HH * DD;
        Blo += (size_t)e * HH * DD;
        bias += (size_t)e * HH;
        __syncthreads();
    }

    const uint32_t sb = smem_u32(smem) + TILES_OFF;

    // one row per thread per tile, 16B segment
    const int seg = tid & 3;               // 16B segment within 64B chunk row
    const int row = tid >> 2;              // 0..127
    size_t arow = GATHER ? (size_t)s_tok[row] : ((size_t)mtile * 128 + row);
    size_t brow = (size_t)nb * 128 + row;
    const bf16* pAh = Ahi + arow * K + seg * 8;
    const bf16* pAl = Alo + arow * K + seg * 8;
    const bf16* pBh = Bhi + brow * K + seg * 8;
    const bf16* pBl = Blo + brow * K + seg * 8;
    const uint32_t so = row * ROWB + seg * 16;

    float acc[2][4][4] = {};
    const int niter = K >> 5;

    // prologue: stages 0..2
    #pragma unroll
    for (int s = 0; s < NSTAGE - 1; s++) {
        if (s < niter) {
            const uint32_t st = sb + s * STAGE_SZ;
            const int ko = s << 5;
            cp16(st + OA_HI + so, pAh + ko);
            cp16(st + OA_LO + so, pAl + ko);
            cp16(st + OB_HI + so, pBh + ko);
            cp16(st + OB_LO + so, pBl + ko);
        }
        CP_COMMIT();
    }

    for (int it = 0; it < niter; it++) {
        CP_WAIT2();
        __syncthreads();

        // issue stage it+3 (buffer last used in iter it-1; sync above protects it)
        {
            const int s = it + NSTAGE - 1;
            if (s < niter) {
                const uint32_t st = sb + (s & (NSTAGE - 1)) * STAGE_SZ;
                const int ko = s << 5;
                cp16(st + OA_HI + so, pAh + ko);
                cp16(st + OA_LO + so, pAl + ko);
                cp16(st + OB_HI + so, pBh + ko);
                cp16(st + OB_LO + so, pBl + ko);
            }
            CP_COMMIT();
        }

        const uint32_t st = sb + (it & (NSTAGE - 1)) * STAGE_SZ;
        #pragma unroll
        for (int ks = 0; ks < 2; ks++) {
            uint32_t ah[2][4], al[2][4], bh[2][4], bl[2][4];
            const int acol = (ks * 16 + (lane >> 4) * 8) * 2;
            #pragma unroll
            for (int mt = 0; mt < 2; mt++) {
                uint32_t ad = st + (wm * 32 + mt * 16 + (lane & 15)) * ROWB + acol;
                ldsm_x4(ah[mt], ad + OA_HI);
                ldsm_x4(al[mt], ad + OA_LO);
            }
            const int bcol = (ks * 16 + ((lane >> 3) & 1) * 8) * 2;
            #pragma unroll
            for (int pr = 0; pr < 2; pr++) {
                uint32_t bd = st + (wn * 32 + pr * 16 + ((lane >> 4) << 3) + (lane & 7)) * ROWB + bcol;
                ldsm_x4(bh[pr], bd + OB_HI);
                ldsm_x4(bl[pr], bd + OB_LO);
            }
            #pragma unroll
            for (int mt = 0; mt < 2; mt++)
                #pragma unroll
                for (int nt = 0; nt < 4; nt++) {
                    const uint32_t* bhp = &bh[nt >> 1][(nt & 1) * 2];
                    const uint32_t* blp = &bl[nt >> 1][(nt & 1) * 2];
                    mma_bf16(acc[mt][nt], ah[mt], bhp);
                    mma_bf16(acc[mt][nt], ah[mt], blp);
                    mma_bf16(acc[mt][nt], al[mt], bhp);
                }
        }
    }

    // -------- epilogue --------
    #pragma unroll
    for (int mt = 0; mt < 2; mt++) {
        #pragma unroll
        for (int half = 0; half < 2; half++) {
            const int mloc = wm * 32 + mt * 16 + half * 8 + (lane >> 2);
            int pid = 0;
            if (GATHER) { pid = s_pid[mloc]; if (pid < 0) continue; }
            #pragma unroll
            for (int nt = 0; nt < 4; nt++) {
                const int c0 = nb * 128 + wn * 32 + nt * 8 + (lane & 3) * 2;
                float v0 = acc[mt][nt][half * 2 + 0] + bias[c0];
                float v1 = acc[mt][nt][half * 2 + 1] + bias[c0 + 1];
                if (MODE == EPI_SCATTER) {
                    float* dst = outf + (size_t)pid * HH + c0;
                    dst[0] = v0; dst[1] = v1;
                } else {
                    size_t base = (size_t)(mtile * 128 + mloc) * N + c0;
                    if (MODE == EPI_RELU_SPLIT || MODE == EPI_RELU_F32) {
                        v0 = fmaxf(v0, 0.f); v1 = fmaxf(v1, 0.f);
                    }
                    if (MODE == EPI_RELU_SPLIT) {
                        bf16 h0 = __float2bfloat16(v0), h1 = __float2bfloat16(v1);
                        outhi[base] = h0; outhi[base + 1] = h1;
                        outlo[base] = __float2bfloat16(v0 - __bfloat162float(h0));
                        outlo[base + 1] = __float2bfloat16(v1 - __bfloat162float(h1));
                    } else {
                        outf[base] = v0; outf[base + 1] = v1;
                    }
                }
            }
        }
    }
}

// ---------------- combine: moe = relu(w0*pair0 + w1*pair1), split to bf16 ----
__global__ void combine_kernel() {
    int idx = blockIdx.x * blockDim.x + threadIdx.x;   // NT*HH
    int t = idx >> 11;
    size_t a_i = (size_t)idx + (size_t)t * HH;
    float w0 = g_wval[2 * t], w1 = g_wval[2 * t + 1];
    float a = g_pair[a_i];
    float b = g_pair[a_i + HH];
    float v = fmaxf(fmaf(w0, a, w1 * b), 0.f);
    bf16 h = __float2bfloat16(v);
    g_moehi[idx] = h;
    g_moelo[idx] = __float2bfloat16(v - __bfloat162float(h));
}

// ---------------- launch ------------------------------------------------------
extern "C" void kernel_launch(void* const* d_in, const int* in_sizes, int n_in,
                              void* d_out, int out_size) {
    const float* x    = (const float*)d_in[0];
    const int*   ft   = (const int*)  d_in[1];
    const float* gw1  = (const float*)d_in[2];
    const float* gb1  = (const float*)d_in[3];
    const float* gw2  = (const float*)d_in[4];
    const float* gb2  = (const float*)d_in[5];
    const float* gw3  = (const float*)d_in[6];
    const float* gb3  = (const float*)d_in[7];
    const float* temb = (const float*)d_in[8];
    const float* tw   = (const float*)d_in[9];
    const float* tb   = (const float*)d_in[10];
    const float* ew   = (const float*)d_in[11];
    const float* eb   = (const float*)d_in[12];
    const float* ow   = (const float*)d_in[13];
    const float* ob   = (const float*)d_in[14];
    float* out = (float*)d_out;

    bf16 *xhi, *xlo, *h1hi, *h1lo, *w1hi, *w1lo, *w2hi, *w2lo, *ewhi, *ewlo, *owhi, *owlo, *mhi, *mlo;
    float *h2, *pair;
    cudaGetSymbolAddress((void**)&xhi, g_xhi);   cudaGetSymbolAddress((void**)&xlo, g_xlo);
    cudaGetSymbolAddress((void**)&h1hi, g_h1hi); cudaGetSymbolAddress((void**)&h1lo, g_h1lo);
    cudaGetSymbolAddress((void**)&w1hi, g_w1hi); cudaGetSymbolAddress((void**)&w1lo, g_w1lo);
    cudaGetSymbolAddress((void**)&w2hi, g_w2hi); cudaGetSymbolAddress((void**)&w2lo, g_w2lo);
    cudaGetSymbolAddress((void**)&ewhi, g_ewhi); cudaGetSymbolAddress((void**)&ewlo, g_ewlo);
    cudaGetSymbolAddress((void**)&owhi, g_owhi); cudaGetSymbolAddress((void**)&owlo, g_owlo);
    cudaGetSymbolAddress((void**)&mhi, g_moehi); cudaGetSymbolAddress((void**)&mlo, g_moelo);
    cudaGetSymbolAddress((void**)&h2, g_h2);     cudaGetSymbolAddress((void**)&pair, g_pair);

    cudaFuncSetAttribute(mma_gemm<EPI_RELU_SPLIT, false>, cudaFuncAttributeMaxDynamicSharedMemorySize, SMEM_GEMM);
    cudaFuncSetAttribute(mma_gemm<EPI_RELU_F32,   false>, cudaFuncAttributeMaxDynamicSharedMemorySize, SMEM_GEMM);
    cudaFuncSetAttribute(mma_gemm<EPI_F32,        false>, cudaFuncAttributeMaxDynamicSharedMemorySize, SMEM_GEMM);
    cudaFuncSetAttribute(mma_gemm<EPI_SCATTER,    true>,  cudaFuncAttributeMaxDynamicSharedMemorySize, SMEM_GEMM);

    zero_cnt_kernel<<<1, 32>>>();

    // conversions: x split; weights transpose+split to [N,K]
    split_x_kernel<<<(NT * DD) / 256, 256>>>(x);
    tsplit_kernel<<<dim3(GHA / 32, DD / 32, 1), dim3(32, 8)>>>(gw1, w1hi, w1lo, DD, GHA);
    tsplit_kernel<<<dim3(GHB / 32, GHA / 32, 1), dim3(32, 8)>>>(gw2, w2hi, w2lo, GHA, GHB);
    tsplit_kernel<<<dim3(HH / 32, DD / 32, NE), dim3(32, 8)>>>(ew, ewhi, ewlo, DD, HH);
    tsplit_kernel<<<dim3(DD / 32, HH / 32, 1), dim3(32, 8)>>>(ow, owhi, owlo, HH, DD);

    // gating MLP on tensor cores
    mma_gemm<EPI_RELU_SPLIT, false><<<dim3(GHA / 128, NT / 128), 512, SMEM_GEMM>>>(
        xhi, xlo, w1hi, w1lo, gb1, nullptr, h1hi, h1lo, GHA, DD);
    mma_gemm<EPI_RELU_F32, false><<<dim3(GHB / 128, NT / 128), 512, SMEM_GEMM>>>(
        h1hi, h1lo, w2hi, w2lo, gb2, h2, nullptr, nullptr, GHB, GHA);

    // routing
    gating_kernel<<<NT / 8, 256>>>(ft, gw3, gb3, temb, tw, tb);

    // selected-expert grouped GEMM (gathered A, scattered C)
    mma_gemm<EPI_SCATTER, true><<<dim3(HH / 128, MAX_MTILES), 512, SMEM_GEMM>>>(
        xhi, xlo, ewhi, ewlo, eb, pair, nullptr, nullptr, HH, DD);

    // combine + relu + split
    combine_kernel<<<(NT * HH) / 256, 256>>>();

    // output projection
    mma_gemm<EPI_F32, false><<<dim3(DD / 128, NT / 128), 512, SMEM_GEMM>>>(
        mhi, mlo, owhi, owlo, ob, out, nullptr, nullptr, DD, HH);
}

// round 6
// speedup vs baseline: 3.1527x; 1.3000x over previous
#include <cuda_runtime.h>
#include <cuda_bf16.h>
#include <cuda_fp16.h>
#include <cstdint>

#define NT   8192
#define DD   1024
#define GHA  512
#define GHB  256
#define NE   8
#define HH   2048
#define MAX_MTILES 136

typedef __nv_bfloat16 bf16;

// ---------------- scratch ---------------------------------------------------
// gating path (bf16 3-term)
__device__ bf16  g_xhi[NT * DD],  g_xlo[NT * DD];
__device__ bf16  g_h1hi[NT * GHA], g_h1lo[NT * GHA];
__device__ float g_h2[NT * GHB];
__device__ bf16  g_w1hi[GHA * DD], g_w1lo[GHA * DD];
__device__ bf16  g_w2hi[GHB * GHA], g_w2lo[GHB * GHA];
// expert/outproj path (fp16 2-term: A 2-limb, W 1-limb)
__device__ __half g_xhh[NT * DD], g_xhl[NT * DD];
__device__ __half g_ewh[(size_t)NE * HH * DD];             // [E][H][D]
__device__ __half g_owh[(size_t)DD * HH];                  // [D][H]
__device__ __half g_mhh[(size_t)NT * HH], g_mhl[(size_t)NT * HH];
// routing
__device__ float g_wval[NT * 2];
__device__ int   g_cnt[NE];
__device__ int   g_list[NE * NT];
__device__ float g_pair[(size_t)NT * 2 * HH];

// ---------------- PTX helpers (sm_80+ baseline only) ------------------------
__device__ __forceinline__ uint32_t smem_u32(const void* p) {
    uint32_t a;
    asm("{ .reg .u64 t; cvta.to.shared.u64 t, %1; cvt.u32.u64 %0, t; }" : "=r"(a) : "l"(p));
    return a;
}
__device__ __forceinline__ void cp16(uint32_t s, const void* g) {
    asm volatile("cp.async.cg.shared.global [%0], [%1], 16;" :: "r"(s), "l"(g));
}
#define CP_COMMIT() asm volatile("cp.async.commit_group;" ::: "memory")
#define CP_WAIT2()  asm volatile("cp.async.wait_group 2;" ::: "memory")

__device__ __forceinline__ void ldsm_x4(uint32_t* r, uint32_t a) {
    asm volatile("ldmatrix.sync.aligned.m8n8.x4.shared.b16 {%0,%1,%2,%3}, [%4];"
        : "=r"(r[0]), "=r"(r[1]), "=r"(r[2]), "=r"(r[3]) : "r"(a));
}
__device__ __forceinline__ void mma_bf16(float* c, const uint32_t* a, const uint32_t* b) {
    asm volatile("mma.sync.aligned.m16n8k16.row.col.f32.bf16.bf16.f32 "
        "{%0,%1,%2,%3}, {%4,%5,%6,%7}, {%8,%9}, {%0,%1,%2,%3};"
        : "+f"(c[0]), "+f"(c[1]), "+f"(c[2]), "+f"(c[3])
        : "r"(a[0]), "r"(a[1]), "r"(a[2]), "r"(a[3]), "r"(b[0]), "r"(b[1]));
}
__device__ __forceinline__ void mma_f16(float* c, const uint32_t* a, const uint32_t* b) {
    asm volatile("mma.sync.aligned.m16n8k16.row.col.f32.f16.f16.f32 "
        "{%0,%1,%2,%3}, {%4,%5,%6,%7}, {%8,%9}, {%0,%1,%2,%3};"
        : "+f"(c[0]), "+f"(c[1]), "+f"(c[2]), "+f"(c[3])
        : "r"(a[0]), "r"(a[1]), "r"(a[2]), "r"(a[3]), "r"(b[0]), "r"(b[1]));
}

// ---------------- small kernels ---------------------------------------------
__global__ void zero_cnt_kernel() { if (threadIdx.x < NE) g_cnt[threadIdx.x] = 0; }

// x -> bf16 hi/lo (gating) AND fp16 hi/lo (expert) in one pass
__global__ void split_x_kernel(const float* __restrict__ x) {
    int i = blockIdx.x * blockDim.x + threadIdx.x;
    float v = x[i];
    bf16 bh = __float2bfloat16(v);
    g_xhi[i] = bh;
    g_xlo[i] = __float2bfloat16(v - __bfloat162float(bh));
    __half hh = __float2half(v);
    g_xhh[i] = hh;
    g_xhl[i] = __float2half(v - __half2float(hh));
}

// in [R][C] fp32 (+z batch) -> out [C][R] bf16 hi/lo
__global__ void tsplit_kernel(const float* __restrict__ in, bf16* __restrict__ ohi,
                              bf16* __restrict__ olo, int R, int C) {
    __shared__ float t[32][33];
    size_t zoff = (size_t)blockIdx.z * R * C;
    in += zoff; ohi += zoff; olo += zoff;
    int c0 = blockIdx.x * 32, r0 = blockIdx.y * 32;
    for (int i = threadIdx.y; i < 32; i += 8)
        t[i][threadIdx.x] = in[(size_t)(r0 + i) * C + c0 + threadIdx.x];
    __syncthreads();
    for (int i = threadIdx.y; i < 32; i += 8) {
        float v = t[threadIdx.x][i];
        bf16 h = __float2bfloat16(v);
        size_t o = (size_t)(c0 + i) * R + r0 + threadIdx.x;
        ohi[o] = h;
        olo[o] = __float2bfloat16(v - __bfloat162float(h));
    }
}

// in [R][C] fp32 (+z batch) -> out [C][R] fp16 (single limb)
__global__ void tconv_h_kernel(const float* __restrict__ in, __half* __restrict__ o,
                               int R, int C) {
    __shared__ float t[32][33];
    size_t zoff = (size_t)blockIdx.z * R * C;
    in += zoff; o += zoff;
    int c0 = blockIdx.x * 32, r0 = blockIdx.y * 32;
    for (int i = threadIdx.y; i < 32; i += 8)
        t[i][threadIdx.x] = in[(size_t)(r0 + i) * C + c0 + threadIdx.x];
    __syncthreads();
    for (int i = threadIdx.y; i < 32; i += 8)
        o[(size_t)(c0 + i) * R + r0 + threadIdx.x] = __float2half(t[threadIdx.x][i]);
}

// ---------------- gating: logits -> top2 -> routing --------------------------
__global__ void gating_kernel(const int* __restrict__ ftypes,
                              const float* __restrict__ gw3, const float* __restrict__ gb3,
                              const float* __restrict__ temb, const float* __restrict__ tw,
                              const float* __restrict__ tb) {
    int gwarp = (blockIdx.x * blockDim.x + threadIdx.x) >> 5;
    int lane = threadIdx.x & 31;
    if (gwarp >= NT) return;
    const int t = gwarp;
    float acc[NE] = {};
    const float* hrow = g_h2 + (size_t)t * GHB;
    for (int j = lane; j < GHB; j += 32) {
        float hv = hrow[j];
        const float* g = gw3 + j * NE;
        #pragma unroll
        for (int e = 0; e < NE; e++) acc[e] = fmaf(hv, g[e], acc[e]);
    }
    int ftv = ftypes[t];
    const float* te = temb + ftv * 128;
    for (int j = lane; j < 128; j += 32) {
        float tv = te[j];
        const float* w = tw + j * NE;
        #pragma unroll
        for (int e = 0; e < NE; e++) acc[e] = fmaf(tv, w[e], acc[e]);
    }
    #pragma unroll
    for (int off = 16; off; off >>= 1)
        #pragma unroll
        for (int e = 0; e < NE; e++) acc[e] += __shfl_xor_sync(0xffffffffu, acc[e], off);
    if (lane == 0) {
        float logits[NE];
        #pragma unroll
        for (int e = 0; e < NE; e++) logits[e] = acc[e] + gb3[e] + tb[e];
        int i0 = 0;
        #pragma unroll
        for (int e = 1; e < NE; e++) if (logits[e] > logits[i0]) i0 = e;
        int i1 = (i0 == 0) ? 1 : 0;
        #pragma unroll
        for (int e = 0; e < NE; e++) {
            if (e == i0 || e == i1) continue;
            if (logits[e] > logits[i1]) i1 = e;
        }
        float r = expf(logits[i1] - logits[i0]);
        float inv = 1.f / (1.f + r);
        g_wval[t * 2 + 0] = inv;
        g_wval[t * 2 + 1] = r * inv;
        int s0 = atomicAdd(&g_cnt[i0], 1); g_list[i0 * NT + s0] = t * 2 + 0;
        int s1 = atomicAdd(&g_cnt[i1], 1); g_list[i1 * NT + s1] = t * 2 + 1;
    }
}

// ================= bf16 3-term GEMM (gating layers) ==========================
#define EPI_RELU_SPLIT 0
#define EPI_RELU_F32   1

#define ROWB      80
#define TILES_OFF 2048
#define STAGE_SZ  40960
#define NSTAGE    4
#define OA_HI 0
#define OA_LO 10240
#define OB_HI 20480
#define OB_LO 30720
#define SMEM_GEMM (TILES_OFF + NSTAGE * STAGE_SZ)   // 165888

template<int MODE>
__global__ void __launch_bounds__(512, 1) mma_gemm(
    const bf16* __restrict__ Ahi, const bf16* __restrict__ Alo,
    const bf16* __restrict__ Bhi, const bf16* __restrict__ Blo,
    const float* __restrict__ bias,
    float* __restrict__ outf, bf16* __restrict__ outhi, bf16* __restrict__ outlo,
    int N, int K) {
    extern __shared__ char smem[];
    const int tid = threadIdx.x, lane = tid & 31, wid = tid >> 5;
    const int wm = wid >> 2, wn = wid & 3;
    const int nb = blockIdx.x;
    const int mtile = blockIdx.y;

    const uint32_t sb = smem_u32(smem) + TILES_OFF;

    const int seg = tid & 3;
    const int row = tid >> 2;
    size_t arow = (size_t)mtile * 128 + row;
    size_t brow = (size_t)nb * 128 + row;
    const bf16* pAh = Ahi + arow * K + seg * 8;
    const bf16* pAl = Alo + arow * K + seg * 8;
    const bf16* pBh = Bhi + brow * K + seg * 8;
    const bf16* pBl = Blo + brow * K + seg * 8;
    const uint32_t so = row * ROWB + seg * 16;

    float acc[2][4][4] = {};
    const int niter = K >> 5;

    #pragma unroll
    for (int s = 0; s < NSTAGE - 1; s++) {
        if (s < niter) {
            const uint32_t st = sb + s * STAGE_SZ;
            const int ko = s << 5;
            cp16(st + OA_HI + so, pAh + ko);
            cp16(st + OA_LO + so, pAl + ko);
            cp16(st + OB_HI + so, pBh + ko);
            cp16(st + OB_LO + so, pBl + ko);
        }
        CP_COMMIT();
    }

    for (int it = 0; it < niter; it++) {
        CP_WAIT2();
        __syncthreads();
        {
            const int s = it + NSTAGE - 1;
            if (s < niter) {
                const uint32_t st = sb + (s & (NSTAGE - 1)) * STAGE_SZ;
                const int ko = s << 5;
                cp16(st + OA_HI + so, pAh + ko);
                cp16(st + OA_LO + so, pAl + ko);
                cp16(st + OB_HI + so, pBh + ko);
                cp16(st + OB_LO + so, pBl + ko);
            }
            CP_COMMIT();
        }

        const uint32_t st = sb + (it & (NSTAGE - 1)) * STAGE_SZ;
        #pragma unroll
        for (int ks = 0; ks < 2; ks++) {
            uint32_t ah[2][4], al[2][4], bh[2][4], bl[2][4];
            const int acol = (ks * 16 + (lane >> 4) * 8) * 2;
            #pragma unroll
            for (int mt = 0; mt < 2; mt++) {
                uint32_t ad = st + (wm * 32 + mt * 16 + (lane & 15)) * ROWB + acol;
                ldsm_x4(ah[mt], ad + OA_HI);
                ldsm_x4(al[mt], ad + OA_LO);
            }
            const int bcol = (ks * 16 + ((lane >> 3) & 1) * 8) * 2;
            #pragma unroll
            for (int pr = 0; pr < 2; pr++) {
                uint32_t bd = st + (wn * 32 + pr * 16 + ((lane >> 4) << 3) + (lane & 7)) * ROWB + bcol;
                ldsm_x4(bh[pr], bd + OB_HI);
                ldsm_x4(bl[pr], bd + OB_LO);
            }
            #pragma unroll
            for (int mt = 0; mt < 2; mt++)
                #pragma unroll
                for (int nt = 0; nt < 4; nt++) {
                    const uint32_t* bhp = &bh[nt >> 1][(nt & 1) * 2];
                    const uint32_t* blp = &bl[nt >> 1][(nt & 1) * 2];
                    mma_bf16(acc[mt][nt], ah[mt], bhp);
                    mma_bf16(acc[mt][nt], ah[mt], blp);
                    mma_bf16(acc[mt][nt], al[mt], bhp);
                }
        }
    }

    #pragma unroll
    for (int mt = 0; mt < 2; mt++) {
        #pragma unroll
        for (int half = 0; half < 2; half++) {
            const int mloc = wm * 32 + mt * 16 + half * 8 + (lane >> 2);
            #pragma unroll
            for (int nt = 0; nt < 4; nt++) {
                const int c0 = nb * 128 + wn * 32 + nt * 8 + (lane & 3) * 2;
                float v0 = fmaxf(acc[mt][nt][half * 2 + 0] + bias[c0], 0.f);
                float v1 = fmaxf(acc[mt][nt][half * 2 + 1] + bias[c0 + 1], 0.f);
                size_t base = (size_t)(mtile * 128 + mloc) * N + c0;
                if (MODE == EPI_RELU_SPLIT) {
                    bf16 h0 = __float2bfloat16(v0), h1 = __float2bfloat16(v1);
                    outhi[base] = h0; outhi[base + 1] = h1;
                    outlo[base] = __float2bfloat16(v0 - __bfloat162float(h0));
                    outlo[base + 1] = __float2bfloat16(v1 - __bfloat162float(h1));
                } else {
                    outf[base] = v0; outf[base + 1] = v1;
                }
            }
        }
    }
}

// ================= fp16 2-term GEMM (expert + outproj) =======================
// C = (Ahi+Alo) @ W^T, W single fp16. A:[M,K] 2-limb fp16, W:[N,K] fp16.
#define HEPI_SCATTER 0
#define HEPI_F32     1

#define HSTAGE_SZ 30720
#define HOA_HI 0
#define HOA_LO 10240
#define HOB    20480
#define SMEM_HGEMM (TILES_OFF + NSTAGE * HSTAGE_SZ)   // 124928

template<int MODE, bool GATHER>
__global__ void __launch_bounds__(512, 1) h_gemm(
    const __half* __restrict__ Ahi, const __half* __restrict__ Alo,
    const __half* __restrict__ W,
    const float* __restrict__ bias,
    float* __restrict__ outf, int N, int K) {
    extern __shared__ char smem[];
    int* s_pid = (int*)smem;
    int* s_tok = (int*)(smem + 512);
    const int tid = threadIdx.x, lane = tid & 31, wid = tid >> 5;
    const int wm = wid >> 2, wn = wid & 3;
    const int nb = blockIdx.x;

    int mtile = blockIdx.y, e = 0;
    if (GATHER) {
        int flat = blockIdx.y, base = 0, cnt = 0;
        bool found = false;
        #pragma unroll
        for (int i = 0; i < NE; i++) {
            int c = g_cnt[i];
            int tiles = (c + 127) >> 7;
            if (!found && flat < base + tiles) { e = i; mtile = flat - base; cnt = c; found = true; }
            base += tiles;
        }
        if (!found) return;
        if (tid < 128) {
            int idx = mtile * 128 + tid;
            int pid = (idx < cnt) ? g_list[e * NT + idx] : -1;
            s_pid[tid] = pid;
            s_tok[tid] = (pid >= 0) ? (pid >> 1) : 0;
        }
        W += (size_t)e * HH * DD;
        bias += (size_t)e * HH;
        __syncthreads();
    }

    const uint32_t sb = smem_u32(smem) + TILES_OFF;

    const int seg = tid & 3;
    const int row = tid >> 2;
    size_t arow = GATHER ? (size_t)s_tok[row] : ((size_t)mtile * 128 + row);
    size_t brow = (size_t)nb * 128 + row;
    const __half* pAh = Ahi + arow * K + seg * 8;
    const __half* pAl = Alo + arow * K + seg * 8;
    const __half* pB  = W + brow * K + seg * 8;
    const uint32_t so = row * ROWB + seg * 16;

    float acc[2][4][4] = {};
    const int niter = K >> 5;

    #pragma unroll
    for (int s = 0; s < NSTAGE - 1; s++) {
        if (s < niter) {
            const uint32_t st = sb + s * HSTAGE_SZ;
            const int ko = s << 5;
            cp16(st + HOA_HI + so, pAh + ko);
            cp16(st + HOA_LO + so, pAl + ko);
            cp16(st + HOB + so, pB + ko);
        }
        CP_COMMIT();
    }

    for (int it = 0; it < niter; it++) {
        CP_WAIT2();
        __syncthreads();
        {
            const int s = it + NSTAGE - 1;
            if (s < niter) {
                const uint32_t st = sb + (s & (NSTAGE - 1)) * HSTAGE_SZ;
                const int ko = s << 5;
                cp16(st + HOA_HI + so, pAh + ko);
                cp16(st + HOA_LO + so, pAl + ko);
                cp16(st + HOB + so, pB + ko);
            }
            CP_COMMIT();
        }

        const uint32_t st = sb + (it & (NSTAGE - 1)) * HSTAGE_SZ;
        #pragma unroll
        for (int ks = 0; ks < 2; ks++) {
            uint32_t ah[2][4], al[2][4], bb[2][4];
            const int acol = (ks * 16 + (lane >> 4) * 8) * 2;
            #pragma unroll
            for (int mt = 0; mt < 2; mt++) {
                uint32_t ad = st + (wm * 32 + mt * 16 + (lane & 15)) * ROWB + acol;
                ldsm_x4(ah[mt], ad + HOA_HI);
                ldsm_x4(al[mt], ad + HOA_LO);
            }
            const int bcol = (ks * 16 + ((lane >> 3) & 1) * 8) * 2;
            #pragma unroll
            for (int pr = 0; pr < 2; pr++) {
                uint32_t bd = st + (wn * 32 + pr * 16 + ((lane >> 4) << 3) + (lane & 7)) * ROWB + bcol;
                ldsm_x4(bb[pr], bd + HOB);
            }
            #pragma unroll
            for (int mt = 0; mt < 2; mt++)
                #pragma unroll
                for (int nt = 0; nt < 4; nt++) {
                    const uint32_t* bp = &bb[nt >> 1][(nt & 1) * 2];
                    mma_f16(acc[mt][nt], ah[mt], bp);
                    mma_f16(acc[mt][nt], al[mt], bp);
                }
        }
    }

    #pragma unroll
    for (int mt = 0; mt < 2; mt++) {
        #pragma unroll
        for (int half = 0; half < 2; half++) {
            const int mloc = wm * 32 + mt * 16 + half * 8 + (lane >> 2);
            int pid = 0;
            if (GATHER) { pid = s_pid[mloc]; if (pid < 0) continue; }
            #pragma unroll
            for (int nt = 0; nt < 4; nt++) {
                const int c0 = nb * 128 + wn * 32 + nt * 8 + (lane & 3) * 2;
                float v0 = acc[mt][nt][half * 2 + 0] + bias[c0];
                float v1 = acc[mt][nt][half * 2 + 1] + bias[c0 + 1];
                if (MODE == HEPI_SCATTER) {
                    float* dst = outf + (size_t)pid * HH + c0;
                    dst[0] = v0; dst[1] = v1;
                } else {
                    size_t base = (size_t)(mtile * 128 + mloc) * N + c0;
                    outf[base] = v0; outf[base + 1] = v1;
                }
            }
        }
    }
}

// ---------------- combine: moe = relu(w0*p0 + w1*p1) -> fp16 hi/lo -----------
__global__ void combine_kernel() {
    int idx = blockIdx.x * blockDim.x + threadIdx.x;   // NT*HH
    int t = idx >> 11;
    size_t a_i = (size_t)idx + (size_t)t * HH;
    float w0 = g_wval[2 * t], w1 = g_wval[2 * t + 1];
    float a = g_pair[a_i];
    float b = g_pair[a_i + HH];
    float v = fmaxf(fmaf(w0, a, w1 * b), 0.f);
    __half h = __float2half(v);
    g_mhh[idx] = h;
    g_mhl[idx] = __float2half(v - __half2float(h));
}

// ---------------- launch ------------------------------------------------------
extern "C" void kernel_launch(void* const* d_in, const int* in_sizes, int n_in,
                              void* d_out, int out_size) {
    const float* x    = (const float*)d_in[0];
    const int*   ft   = (const int*)  d_in[1];
    const float* gw1  = (const float*)d_in[2];
    const float* gb1  = (const float*)d_in[3];
    const float* gw2  = (const float*)d_in[4];
    const float* gb2  = (const float*)d_in[5];
    const float* gw3  = (const float*)d_in[6];
    const float* gb3  = (const float*)d_in[7];
    const float* temb = (const float*)d_in[8];
    const float* tw   = (const float*)d_in[9];
    const float* tb   = (const float*)d_in[10];
    const float* ew   = (const float*)d_in[11];
    const float* eb   = (const float*)d_in[12];
    const float* ow   = (const float*)d_in[13];
    const float* ob   = (const float*)d_in[14];
    float* out = (float*)d_out;

    bf16 *xhi, *xlo, *h1hi, *h1lo, *w1hi, *w1lo, *w2hi, *w2lo;
    __half *xhh, *xhl, *ewh, *owh, *mhh, *mhl;
    float *h2, *pair;
    cudaGetSymbolAddress((void**)&xhi, g_xhi);   cudaGetSymbolAddress((void**)&xlo, g_xlo);
    cudaGetSymbolAddress((void**)&h1hi, g_h1hi); cudaGetSymbolAddress((void**)&h1lo, g_h1lo);
    cudaGetSymbolAddress((void**)&w1hi, g_w1hi); cudaGetSymbolAddress((void**)&w1lo, g_w1lo);
    cudaGetSymbolAddress((void**)&w2hi, g_w2hi); cudaGetSymbolAddress((void**)&w2lo, g_w2lo);
    cudaGetSymbolAddress((void**)&xhh, g_xhh);   cudaGetSymbolAddress((void**)&xhl, g_xhl);
    cudaGetSymbolAddress((void**)&ewh, g_ewh);   cudaGetSymbolAddress((void**)&owh, g_owh);
    cudaGetSymbolAddress((void**)&mhh, g_mhh);   cudaGetSymbolAddress((void**)&mhl, g_mhl);
    cudaGetSymbolAddress((void**)&h2, g_h2);     cudaGetSymbolAddress((void**)&pair, g_pair);

    cudaFuncSetAttribute(mma_gemm<EPI_RELU_SPLIT>, cudaFuncAttributeMaxDynamicSharedMemorySize, SMEM_GEMM);
    cudaFuncSetAttribute(mma_gemm<EPI_RELU_F32>,   cudaFuncAttributeMaxDynamicSharedMemorySize, SMEM_GEMM);
    cudaFuncSetAttribute(h_gemm<HEPI_SCATTER, true>,  cudaFuncAttributeMaxDynamicSharedMemorySize, SMEM_HGEMM);
    cudaFuncSetAttribute(h_gemm<HEPI_F32,     false>, cudaFuncAttributeMaxDynamicSharedMemorySize, SMEM_HGEMM);

    zero_cnt_kernel<<<1, 32>>>();

    // conversions
    split_x_kernel<<<(NT * DD) / 256, 256>>>(x);
    tsplit_kernel<<<dim3(GHA / 32, DD / 32, 1), dim3(32, 8)>>>(gw1, w1hi, w1lo, DD, GHA);
    tsplit_kernel<<<dim3(GHB / 32, GHA / 32, 1), dim3(32, 8)>>>(gw2, w2hi, w2lo, GHA, GHB);
    tconv_h_kernel<<<dim3(HH / 32, DD / 32, NE), dim3(32, 8)>>>(ew, ewh, DD, HH);
    tconv_h_kernel<<<dim3(DD / 32, HH / 32, 1), dim3(32, 8)>>>(ow, owh, HH, DD);

    // gating MLP (bf16 3-term, routing-grade precision)
    mma_gemm<EPI_RELU_SPLIT><<<dim3(GHA / 128, NT / 128), 512, SMEM_GEMM>>>(
        xhi, xlo, w1hi, w1lo, gb1, nullptr, h1hi, h1lo, GHA, DD);
    mma_gemm<EPI_RELU_F32><<<dim3(GHB / 128, NT / 128), 512, SMEM_GEMM>>>(
        h1hi, h1lo, w2hi, w2lo, gb2, h2, nullptr, nullptr, GHB, GHA);

    // routing
    gating_kernel<<<NT / 8, 256>>>(ft, gw3, gb3, temb, tw, tb);

    // expert grouped GEMM (fp16 2-term, gathered A, scattered C)
    h_gemm<HEPI_SCATTER, true><<<dim3(HH / 128, MAX_MTILES), 512, SMEM_HGEMM>>>(
        xhh, xhl, ewh, eb, pair, HH, DD);

    // combine + relu + fp16 split
    combine_kernel<<<(NT * HH) / 256, 256>>>();

    // output projection (fp16 2-term)
    h_gemm<HEPI_F32, false><<<dim3(DD / 128, NT / 128), 512, SMEM_HGEMM>>>(
        mhh, mhl, owh, ob, out, DD, HH);
}

// round 7
// speedup vs baseline: 4.0798x; 1.2940x over previous
#include <cuda_runtime.h>
#include <cuda_bf16.h>
#include <cuda_fp16.h>
#include <cstdint>

#define NT   8192
#define DD   1024
#define GHA  512
#define GHB  256
#define NE   8
#define HH   2048
#define MAX_MTILES 136

typedef __nv_bfloat16 bf16;

// ---------------- scratch ---------------------------------------------------
// gating path (bf16 3-term — routing-grade precision)
__device__ bf16  g_xhi[NT * DD],  g_xlo[NT * DD];
__device__ bf16  g_h1hi[NT * GHA], g_h1lo[NT * GHA];
__device__ float g_h2[NT * GHB];
__device__ bf16  g_w1hi[GHA * DD], g_w1lo[GHA * DD];
__device__ bf16  g_w2hi[GHB * GHA], g_w2lo[GHB * GHA];
// expert/outproj path (plain fp16 GEMMs)
__device__ __half g_xh[NT * DD];
__device__ __half g_ewh[(size_t)NE * HH * DD];             // [E][H][D]
__device__ __half g_owh[(size_t)DD * HH];                  // [D][H]
__device__ __half g_mh[(size_t)NT * HH];
// routing
__device__ float g_wval[NT * 2];
__device__ int   g_cnt[NE];
__device__ int   g_list[NE * NT];
__device__ float g_pair[(size_t)NT * 2 * HH];

// ---------------- PTX helpers (sm_80+ baseline only) ------------------------
__device__ __forceinline__ uint32_t smem_u32(const void* p) {
    uint32_t a;
    asm("{ .reg .u64 t; cvta.to.shared.u64 t, %1; cvt.u32.u64 %0, t; }" : "=r"(a) : "l"(p));
    return a;
}
__device__ __forceinline__ void cp16(uint32_t s, const void* g) {
    asm volatile("cp.async.cg.shared.global [%0], [%1], 16;" :: "r"(s), "l"(g));
}
#define CP_COMMIT() asm volatile("cp.async.commit_group;" ::: "memory")
#define CP_WAIT2()  asm volatile("cp.async.wait_group 2;" ::: "memory")

__device__ __forceinline__ void ldsm_x4(uint32_t* r, uint32_t a) {
    asm volatile("ldmatrix.sync.aligned.m8n8.x4.shared.b16 {%0,%1,%2,%3}, [%4];"
        : "=r"(r[0]), "=r"(r[1]), "=r"(r[2]), "=r"(r[3]) : "r"(a));
}
__device__ __forceinline__ void mma_bf16(float* c, const uint32_t* a, const uint32_t* b) {
    asm volatile("mma.sync.aligned.m16n8k16.row.col.f32.bf16.bf16.f32 "
        "{%0,%1,%2,%3}, {%4,%5,%6,%7}, {%8,%9}, {%0,%1,%2,%3};"
        : "+f"(c[0]), "+f"(c[1]), "+f"(c[2]), "+f"(c[3])
        : "r"(a[0]), "r"(a[1]), "r"(a[2]), "r"(a[3]), "r"(b[0]), "r"(b[1]));
}
__device__ __forceinline__ void mma_f16(float* c, const uint32_t* a, const uint32_t* b) {
    asm volatile("mma.sync.aligned.m16n8k16.row.col.f32.f16.f16.f32 "
        "{%0,%1,%2,%3}, {%4,%5,%6,%7}, {%8,%9}, {%0,%1,%2,%3};"
        : "+f"(c[0]), "+f"(c[1]), "+f"(c[2]), "+f"(c[3])
        : "r"(a[0]), "r"(a[1]), "r"(a[2]), "r"(a[3]), "r"(b[0]), "r"(b[1]));
}

// ---------------- small kernels ---------------------------------------------
__global__ void zero_cnt_kernel() { if (threadIdx.x < NE) g_cnt[threadIdx.x] = 0; }

// x -> bf16 hi/lo (gating) AND fp16 single (expert) in one pass
__global__ void split_x_kernel(const float* __restrict__ x) {
    int i = blockIdx.x * blockDim.x + threadIdx.x;
    float v = x[i];
    bf16 bh = __float2bfloat16(v);
    g_xhi[i] = bh;
    g_xlo[i] = __float2bfloat16(v - __bfloat162float(bh));
    g_xh[i] = __float2half(v);
}

// in [R][C] fp32 (+z batch) -> out [C][R] bf16 hi/lo
__global__ void tsplit_kernel(const float* __restrict__ in, bf16* __restrict__ ohi,
                              bf16* __restrict__ olo, int R, int C) {
    __shared__ float t[32][33];
    size_t zoff = (size_t)blockIdx.z * R * C;
    in += zoff; ohi += zoff; olo += zoff;
    int c0 = blockIdx.x * 32, r0 = blockIdx.y * 32;
    for (int i = threadIdx.y; i < 32; i += 8)
        t[i][threadIdx.x] = in[(size_t)(r0 + i) * C + c0 + threadIdx.x];
    __syncthreads();
    for (int i = threadIdx.y; i < 32; i += 8) {
        float v = t[threadIdx.x][i];
        bf16 h = __float2bfloat16(v);
        size_t o = (size_t)(c0 + i) * R + r0 + threadIdx.x;
        ohi[o] = h;
        olo[o] = __float2bfloat16(v - __bfloat162float(h));
    }
}

// in [R][C] fp32 (+z batch) -> out [C][R] fp16 (single limb)
__global__ void tconv_h_kernel(const float* __restrict__ in, __half* __restrict__ o,
                               int R, int C) {
    __shared__ float t[32][33];
    size_t zoff = (size_t)blockIdx.z * R * C;
    in += zoff; o += zoff;
    int c0 = blockIdx.x * 32, r0 = blockIdx.y * 32;
    for (int i = threadIdx.y; i < 32; i += 8)
        t[i][threadIdx.x] = in[(size_t)(r0 + i) * C + c0 + threadIdx.x];
    __syncthreads();
    for (int i = threadIdx.y; i < 32; i += 8)
        o[(size_t)(c0 + i) * R + r0 + threadIdx.x] = __float2half(t[threadIdx.x][i]);
}

// ---------------- gating: logits -> top2 -> routing --------------------------
__global__ void gating_kernel(const int* __restrict__ ftypes,
                              const float* __restrict__ gw3, const float* __restrict__ gb3,
                              const float* __restrict__ temb, const float* __restrict__ tw,
                              const float* __restrict__ tb) {
    int gwarp = (blockIdx.x * blockDim.x + threadIdx.x) >> 5;
    int lane = threadIdx.x & 31;
    if (gwarp >= NT) return;
    const int t = gwarp;
    float acc[NE] = {};
    const float* hrow = g_h2 + (size_t)t * GHB;
    for (int j = lane; j < GHB; j += 32) {
        float hv = hrow[j];
        const float* g = gw3 + j * NE;
        #pragma unroll
        for (int e = 0; e < NE; e++) acc[e] = fmaf(hv, g[e], acc[e]);
    }
    int ftv = ftypes[t];
    const float* te = temb + ftv * 128;
    for (int j = lane; j < 128; j += 32) {
        float tv = te[j];
        const float* w = tw + j * NE;
        #pragma unroll
        for (int e = 0; e < NE; e++) acc[e] = fmaf(tv, w[e], acc[e]);
    }
    #pragma unroll
    for (int off = 16; off; off >>= 1)
        #pragma unroll
        for (int e = 0; e < NE; e++) acc[e] += __shfl_xor_sync(0xffffffffu, acc[e], off);
    if (lane == 0) {
        float logits[NE];
        #pragma unroll
        for (int e = 0; e < NE; e++) logits[e] = acc[e] + gb3[e] + tb[e];
        int i0 = 0;
        #pragma unroll
        for (int e = 1; e < NE; e++) if (logits[e] > logits[i0]) i0 = e;
        int i1 = (i0 == 0) ? 1 : 0;
        #pragma unroll
        for (int e = 0; e < NE; e++) {
            if (e == i0 || e == i1) continue;
            if (logits[e] > logits[i1]) i1 = e;
        }
        float r = expf(logits[i1] - logits[i0]);
        float inv = 1.f / (1.f + r);
        g_wval[t * 2 + 0] = inv;
        g_wval[t * 2 + 1] = r * inv;
        int s0 = atomicAdd(&g_cnt[i0], 1); g_list[i0 * NT + s0] = t * 2 + 0;
        int s1 = atomicAdd(&g_cnt[i1], 1); g_list[i1 * NT + s1] = t * 2 + 1;
    }
}

// ================= bf16 3-term GEMM (gating layers) ==========================
#define EPI_RELU_SPLIT 0
#define EPI_RELU_F32   1

#define ROWB      80
#define TILES_OFF 2048
#define STAGE_SZ  40960
#define NSTAGE    4
#define OA_HI 0
#define OA_LO 10240
#define OB_HI 20480
#define OB_LO 30720
#define SMEM_GEMM (TILES_OFF + NSTAGE * STAGE_SZ)   // 165888

template<int MODE>
__global__ void __launch_bounds__(512, 1) mma_gemm(
    const bf16* __restrict__ Ahi, const bf16* __restrict__ Alo,
    const bf16* __restrict__ Bhi, const bf16* __restrict__ Blo,
    const float* __restrict__ bias,
    float* __restrict__ outf, bf16* __restrict__ outhi, bf16* __restrict__ outlo,
    int N, int K) {
    extern __shared__ char smem[];
    const int tid = threadIdx.x, lane = tid & 31, wid = tid >> 5;
    const int wm = wid >> 2, wn = wid & 3;
    const int nb = blockIdx.x;
    const int mtile = blockIdx.y;

    const uint32_t sb = smem_u32(smem) + TILES_OFF;

    const int seg = tid & 3;
    const int row = tid >> 2;
    size_t arow = (size_t)mtile * 128 + row;
    size_t brow = (size_t)nb * 128 + row;
    const bf16* pAh = Ahi + arow * K + seg * 8;
    const bf16* pAl = Alo + arow * K + seg * 8;
    const bf16* pBh = Bhi + brow * K + seg * 8;
    const bf16* pBl = Blo + brow * K + seg * 8;
    const uint32_t so = row * ROWB + seg * 16;

    float acc[2][4][4] = {};
    const int niter = K >> 5;

    #pragma unroll
    for (int s = 0; s < NSTAGE - 1; s++) {
        if (s < niter) {
            const uint32_t st = sb + s * STAGE_SZ;
            const int ko = s << 5;
            cp16(st + OA_HI + so, pAh + ko);
            cp16(st + OA_LO + so, pAl + ko);
            cp16(st + OB_HI + so, pBh + ko);
            cp16(st + OB_LO + so, pBl + ko);
        }
        CP_COMMIT();
    }

    for (int it = 0; it < niter; it++) {
        CP_WAIT2();
        __syncthreads();
        {
            const int s = it + NSTAGE - 1;
            if (s < niter) {
                const uint32_t st = sb + (s & (NSTAGE - 1)) * STAGE_SZ;
                const int ko = s << 5;
                cp16(st + OA_HI + so, pAh + ko);
                cp16(st + OA_LO + so, pAl + ko);
                cp16(st + OB_HI + so, pBh + ko);
                cp16(st + OB_LO + so, pBl + ko);
            }
            CP_COMMIT();
        }

        const uint32_t st = sb + (it & (NSTAGE - 1)) * STAGE_SZ;
        #pragma unroll
        for (int ks = 0; ks < 2; ks++) {
            uint32_t ah[2][4], al[2][4], bh[2][4], bl[2][4];
            const int acol = (ks * 16 + (lane >> 4) * 8) * 2;
            #pragma unroll
            for (int mt = 0; mt < 2; mt++) {
                uint32_t ad = st + (wm * 32 + mt * 16 + (lane & 15)) * ROWB + acol;
                ldsm_x4(ah[mt], ad + OA_HI);
                ldsm_x4(al[mt], ad + OA_LO);
            }
            const int bcol = (ks * 16 + ((lane >> 3) & 1) * 8) * 2;
            #pragma unroll
            for (int pr = 0; pr < 2; pr++) {
                uint32_t bd = st + (wn * 32 + pr * 16 + ((lane >> 4) << 3) + (lane & 7)) * ROWB + bcol;
                ldsm_x4(bh[pr], bd + OB_HI);
                ldsm_x4(bl[pr], bd + OB_LO);
            }
            #pragma unroll
            for (int mt = 0; mt < 2; mt++)
                #pragma unroll
                for (int nt = 0; nt < 4; nt++) {
                    const uint32_t* bhp = &bh[nt >> 1][(nt & 1) * 2];
                    const uint32_t* blp = &bl[nt >> 1][(nt & 1) * 2];
                    mma_bf16(acc[mt][nt], ah[mt], bhp);
                    mma_bf16(acc[mt][nt], ah[mt], blp);
                    mma_bf16(acc[mt][nt], al[mt], bhp);
                }
        }
    }

    #pragma unroll
    for (int mt = 0; mt < 2; mt++) {
        #pragma unroll
        for (int half = 0; half < 2; half++) {
            const int mloc = wm * 32 + mt * 16 + half * 8 + (lane >> 2);
            #pragma unroll
            for (int nt = 0; nt < 4; nt++) {
                const int c0 = nb * 128 + wn * 32 + nt * 8 + (lane & 3) * 2;
                float v0 = fmaxf(acc[mt][nt][half * 2 + 0] + bias[c0], 0.f);
                float v1 = fmaxf(acc[mt][nt][half * 2 + 1] + bias[c0 + 1], 0.f);
                size_t base = (size_t)(mtile * 128 + mloc) * N + c0;
                if (MODE == EPI_RELU_SPLIT) {
                    bf16 h0 = __float2bfloat16(v0), h1 = __float2bfloat16(v1);
                    outhi[base] = h0; outhi[base + 1] = h1;
                    outlo[base] = __float2bfloat16(v0 - __bfloat162float(h0));
                    outlo[base + 1] = __float2bfloat16(v1 - __bfloat162float(h1));
                } else {
                    outf[base] = v0; outf[base + 1] = v1;
                }
            }
        }
    }
}

// ================= plain fp16 GEMM (expert + outproj) ========================
// C = A @ W^T. A:[M,K] fp16, W:[N,K] fp16.
#define HEPI_SCATTER 0
#define HEPI_F32     1

#define HSTAGE_SZ 20480
#define HOA 0
#define HOB 10240
#define SMEM_HGEMM (TILES_OFF + NSTAGE * HSTAGE_SZ)   // 83968

template<int MODE, bool GATHER>
__global__ void __launch_bounds__(512, 1) h_gemm(
    const __half* __restrict__ A,
    const __half* __restrict__ W,
    const float* __restrict__ bias,
    float* __restrict__ outf, int N, int K) {
    extern __shared__ char smem[];
    int* s_pid = (int*)smem;
    int* s_tok = (int*)(smem + 512);
    const int tid = threadIdx.x, lane = tid & 31, wid = tid >> 5;
    const int wm = wid >> 2, wn = wid & 3;
    const int nb = blockIdx.x;

    int mtile = blockIdx.y, e = 0;
    if (GATHER) {
        int flat = blockIdx.y, base = 0, cnt = 0;
        bool found = false;
        #pragma unroll
        for (int i = 0; i < NE; i++) {
            int c = g_cnt[i];
            int tiles = (c + 127) >> 7;
            if (!found && flat < base + tiles) { e = i; mtile = flat - base; cnt = c; found = true; }
            base += tiles;
        }
        if (!found) return;
        if (tid < 128) {
            int idx = mtile * 128 + tid;
            int pid = (idx < cnt) ? g_list[e * NT + idx] : -1;
            s_pid[tid] = pid;
            s_tok[tid] = (pid >= 0) ? (pid >> 1) : 0;
        }
        W += (size_t)e * HH * DD;
        bias += (size_t)e * HH;
        __syncthreads();
    }

    const uint32_t sb = smem_u32(smem) + TILES_OFF;

    const int seg = tid & 3;
    const int row = tid >> 2;
    size_t arow = GATHER ? (size_t)s_tok[row] : ((size_t)mtile * 128 + row);
    size_t brow = (size_t)nb * 128 + row;
    const __half* pA = A + arow * K + seg * 8;
    const __half* pB = W + brow * K + seg * 8;
    const uint32_t so = row * ROWB + seg * 16;

    float acc[2][4][4] = {};
    const int niter = K >> 5;

    #pragma unroll
    for (int s = 0; s < NSTAGE - 1; s++) {
        if (s < niter) {
            const uint32_t st = sb + s * HSTAGE_SZ;
            const int ko = s << 5;
            cp16(st + HOA + so, pA + ko);
            cp16(st + HOB + so, pB + ko);
        }
        CP_COMMIT();
    }

    for (int it = 0; it < niter; it++) {
        CP_WAIT2();
        __syncthreads();
        {
            const int s = it + NSTAGE - 1;
            if (s < niter) {
                const uint32_t st = sb + (s & (NSTAGE - 1)) * HSTAGE_SZ;
                const int ko = s << 5;
                cp16(st + HOA + so, pA + ko);
                cp16(st + HOB + so, pB + ko);
            }
            CP_COMMIT();
        }

        const uint32_t st = sb + (it & (NSTAGE - 1)) * HSTAGE_SZ;
        #pragma unroll
        for (int ks = 0; ks < 2; ks++) {
            uint32_t ah[2][4], bb[2][4];
            const int acol = (ks * 16 + (lane >> 4) * 8) * 2;
            #pragma unroll
            for (int mt = 0; mt < 2; mt++) {
                uint32_t ad = st + (wm * 32 + mt * 16 + (lane & 15)) * ROWB + acol;
                ldsm_x4(ah[mt], ad + HOA);
            }
            const int bcol = (ks * 16 + ((lane >> 3) & 1) * 8) * 2;
            #pragma unroll
            for (int pr = 0; pr < 2; pr++) {
                uint32_t bd = st + (wn * 32 + pr * 16 + ((lane >> 4) << 3) + (lane & 7)) * ROWB + bcol;
                ldsm_x4(bb[pr], bd + HOB);
            }
            #pragma unroll
            for (int mt = 0; mt < 2; mt++)
                #pragma unroll
                for (int nt = 0; nt < 4; nt++) {
                    const uint32_t* bp = &bb[nt >> 1][(nt & 1) * 2];
                    mma_f16(acc[mt][nt], ah[mt], bp);
                }
        }
    }

    #pragma unroll
    for (int mt = 0; mt < 2; mt++) {
        #pragma unroll
        for (int half = 0; half < 2; half++) {
            const int mloc = wm * 32 + mt * 16 + half * 8 + (lane >> 2);
            int pid = 0;
            if (GATHER) { pid = s_pid[mloc]; if (pid < 0) continue; }
            #pragma unroll
            for (int nt = 0; nt < 4; nt++) {
                const int c0 = nb * 128 + wn * 32 + nt * 8 + (lane & 3) * 2;
                float v0 = acc[mt][nt][half * 2 + 0] + bias[c0];
                float v1 = acc[mt][nt][half * 2 + 1] + bias[c0 + 1];
                if (MODE == HEPI_SCATTER) {
                    float* dst = outf + (size_t)pid * HH + c0;
                    dst[0] = v0; dst[1] = v1;
                } else {
                    size_t base = (size_t)(mtile * 128 + mloc) * N + c0;
                    outf[base] = v0; outf[base + 1] = v1;
                }
            }
        }
    }
}

// ---------------- combine: moe = relu(w0*p0 + w1*p1) -> fp16 -----------------
__global__ void combine_kernel() {
    int idx = blockIdx.x * blockDim.x + threadIdx.x;   // NT*HH
    int t = idx >> 11;
    size_t a_i = (size_t)idx + (size_t)t * HH;
    float w0 = g_wval[2 * t], w1 = g_wval[2 * t + 1];
    float a = g_pair[a_i];
    float b = g_pair[a_i + HH];
    float v = fmaxf(fmaf(w0, a, w1 * b), 0.f);
    g_mh[idx] = __float2half(v);
}

// ---------------- launch ------------------------------------------------------
extern "C" void kernel_launch(void* const* d_in, const int* in_sizes, int n_in,
                              void* d_out, int out_size) {
    const float* x    = (const float*)d_in[0];
    const int*   ft   = (const int*)  d_in[1];
    const float* gw1  = (const float*)d_in[2];
    const float* gb1  = (const float*)d_in[3];
    const float* gw2  = (const float*)d_in[4];
    const float* gb2  = (const float*)d_in[5];
    const float* gw3  = (const float*)d_in[6];
    const float* gb3  = (const float*)d_in[7];
    const float* temb = (const float*)d_in[8];
    const float* tw   = (const float*)d_in[9];
    const float* tb   = (const float*)d_in[10];
    const float* ew   = (const float*)d_in[11];
    const float* eb   = (const float*)d_in[12];
    const float* ow   = (const float*)d_in[13];
    const float* ob   = (const float*)d_in[14];
    float* out = (float*)d_out;

    bf16 *xhi, *xlo, *h1hi, *h1lo, *w1hi, *w1lo, *w2hi, *w2lo;
    __half *xh, *ewh, *owh, *mh;
    float *h2, *pair;
    cudaGetSymbolAddress((void**)&xhi, g_xhi);   cudaGetSymbolAddress((void**)&xlo, g_xlo);
    cudaGetSymbolAddress((void**)&h1hi, g_h1hi); cudaGetSymbolAddress((void**)&h1lo, g_h1lo);
    cudaGetSymbolAddress((void**)&w1hi, g_w1hi); cudaGetSymbolAddress((void**)&w1lo, g_w1lo);
    cudaGetSymbolAddress((void**)&w2hi, g_w2hi); cudaGetSymbolAddress((void**)&w2lo, g_w2lo);
    cudaGetSymbolAddress((void**)&xh, g_xh);
    cudaGetSymbolAddress((void**)&ewh, g_ewh);   cudaGetSymbolAddress((void**)&owh, g_owh);
    cudaGetSymbolAddress((void**)&mh, g_mh);
    cudaGetSymbolAddress((void**)&h2, g_h2);     cudaGetSymbolAddress((void**)&pair, g_pair);

    cudaFuncSetAttribute(mma_gemm<EPI_RELU_SPLIT>, cudaFuncAttributeMaxDynamicSharedMemorySize, SMEM_GEMM);
    cudaFuncSetAttribute(mma_gemm<EPI_RELU_F32>,   cudaFuncAttributeMaxDynamicSharedMemorySize, SMEM_GEMM);
    cudaFuncSetAttribute(h_gemm<HEPI_SCATTER, true>,  cudaFuncAttributeMaxDynamicSharedMemorySize, SMEM_HGEMM);
    cudaFuncSetAttribute(h_gemm<HEPI_F32,     false>, cudaFuncAttributeMaxDynamicSharedMemorySize, SMEM_HGEMM);

    zero_cnt_kernel<<<1, 32>>>();

    // conversions
    split_x_kernel<<<(NT * DD) / 256, 256>>>(x);
    tsplit_kernel<<<dim3(GHA / 32, DD / 32, 1), dim3(32, 8)>>>(gw1, w1hi, w1lo, DD, GHA);
    tsplit_kernel<<<dim3(GHB / 32, GHA / 32, 1), dim3(32, 8)>>>(gw2, w2hi, w2lo, GHA, GHB);
    tconv_h_kernel<<<dim3(HH / 32, DD / 32, NE), dim3(32, 8)>>>(ew, ewh, DD, HH);
    tconv_h_kernel<<<dim3(DD / 32, HH / 32, 1), dim3(32, 8)>>>(ow, owh, HH, DD);

    // gating MLP (bf16 3-term, routing-grade precision)
    mma_gemm<EPI_RELU_SPLIT><<<dim3(GHA / 128, NT / 128), 512, SMEM_GEMM>>>(
        xhi, xlo, w1hi, w1lo, gb1, nullptr, h1hi, h1lo, GHA, DD);
    mma_gemm<EPI_RELU_F32><<<dim3(GHB / 128, NT / 128), 512, SMEM_GEMM>>>(
        h1hi, h1lo, w2hi, w2lo, gb2, h2, nullptr, nullptr, GHB, GHA);

    // routing
    gating_kernel<<<NT / 8, 256>>>(ft, gw3, gb3, temb, tw, tb);

    // expert grouped GEMM (fp16, gathered A, scattered C)
    h_gemm<HEPI_SCATTER, true><<<dim3(HH / 128, MAX_MTILES), 512, SMEM_HGEMM>>>(
        xh, ewh, eb, pair, HH, DD);

    // combine + relu -> fp16
    combine_kernel<<<(NT * HH) / 256, 256>>>();

    // output projection (fp16)
    h_gemm<HEPI_F32, false><<<dim3(DD / 128, NT / 128), 512, SMEM_HGEMM>>>(
        mh, owh, ob, out, DD, HH);
}

// round 8
// speedup vs baseline: 4.4511x; 1.0910x over previous
#include <cuda_runtime.h>
#include <cuda_bf16.h>
#include <cuda_fp16.h>
#include <cstdint>

#define NT   8192
#define DD   1024
#define GHA  512
#define GHB  256
#define NE   8
#define HH   2048
#define MAX_MTILES 136

typedef __nv_bfloat16 bf16;

// ---------------- scratch ---------------------------------------------------
// gating path (bf16 3-term — routing-grade precision)
__device__ bf16  g_xhi[NT * DD],  g_xlo[NT * DD];
__device__ bf16  g_h1hi[NT * GHA], g_h1lo[NT * GHA];
__device__ float g_h2[NT * GHB];
__device__ bf16  g_w1hi[GHA * DD], g_w1lo[GHA * DD];
__device__ bf16  g_w2hi[GHB * GHA], g_w2lo[GHB * GHA];
// expert/outproj path (plain fp16 GEMMs)
__device__ __half g_xh[NT * DD];
__device__ __half g_ewh[(size_t)NE * HH * DD];             // [E][H][D]
__device__ __half g_owh[(size_t)DD * HH];                  // [D][H]
__device__ __half g_mh[(size_t)NT * HH];
__device__ __half g_pairh[(size_t)NT * 2 * HH];            // fp16 pair buffer
// routing
__device__ float g_wval[NT * 2];
__device__ int   g_cnt[NE];
__device__ int   g_list[NE * NT];

// ---------------- PTX helpers (sm_80+ baseline only) ------------------------
__device__ __forceinline__ uint32_t smem_u32(const void* p) {
    uint32_t a;
    asm("{ .reg .u64 t; cvta.to.shared.u64 t, %1; cvt.u32.u64 %0, t; }" : "=r"(a) : "l"(p));
    return a;
}
__device__ __forceinline__ void cp16(uint32_t s, const void* g) {
    asm volatile("cp.async.cg.shared.global [%0], [%1], 16;" :: "r"(s), "l"(g));
}
#define CP_COMMIT() asm volatile("cp.async.commit_group;" ::: "memory")
#define CP_WAIT2()  asm volatile("cp.async.wait_group 2;" ::: "memory")

__device__ __forceinline__ void ldsm_x4(uint32_t* r, uint32_t a) {
    asm volatile("ldmatrix.sync.aligned.m8n8.x4.shared.b16 {%0,%1,%2,%3}, [%4];"
        : "=r"(r[0]), "=r"(r[1]), "=r"(r[2]), "=r"(r[3]) : "r"(a));
}
__device__ __forceinline__ void mma_bf16(float* c, const uint32_t* a, const uint32_t* b) {
    asm volatile("mma.sync.aligned.m16n8k16.row.col.f32.bf16.bf16.f32 "
        "{%0,%1,%2,%3}, {%4,%5,%6,%7}, {%8,%9}, {%0,%1,%2,%3};"
        : "+f"(c[0]), "+f"(c[1]), "+f"(c[2]), "+f"(c[3])
        : "r"(a[0]), "r"(a[1]), "r"(a[2]), "r"(a[3]), "r"(b[0]), "r"(b[1]));
}
__device__ __forceinline__ void mma_f16(float* c, const uint32_t* a, const uint32_t* b) {
    asm volatile("mma.sync.aligned.m16n8k16.row.col.f32.f16.f16.f32 "
        "{%0,%1,%2,%3}, {%4,%5,%6,%7}, {%8,%9}, {%0,%1,%2,%3};"
        : "+f"(c[0]), "+f"(c[1]), "+f"(c[2]), "+f"(c[3])
        : "r"(a[0]), "r"(a[1]), "r"(a[2]), "r"(a[3]), "r"(b[0]), "r"(b[1]));
}

// ---------------- small kernels ---------------------------------------------
__global__ void zero_cnt_kernel() { if (threadIdx.x < NE) g_cnt[threadIdx.x] = 0; }

// x -> bf16 hi/lo (gating) AND fp16 single (expert), 4 elems/thread
__global__ void split_x_kernel(const float* __restrict__ x) {
    int i4 = blockIdx.x * blockDim.x + threadIdx.x;      // over NT*DD/4
    float4 v = ((const float4*)x)[i4];
    float f[4] = {v.x, v.y, v.z, v.w};
    bf16 bh[4]; bf16 bl[4]; __half hh[4];
    #pragma unroll
    for (int k = 0; k < 4; k++) {
        bh[k] = __float2bfloat16(f[k]);
        bl[k] = __float2bfloat16(f[k] - __bfloat162float(bh[k]));
        hh[k] = __float2half(f[k]);
    }
    __nv_bfloat162* xhi2 = (__nv_bfloat162*)g_xhi;
    __nv_bfloat162* xlo2 = (__nv_bfloat162*)g_xlo;
    __half2* xh2 = (__half2*)g_xh;
    xhi2[2 * i4 + 0] = __nv_bfloat162(bh[0], bh[1]);
    xhi2[2 * i4 + 1] = __nv_bfloat162(bh[2], bh[3]);
    xlo2[2 * i4 + 0] = __nv_bfloat162(bl[0], bl[1]);
    xlo2[2 * i4 + 1] = __nv_bfloat162(bl[2], bl[3]);
    xh2[2 * i4 + 0] = __half2(hh[0], hh[1]);
    xh2[2 * i4 + 1] = __half2(hh[2], hh[3]);
}

// in [R][C] fp32 (+z batch) -> out [C][R] bf16 hi/lo
__global__ void tsplit_kernel(const float* __restrict__ in, bf16* __restrict__ ohi,
                              bf16* __restrict__ olo, int R, int C) {
    __shared__ float t[32][33];
    size_t zoff = (size_t)blockIdx.z * R * C;
    in += zoff; ohi += zoff; olo += zoff;
    int c0 = blockIdx.x * 32, r0 = blockIdx.y * 32;
    for (int i = threadIdx.y; i < 32; i += 8)
        t[i][threadIdx.x] = in[(size_t)(r0 + i) * C + c0 + threadIdx.x];
    __syncthreads();
    for (int i = threadIdx.y; i < 32; i += 8) {
        float v = t[threadIdx.x][i];
        bf16 h = __float2bfloat16(v);
        size_t o = (size_t)(c0 + i) * R + r0 + threadIdx.x;
        ohi[o] = h;
        olo[o] = __float2bfloat16(v - __bfloat162float(h));
    }
}

// in [R][C] fp32 (+z batch) -> out [C][R] fp16 (single limb)
__global__ void tconv_h_kernel(const float* __restrict__ in, __half* __restrict__ o,
                               int R, int C) {
    __shared__ float t[32][33];
    size_t zoff = (size_t)blockIdx.z * R * C;
    in += zoff; o += zoff;
    int c0 = blockIdx.x * 32, r0 = blockIdx.y * 32;
    for (int i = threadIdx.y; i < 32; i += 8)
        t[i][threadIdx.x] = in[(size_t)(r0 + i) * C + c0 + threadIdx.x];
    __syncthreads();
    for (int i = threadIdx.y; i < 32; i += 8)
        o[(size_t)(c0 + i) * R + r0 + threadIdx.x] = __float2half(t[threadIdx.x][i]);
}

// ---------------- gating: logits -> top2 -> routing (smem-cached weights) ----
__global__ void __launch_bounds__(256) gating_kernel(
    const int* __restrict__ ftypes,
    const float* __restrict__ gw3, const float* __restrict__ gb3,
    const float* __restrict__ temb, const float* __restrict__ tw,
    const float* __restrict__ tb) {
    __shared__ float s_g[NE][GHB];     // gw3 transposed, 8KB
    __shared__ float s_t[NE][128];     // tw transposed, 4KB
    __shared__ float s_e[3][128];      // type_emb, 1.5KB
    __shared__ float s_b[NE];
    const int tid = threadIdx.x;
    for (int i = tid; i < NE * GHB; i += 256) {
        int e = i / GHB, j = i % GHB;
        s_g[e][j] = gw3[j * NE + e];
    }
    for (int i = tid; i < NE * 128; i += 256) {
        int e = i / 128, j = i % 128;
        s_t[e][j] = tw[j * NE + e];
    }
    for (int i = tid; i < 3 * 128; i += 256) s_e[i / 128][i % 128] = temb[i];
    if (tid < NE) s_b[tid] = gb3[tid] + tb[tid];
    __syncthreads();

    const int warp = tid >> 5, lane = tid & 31;
    const int t = blockIdx.x * 8 + warp;
    float acc[NE] = {};
    const float4* hrow = (const float4*)(g_h2 + (size_t)t * GHB);
    #pragma unroll
    for (int j4 = lane; j4 < GHB / 4; j4 += 32) {
        float4 hv = hrow[j4];
        #pragma unroll
        for (int e = 0; e < NE; e++) {
            float4 g = ((const float4*)&s_g[e][0])[j4];
            acc[e] = fmaf(hv.x, g.x, fmaf(hv.y, g.y, fmaf(hv.z, g.z, fmaf(hv.w, g.w, acc[e]))));
        }
    }
    int ftv = ftypes[t];
    {
        int j4 = lane;                                  // 128/4 = 32 → one step
        float4 tv = ((const float4*)&s_e[ftv][0])[j4];
        #pragma unroll
        for (int e = 0; e < NE; e++) {
            float4 w = ((const float4*)&s_t[e][0])[j4];
            acc[e] = fmaf(tv.x, w.x, fmaf(tv.y, w.y, fmaf(tv.z, w.z, fmaf(tv.w, w.w, acc[e]))));
        }
    }
    #pragma unroll
    for (int off = 16; off; off >>= 1)
        #pragma unroll
        for (int e = 0; e < NE; e++) acc[e] += __shfl_xor_sync(0xffffffffu, acc[e], off);
    if (lane == 0) {
        float logits[NE];
        #pragma unroll
        for (int e = 0; e < NE; e++) logits[e] = acc[e] + s_b[e];
        int i0 = 0;
        #pragma unroll
        for (int e = 1; e < NE; e++) if (logits[e] > logits[i0]) i0 = e;
        int i1 = (i0 == 0) ? 1 : 0;
        #pragma unroll
        for (int e = 0; e < NE; e++) {
            if (e == i0 || e == i1) continue;
            if (logits[e] > logits[i1]) i1 = e;
        }
        float r = expf(logits[i1] - logits[i0]);
        float inv = 1.f / (1.f + r);
        g_wval[t * 2 + 0] = inv;
        g_wval[t * 2 + 1] = r * inv;
        int s0 = atomicAdd(&g_cnt[i0], 1); g_list[i0 * NT + s0] = t * 2 + 0;
        int s1 = atomicAdd(&g_cnt[i1], 1); g_list[i1 * NT + s1] = t * 2 + 1;
    }
}

// ================= bf16 3-term GEMM (gating layers) ==========================
#define EPI_RELU_SPLIT 0
#define EPI_RELU_F32   1

#define ROWB      80
#define TILES_OFF 2048
#define STAGE_SZ  40960
#define NSTAGE    4
#define OA_HI 0
#define OA_LO 10240
#define OB_HI 20480
#define OB_LO 30720
#define SMEM_GEMM (TILES_OFF + NSTAGE * STAGE_SZ)   // 165888

template<int MODE>
__global__ void __launch_bounds__(512, 1) mma_gemm(
    const bf16* __restrict__ Ahi, const bf16* __restrict__ Alo,
    const bf16* __restrict__ Bhi, const bf16* __restrict__ Blo,
    const float* __restrict__ bias,
    float* __restrict__ outf, bf16* __restrict__ outhi, bf16* __restrict__ outlo,
    int N, int K) {
    extern __shared__ char smem[];
    const int tid = threadIdx.x, lane = tid & 31, wid = tid >> 5;
    const int wm = wid >> 2, wn = wid & 3;
    const int nb = blockIdx.x;
    const int mtile = blockIdx.y;

    const uint32_t sb = smem_u32(smem) + TILES_OFF;

    const int seg = tid & 3;
    const int row = tid >> 2;
    size_t arow = (size_t)mtile * 128 + row;
    size_t brow = (size_t)nb * 128 + row;
    const bf16* pAh = Ahi + arow * K + seg * 8;
    const bf16* pAl = Alo + arow * K + seg * 8;
    const bf16* pBh = Bhi + brow * K + seg * 8;
    const bf16* pBl = Blo + brow * K + seg * 8;
    const uint32_t so = row * ROWB + seg * 16;

    float acc[2][4][4] = {};
    const int niter = K >> 5;

    #pragma unroll
    for (int s = 0; s < NSTAGE - 1; s++) {
        if (s < niter) {
            const uint32_t st = sb + s * STAGE_SZ;
            const int ko = s << 5;
            cp16(st + OA_HI + so, pAh + ko);
            cp16(st + OA_LO + so, pAl + ko);
            cp16(st + OB_HI + so, pBh + ko);
            cp16(st + OB_LO + so, pBl + ko);
        }
        CP_COMMIT();
    }

    for (int it = 0; it < niter; it++) {
        CP_WAIT2();
        __syncthreads();
        {
            const int s = it + NSTAGE - 1;
            if (s < niter) {
                const uint32_t st = sb + (s & (NSTAGE - 1)) * STAGE_SZ;
                const int ko = s << 5;
                cp16(st + OA_HI + so, pAh + ko);
                cp16(st + OA_LO + so, pAl + ko);
                cp16(st + OB_HI + so, pBh + ko);
                cp16(st + OB_LO + so, pBl + ko);
            }
            CP_COMMIT();
        }

        const uint32_t st = sb + (it & (NSTAGE - 1)) * STAGE_SZ;
        #pragma unroll
        for (int ks = 0; ks < 2; ks++) {
            uint32_t ah[2][4], al[2][4], bh[2][4], bl[2][4];
            const int acol = (ks * 16 + (lane >> 4) * 8) * 2;
            #pragma unroll
            for (int mt = 0; mt < 2; mt++) {
                uint32_t ad = st + (wm * 32 + mt * 16 + (lane & 15)) * ROWB + acol;
                ldsm_x4(ah[mt], ad + OA_HI);
                ldsm_x4(al[mt], ad + OA_LO);
            }
            const int bcol = (ks * 16 + ((lane >> 3) & 1) * 8) * 2;
            #pragma unroll
            for (int pr = 0; pr < 2; pr++) {
                uint32_t bd = st + (wn * 32 + pr * 16 + ((lane >> 4) << 3) + (lane & 7)) * ROWB + bcol;
                ldsm_x4(bh[pr], bd + OB_HI);
                ldsm_x4(bl[pr], bd + OB_LO);
            }
            #pragma unroll
            for (int mt = 0; mt < 2; mt++)
                #pragma unroll
                for (int nt = 0; nt < 4; nt++) {
                    const uint32_t* bhp = &bh[nt >> 1][(nt & 1) * 2];
                    const uint32_t* blp = &bl[nt >> 1][(nt & 1) * 2];
                    mma_bf16(acc[mt][nt], ah[mt], bhp);
                    mma_bf16(acc[mt][nt], ah[mt], blp);
                    mma_bf16(acc[mt][nt], al[mt], bhp);
                }
        }
    }

    #pragma unroll
    for (int mt = 0; mt < 2; mt++) {
        #pragma unroll
        for (int half = 0; half < 2; half++) {
            const int mloc = wm * 32 + mt * 16 + half * 8 + (lane >> 2);
            #pragma unroll
            for (int nt = 0; nt < 4; nt++) {
                const int c0 = nb * 128 + wn * 32 + nt * 8 + (lane & 3) * 2;
                float v0 = fmaxf(acc[mt][nt][half * 2 + 0] + bias[c0], 0.f);
                float v1 = fmaxf(acc[mt][nt][half * 2 + 1] + bias[c0 + 1], 0.f);
                size_t base = (size_t)(mtile * 128 + mloc) * N + c0;
                if (MODE == EPI_RELU_SPLIT) {
                    bf16 h0 = __float2bfloat16(v0), h1 = __float2bfloat16(v1);
                    outhi[base] = h0; outhi[base + 1] = h1;
                    outlo[base] = __float2bfloat16(v0 - __bfloat162float(h0));
                    outlo[base + 1] = __float2bfloat16(v1 - __bfloat162float(h1));
                } else {
                    outf[base] = v0; outf[base + 1] = v1;
                }
            }
        }
    }
}

// ================= plain fp16 GEMM (expert + outproj) ========================
#define HEPI_SCATTER 0
#define HEPI_F32     1

#define HSTAGE_SZ 20480
#define HOA 0
#define HOB 10240
#define SMEM_HGEMM (TILES_OFF + NSTAGE * HSTAGE_SZ)   // 83968

template<int MODE, bool GATHER>
__global__ void __launch_bounds__(512, 1) h_gemm(
    const __half* __restrict__ A,
    const __half* __restrict__ W,
    const float* __restrict__ bias,
    float* __restrict__ outf, __half* __restrict__ outh, int N, int K) {
    extern __shared__ char smem[];
    int* s_pid = (int*)smem;
    int* s_tok = (int*)(smem + 512);
    const int tid = threadIdx.x, lane = tid & 31, wid = tid >> 5;
    const int wm = wid >> 2, wn = wid & 3;
    const int nb = blockIdx.x;

    int mtile = blockIdx.y, e = 0;
    if (GATHER) {
        int flat = blockIdx.y, base = 0, cnt = 0;
        bool found = false;
        #pragma unroll
        for (int i = 0; i < NE; i++) {
            int c = g_cnt[i];
            int tiles = (c + 127) >> 7;
            if (!found && flat < base + tiles) { e = i; mtile = flat - base; cnt = c; found = true; }
            base += tiles;
        }
        if (!found) return;
        if (tid < 128) {
            int idx = mtile * 128 + tid;
            int pid = (idx < cnt) ? g_list[e * NT + idx] : -1;
            s_pid[tid] = pid;
            s_tok[tid] = (pid >= 0) ? (pid >> 1) : 0;
        }
        W += (size_t)e * HH * DD;
        bias += (size_t)e * HH;
        __syncthreads();
    }

    const uint32_t sb = smem_u32(smem) + TILES_OFF;

    const int seg = tid & 3;
    const int row = tid >> 2;
    size_t arow = GATHER ? (size_t)s_tok[row] : ((size_t)mtile * 128 + row);
    size_t brow = (size_t)nb * 128 + row;
    const __half* pA = A + arow * K + seg * 8;
    const __half* pB = W + brow * K + seg * 8;
    const uint32_t so = row * ROWB + seg * 16;

    float acc[2][4][4] = {};
    const int niter = K >> 5;

    #pragma unroll
    for (int s = 0; s < NSTAGE - 1; s++) {
        if (s < niter) {
            const uint32_t st = sb + s * HSTAGE_SZ;
            const int ko = s << 5;
            cp16(st + HOA + so, pA + ko);
            cp16(st + HOB + so, pB + ko);
        }
        CP_COMMIT();
    }

    for (int it = 0; it < niter; it++) {
        CP_WAIT2();
        __syncthreads();
        {
            const int s = it + NSTAGE - 1;
            if (s < niter) {
                const uint32_t st = sb + (s & (NSTAGE - 1)) * HSTAGE_SZ;
                const int ko = s << 5;
                cp16(st + HOA + so, pA + ko);
                cp16(st + HOB + so, pB + ko);
            }
            CP_COMMIT();
        }

        const uint32_t st = sb + (it & (NSTAGE - 1)) * HSTAGE_SZ;
        #pragma unroll
        for (int ks = 0; ks < 2; ks++) {
            uint32_t ah[2][4], bb[2][4];
            const int acol = (ks * 16 + (lane >> 4) * 8) * 2;
            #pragma unroll
            for (int mt = 0; mt < 2; mt++) {
                uint32_t ad = st + (wm * 32 + mt * 16 + (lane & 15)) * ROWB + acol;
                ldsm_x4(ah[mt], ad + HOA);
            }
            const int bcol = (ks * 16 + ((lane >> 3) & 1) * 8) * 2;
            #pragma unroll
            for (int pr = 0; pr < 2; pr++) {
                uint32_t bd = st + (wn * 32 + pr * 16 + ((lane >> 4) << 3) + (lane & 7)) * ROWB + bcol;
                ldsm_x4(bb[pr], bd + HOB);
            }
            #pragma unroll
            for (int mt = 0; mt < 2; mt++)
                #pragma unroll
                for (int nt = 0; nt < 4; nt++) {
                    const uint32_t* bp = &bb[nt >> 1][(nt & 1) * 2];
                    mma_f16(acc[mt][nt], ah[mt], bp);
                }
        }
    }

    #pragma unroll
    for (int mt = 0; mt < 2; mt++) {
        #pragma unroll
        for (int half = 0; half < 2; half++) {
            const int mloc = wm * 32 + mt * 16 + half * 8 + (lane >> 2);
            int pid = 0;
            if (GATHER) { pid = s_pid[mloc]; if (pid < 0) continue; }
            #pragma unroll
            for (int nt = 0; nt < 4; nt++) {
                const int c0 = nb * 128 + wn * 32 + nt * 8 + (lane & 3) * 2;
                float v0 = acc[mt][nt][half * 2 + 0] + bias[c0];
                float v1 = acc[mt][nt][half * 2 + 1] + bias[c0 + 1];
                if (MODE == HEPI_SCATTER) {
                    __half2* dst = (__half2*)(outh + (size_t)pid * HH + c0);
                    *dst = __floats2half2_rn(v0, v1);
                } else {
                    size_t base = (size_t)(mtile * 128 + mloc) * N + c0;
                    outf[base] = v0; outf[base + 1] = v1;
                }
            }
        }
    }
}

// ---------------- combine: moe = relu(w0*p0 + w1*p1) -> fp16 (half2) ---------
__global__ void combine_kernel() {
    int idx = blockIdx.x * blockDim.x + threadIdx.x;   // over NT*HH/2
    int t = idx >> 10;                                 // HH/2 = 1024
    int c = idx & 1023;
    float w0 = g_wval[2 * t], w1 = g_wval[2 * t + 1];
    const __half2* p = (const __half2*)g_pairh;
    float2 a = __half22float2(p[(size_t)t * HH + c]);
    float2 b = __half22float2(p[(size_t)t * HH + (HH / 2) + c]);
    float v0 = fmaxf(fmaf(w0, a.x, w1 * b.x), 0.f);
    float v1 = fmaxf(fmaf(w0, a.y, w1 * b.y), 0.f);
    ((__half2*)g_mh)[idx] = __floats2half2_rn(v0, v1);
}

// ---------------- launch ------------------------------------------------------
extern "C" void kernel_launch(void* const* d_in, const int* in_sizes, int n_in,
                              void* d_out, int out_size) {
    const float* x    = (const float*)d_in[0];
    const int*   ft   = (const int*)  d_in[1];
    const float* gw1  = (const float*)d_in[2];
    const float* gb1  = (const float*)d_in[3];
    const float* gw2  = (const float*)d_in[4];
    const float* gb2  = (const float*)d_in[5];
    const float* gw3  = (const float*)d_in[6];
    const float* gb3  = (const float*)d_in[7];
    const float* temb = (const float*)d_in[8];
    const float* tw   = (const float*)d_in[9];
    const float* tb   = (const float*)d_in[10];
    const float* ew   = (const float*)d_in[11];
    const float* eb   = (const float*)d_in[12];
    const float* ow   = (const float*)d_in[13];
    const float* ob   = (const float*)d_in[14];
    float* out = (float*)d_out;

    bf16 *xhi, *xlo, *h1hi, *h1lo, *w1hi, *w1lo, *w2hi, *w2lo;
    __half *xh, *ewh, *owh, *mh, *pairh;
    float *h2;
    cudaGetSymbolAddress((void**)&xhi, g_xhi);   cudaGetSymbolAddress((void**)&xlo, g_xlo);
    cudaGetSymbolAddress((void**)&h1hi, g_h1hi); cudaGetSymbolAddress((void**)&h1lo, g_h1lo);
    cudaGetSymbolAddress((void**)&w1hi, g_w1hi); cudaGetSymbolAddress((void**)&w1lo, g_w1lo);
    cudaGetSymbolAddress((void**)&w2hi, g_w2hi); cudaGetSymbolAddress((void**)&w2lo, g_w2lo);
    cudaGetSymbolAddress((void**)&xh, g_xh);
    cudaGetSymbolAddress((void**)&ewh, g_ewh);   cudaGetSymbolAddress((void**)&owh, g_owh);
    cudaGetSymbolAddress((void**)&mh, g_mh);     cudaGetSymbolAddress((void**)&pairh, g_pairh);
    cudaGetSymbolAddress((void**)&h2, g_h2);

    cudaFuncSetAttribute(mma_gemm<EPI_RELU_SPLIT>, cudaFuncAttributeMaxDynamicSharedMemorySize, SMEM_GEMM);
    cudaFuncSetAttribute(mma_gemm<EPI_RELU_F32>,   cudaFuncAttributeMaxDynamicSharedMemorySize, SMEM_GEMM);
    cudaFuncSetAttribute(h_gemm<HEPI_SCATTER, true>,  cudaFuncAttributeMaxDynamicSharedMemorySize, SMEM_HGEMM);
    cudaFuncSetAttribute(h_gemm<HEPI_F32,     false>, cudaFuncAttributeMaxDynamicSharedMemorySize, SMEM_HGEMM);

    zero_cnt_kernel<<<1, 32>>>();

    // conversions
    split_x_kernel<<<(NT * DD / 4) / 256, 256>>>(x);
    tsplit_kernel<<<dim3(GHA / 32, DD / 32, 1), dim3(32, 8)>>>(gw1, w1hi, w1lo, DD, GHA);
    tsplit_kernel<<<dim3(GHB / 32, GHA / 32, 1), dim3(32, 8)>>>(gw2, w2hi, w2lo, GHA, GHB);
    tconv_h_kernel<<<dim3(HH / 32, DD / 32, NE), dim3(32, 8)>>>(ew, ewh, DD, HH);
    tconv_h_kernel<<<dim3(DD / 32, HH / 32, 1), dim3(32, 8)>>>(ow, owh, HH, DD);

    // gating MLP (bf16 3-term, routing-grade precision)
    mma_gemm<EPI_RELU_SPLIT><<<dim3(GHA / 128, NT / 128), 512, SMEM_GEMM>>>(
        xhi, xlo, w1hi, w1lo, gb1, nullptr, h1hi, h1lo, GHA, DD);
    mma_gemm<EPI_RELU_F32><<<dim3(GHB / 128, NT / 128), 512, SMEM_GEMM>>>(
        h1hi, h1lo, w2hi, w2lo, gb2, h2, nullptr, nullptr, GHB, GHA);

    // routing
    gating_kernel<<<NT / 8, 256>>>(ft, gw3, gb3, temb, tw, tb);

    // expert grouped GEMM (fp16, gathered A, scattered fp16 C)
    h_gemm<HEPI_SCATTER, true><<<dim3(HH / 128, MAX_MTILES), 512, SMEM_HGEMM>>>(
        xh, ewh, eb, nullptr, pairh, HH, DD);

    // combine + relu -> fp16
    combine_kernel<<<(NT * HH / 2) / 256, 256>>>();

    // output projection (fp16)
    h_gemm<HEPI_F32, false><<<dim3(DD / 128, NT / 128), 512, SMEM_HGEMM>>>(
        mh, owh, ob, out, nullptr, DD, HH);
}

// round 9
// speedup vs baseline: 4.6035x; 1.0342x over previous
#include <cuda_runtime.h>
#include <cuda_bf16.h>
#include <cuda_fp16.h>
#include <cstdint>

#define NT   8192
#define DD   1024
#define GHA  512
#define GHB  256
#define NE   8
#define HH   2048
#define MAX_MTILES 136

typedef __nv_bfloat16 bf16;

// ---------------- scratch ---------------------------------------------------
__device__ bf16  g_xhi[NT * DD],  g_xlo[NT * DD];
__device__ bf16  g_h1hi[NT * GHA], g_h1lo[NT * GHA];
__device__ float g_h2[NT * GHB];
__device__ bf16  g_w1hi[GHA * DD], g_w1lo[GHA * DD];
__device__ bf16  g_w2hi[GHB * GHA], g_w2lo[GHB * GHA];
__device__ __half g_xh[NT * DD];
__device__ __half g_ewh[(size_t)NE * HH * DD];             // [E][H][D]
__device__ __half g_owh[(size_t)DD * HH];                  // [D][H]
__device__ __half g_mh[(size_t)NT * HH];
__device__ __half g_pairh[(size_t)NT * 2 * HH];
__device__ float g_wval[NT * 2];
__device__ int   g_cnt[NE];
__device__ int   g_list[NE * NT];

// ---------------- PTX helpers (sm_80+ baseline only) ------------------------
__device__ __forceinline__ uint32_t smem_u32(const void* p) {
    uint32_t a;
    asm("{ .reg .u64 t; cvta.to.shared.u64 t, %1; cvt.u32.u64 %0, t; }" : "=r"(a) : "l"(p));
    return a;
}
__device__ __forceinline__ void cp16(uint32_t s, const void* g) {
    asm volatile("cp.async.cg.shared.global [%0], [%1], 16;" :: "r"(s), "l"(g));
}
#define CP_COMMIT() asm volatile("cp.async.commit_group;" ::: "memory")
#define CP_WAIT2()  asm volatile("cp.async.wait_group 2;" ::: "memory")

__device__ __forceinline__ void ldsm_x4(uint32_t* r, uint32_t a) {
    asm volatile("ldmatrix.sync.aligned.m8n8.x4.shared.b16 {%0,%1,%2,%3}, [%4];"
        : "=r"(r[0]), "=r"(r[1]), "=r"(r[2]), "=r"(r[3]) : "r"(a));
}
__device__ __forceinline__ void mma_bf16(float* c, const uint32_t* a, const uint32_t* b) {
    asm volatile("mma.sync.aligned.m16n8k16.row.col.f32.bf16.bf16.f32 "
        "{%0,%1,%2,%3}, {%4,%5,%6,%7}, {%8,%9}, {%0,%1,%2,%3};"
        : "+f"(c[0]), "+f"(c[1]), "+f"(c[2]), "+f"(c[3])
        : "r"(a[0]), "r"(a[1]), "r"(a[2]), "r"(a[3]), "r"(b[0]), "r"(b[1]));
}
__device__ __forceinline__ void mma_f16(float* c, const uint32_t* a, const uint32_t* b) {
    asm volatile("mma.sync.aligned.m16n8k16.row.col.f32.f16.f16.f32 "
        "{%0,%1,%2,%3}, {%4,%5,%6,%7}, {%8,%9}, {%0,%1,%2,%3};"
        : "+f"(c[0]), "+f"(c[1]), "+f"(c[2]), "+f"(c[3])
        : "r"(a[0]), "r"(a[1]), "r"(a[2]), "r"(a[3]), "r"(b[0]), "r"(b[1]));
}

// ---------------- fused prep kernel ------------------------------------------
// sections (flat blockIdx.x):
//   [0, 8192)            split_x (4 elems/thread) + zero_cnt in block 0
//   [8192, 8704)         tsplit gw1   (bx over GHA/32=16, by over DD/32=32)
//   [8704, 8832)         tsplit gw2   (bx over GHB/32=8,  by over GHA/32=16)
//   [8832, 25216)        tconv ew     (bx over HH/32=64,  by over DD/32=32, z 8)
//   [25216, 27264)       tconv ow     (bx over DD/32=32,  by over HH/32=64)
#define PREP_BLOCKS 27264

__global__ void __launch_bounds__(256) prep_kernel(
    const float* __restrict__ x, const float* __restrict__ gw1,
    const float* __restrict__ gw2, const float* __restrict__ ew,
    const float* __restrict__ ow) {
    __shared__ float t[32][33];
    int b = blockIdx.x;
    const int tid = threadIdx.x;

    if (b < 8192) {
        if (b == 0 && tid < NE) g_cnt[tid] = 0;
        int i4 = b * 256 + tid;
        float4 v = ((const float4*)x)[i4];
        float f[4] = {v.x, v.y, v.z, v.w};
        bf16 bh[4]; bf16 bl[4]; __half hh[4];
        #pragma unroll
        for (int k = 0; k < 4; k++) {
            bh[k] = __float2bfloat16(f[k]);
            bl[k] = __float2bfloat16(f[k] - __bfloat162float(bh[k]));
            hh[k] = __float2half(f[k]);
        }
        __nv_bfloat162* xhi2 = (__nv_bfloat162*)g_xhi;
        __nv_bfloat162* xlo2 = (__nv_bfloat162*)g_xlo;
        __half2* xh2 = (__half2*)g_xh;
        xhi2[2 * i4 + 0] = __nv_bfloat162(bh[0], bh[1]);
        xhi2[2 * i4 + 1] = __nv_bfloat162(bh[2], bh[3]);
        xlo2[2 * i4 + 0] = __nv_bfloat162(bl[0], bl[1]);
        xlo2[2 * i4 + 1] = __nv_bfloat162(bl[2], bl[3]);
        xh2[2 * i4 + 0] = __half2(hh[0], hh[1]);
        xh2[2 * i4 + 1] = __half2(hh[2], hh[3]);
        return;
    }
    b -= 8192;

    const float* in;
    bf16 *ohi = nullptr, *olo = nullptr;
    __half* oh = nullptr;
    int R, C, bx, by;
    size_t zoff = 0;
    bool half_mode;
    if (b < 512) {
        half_mode = false; in = gw1; ohi = g_w1hi; olo = g_w1lo;
        R = DD; C = GHA; bx = b % 16; by = b / 16;
    } else if (b < 640) {
        b -= 512;
        half_mode = false; in = gw2; ohi = g_w2hi; olo = g_w2lo;
        R = GHA; C = GHB; bx = b % 8; by = b / 8;
    } else if (b < 640 + 16384) {
        b -= 640;
        half_mode = true; in = ew; oh = g_ewh;
        R = DD; C = HH; bx = b % 64; by = (b / 64) % 32;
        zoff = (size_t)(b / (64 * 32)) * R * C;
    } else {
        b -= 640 + 16384;
        half_mode = true; in = ow; oh = g_owh;
        R = HH; C = DD; bx = b % 32; by = b / 32;
    }
    in += zoff;
    const int c0 = bx * 32, r0 = by * 32;
    const int tx = tid & 31, ty = tid >> 5;
    for (int i = ty; i < 32; i += 8)
        t[i][tx] = in[(size_t)(r0 + i) * C + c0 + tx];
    __syncthreads();
    if (half_mode) {
        oh += zoff;
        for (int i = ty; i < 32; i += 8)
            oh[(size_t)(c0 + i) * R + r0 + tx] = __float2half(t[tx][i]);
    } else {
        for (int i = ty; i < 32; i += 8) {
            float v = t[tx][i];
            bf16 h = __float2bfloat16(v);
            size_t o = (size_t)(c0 + i) * R + r0 + tx;
            ohi[o] = h;
            olo[o] = __float2bfloat16(v - __bfloat162float(h));
        }
    }
}

// ---------------- gating: logits -> top2 -> routing (smem-cached weights) ----
__global__ void __launch_bounds__(256) gating_kernel(
    const int* __restrict__ ftypes,
    const float* __restrict__ gw3, const float* __restrict__ gb3,
    const float* __restrict__ temb, const float* __restrict__ tw,
    const float* __restrict__ tb) {
    __shared__ float s_g[NE][GHB];
    __shared__ float s_t[NE][128];
    __shared__ float s_e[3][128];
    __shared__ float s_b[NE];
    const int tid = threadIdx.x;
    for (int i = tid; i < NE * GHB; i += 256) {
        int e = i / GHB, j = i % GHB;
        s_g[e][j] = gw3[j * NE + e];
    }
    for (int i = tid; i < NE * 128; i += 256) {
        int e = i / 128, j = i % 128;
        s_t[e][j] = tw[j * NE + e];
    }
    for (int i = tid; i < 3 * 128; i += 256) s_e[i / 128][i % 128] = temb[i];
    if (tid < NE) s_b[tid] = gb3[tid] + tb[tid];
    __syncthreads();

    const int warp = tid >> 5, lane = tid & 31;
    const int t = blockIdx.x * 8 + warp;
    float acc[NE] = {};
    const float4* hrow = (const float4*)(g_h2 + (size_t)t * GHB);
    #pragma unroll
    for (int j4 = lane; j4 < GHB / 4; j4 += 32) {
        float4 hv = hrow[j4];
        #pragma unroll
        for (int e = 0; e < NE; e++) {
            float4 g = ((const float4*)&s_g[e][0])[j4];
            acc[e] = fmaf(hv.x, g.x, fmaf(hv.y, g.y, fmaf(hv.z, g.z, fmaf(hv.w, g.w, acc[e]))));
        }
    }
    int ftv = ftypes[t];
    {
        int j4 = lane;
        float4 tv = ((const float4*)&s_e[ftv][0])[j4];
        #pragma unroll
        for (int e = 0; e < NE; e++) {
            float4 w = ((const float4*)&s_t[e][0])[j4];
            acc[e] = fmaf(tv.x, w.x, fmaf(tv.y, w.y, fmaf(tv.z, w.z, fmaf(tv.w, w.w, acc[e]))));
        }
    }
    #pragma unroll
    for (int off = 16; off; off >>= 1)
        #pragma unroll
        for (int e = 0; e < NE; e++) acc[e] += __shfl_xor_sync(0xffffffffu, acc[e], off);
    if (lane == 0) {
        float logits[NE];
        #pragma unroll
        for (int e = 0; e < NE; e++) logits[e] = acc[e] + s_b[e];
        int i0 = 0;
        #pragma unroll
        for (int e = 1; e < NE; e++) if (logits[e] > logits[i0]) i0 = e;
        int i1 = (i0 == 0) ? 1 : 0;
        #pragma unroll
        for (int e = 0; e < NE; e++) {
            if (e == i0 || e == i1) continue;
            if (logits[e] > logits[i1]) i1 = e;
        }
        float r = expf(logits[i1] - logits[i0]);
        float inv = 1.f / (1.f + r);
        g_wval[t * 2 + 0] = inv;
        g_wval[t * 2 + 1] = r * inv;
        int s0 = atomicAdd(&g_cnt[i0], 1); g_list[i0 * NT + s0] = t * 2 + 0;
        int s1 = atomicAdd(&g_cnt[i1], 1); g_list[i1 * NT + s1] = t * 2 + 1;
    }
}

// ================= bf16 3-term GEMM (gating layers), K-chunk 32 ==============
#define EPI_RELU_SPLIT 0
#define EPI_RELU_F32   1

#define ROWB      80
#define TILES_OFF 2048
#define STAGE_SZ  40960
#define NSTAGE    4
#define OA_HI 0
#define OA_LO 10240
#define OB_HI 20480
#define OB_LO 30720
#define SMEM_GEMM (TILES_OFF + NSTAGE * STAGE_SZ)   // 165888

template<int MODE>
__global__ void __launch_bounds__(512, 1) mma_gemm(
    const bf16* __restrict__ Ahi, const bf16* __restrict__ Alo,
    const bf16* __restrict__ Bhi, const bf16* __restrict__ Blo,
    const float* __restrict__ bias,
    float* __restrict__ outf, bf16* __restrict__ outhi, bf16* __restrict__ outlo,
    int N, int K) {
    extern __shared__ char smem[];
    const int tid = threadIdx.x, lane = tid & 31, wid = tid >> 5;
    const int wm = wid >> 2, wn = wid & 3;
    const int nb = blockIdx.x;
    const int mtile = blockIdx.y;

    const uint32_t sb = smem_u32(smem) + TILES_OFF;

    const int seg = tid & 3;
    const int row = tid >> 2;
    size_t arow = (size_t)mtile * 128 + row;
    size_t brow = (size_t)nb * 128 + row;
    const bf16* pAh = Ahi + arow * K + seg * 8;
    const bf16* pAl = Alo + arow * K + seg * 8;
    const bf16* pBh = Bhi + brow * K + seg * 8;
    const bf16* pBl = Blo + brow * K + seg * 8;
    const uint32_t so = row * ROWB + seg * 16;

    float acc[2][4][4] = {};
    const int niter = K >> 5;

    #pragma unroll
    for (int s = 0; s < NSTAGE - 1; s++) {
        if (s < niter) {
            const uint32_t st = sb + s * STAGE_SZ;
            const int ko = s << 5;
            cp16(st + OA_HI + so, pAh + ko);
            cp16(st + OA_LO + so, pAl + ko);
            cp16(st + OB_HI + so, pBh + ko);
            cp16(st + OB_LO + so, pBl + ko);
        }
        CP_COMMIT();
    }

    for (int it = 0; it < niter; it++) {
        CP_WAIT2();
        __syncthreads();
        {
            const int s = it + NSTAGE - 1;
            if (s < niter) {
                const uint32_t st = sb + (s & (NSTAGE - 1)) * STAGE_SZ;
                const int ko = s << 5;
                cp16(st + OA_HI + so, pAh + ko);
                cp16(st + OA_LO + so, pAl + ko);
                cp16(st + OB_HI + so, pBh + ko);
                cp16(st + OB_LO + so, pBl + ko);
            }
            CP_COMMIT();
        }

        const uint32_t st = sb + (it & (NSTAGE - 1)) * STAGE_SZ;
        #pragma unroll
        for (int ks = 0; ks < 2; ks++) {
            uint32_t ah[2][4], al[2][4], bh[2][4], bl[2][4];
            const int acol = (ks * 16 + (lane >> 4) * 8) * 2;
            #pragma unroll
            for (int mt = 0; mt < 2; mt++) {
                uint32_t ad = st + (wm * 32 + mt * 16 + (lane & 15)) * ROWB + acol;
                ldsm_x4(ah[mt], ad + OA_HI);
                ldsm_x4(al[mt], ad + OA_LO);
            }
            const int bcol = (ks * 16 + ((lane >> 3) & 1) * 8) * 2;
            #pragma unroll
            for (int pr = 0; pr < 2; pr++) {
                uint32_t bd = st + (wn * 32 + pr * 16 + ((lane >> 4) << 3) + (lane & 7)) * ROWB + bcol;
                ldsm_x4(bh[pr], bd + OB_HI);
                ldsm_x4(bl[pr], bd + OB_LO);
            }
            #pragma unroll
            for (int mt = 0; mt < 2; mt++)
                #pragma unroll
                for (int nt = 0; nt < 4; nt++) {
                    const uint32_t* bhp = &bh[nt >> 1][(nt & 1) * 2];
                    const uint32_t* blp = &bl[nt >> 1][(nt & 1) * 2];
                    mma_bf16(acc[mt][nt], ah[mt], bhp);
                    mma_bf16(acc[mt][nt], ah[mt], blp);
                    mma_bf16(acc[mt][nt], al[mt], bhp);
                }
        }
    }

    #pragma unroll
    for (int mt = 0; mt < 2; mt++) {
        #pragma unroll
        for (int half = 0; half < 2; half++) {
            const int mloc = wm * 32 + mt * 16 + half * 8 + (lane >> 2);
            #pragma unroll
            for (int nt = 0; nt < 4; nt++) {
                const int c0 = nb * 128 + wn * 32 + nt * 8 + (lane & 3) * 2;
                float v0 = fmaxf(acc[mt][nt][half * 2 + 0] + bias[c0], 0.f);
                float v1 = fmaxf(acc[mt][nt][half * 2 + 1] + bias[c0 + 1], 0.f);
                size_t base = (size_t)(mtile * 128 + mloc) * N + c0;
                if (MODE == EPI_RELU_SPLIT) {
                    bf16 h0 = __float2bfloat16(v0), h1 = __float2bfloat16(v1);
                    outhi[base] = h0; outhi[base + 1] = h1;
                    outlo[base] = __float2bfloat16(v0 - __bfloat162float(h0));
                    outlo[base + 1] = __float2bfloat16(v1 - __bfloat162float(h1));
                } else {
                    outf[base] = v0; outf[base + 1] = v1;
                }
            }
        }
    }
}

// ================= plain fp16 GEMM (expert + outproj), K-chunk 64 ============
#define HEPI_SCATTER 0
#define HEPI_F32     1

#define HROWB     144            // 128 data bytes + 16 pad
#define HTILE_SZ  18432          // 128 * 144
#define HSTAGE_SZ 36864
#define HOA 0
#define HOB 18432
#define SMEM_HGEMM (TILES_OFF + NSTAGE * HSTAGE_SZ)   // 149504

template<int MODE, bool GATHER>
__global__ void __launch_bounds__(512, 1) h_gemm(
    const __half* __restrict__ A,
    const __half* __restrict__ W,
    const float* __restrict__ bias,
    float* __restrict__ outf, __half* __restrict__ outh, int N, int K) {
    extern __shared__ char smem[];
    int* s_pid = (int*)smem;
    int* s_tok = (int*)(smem + 512);
    const int tid = threadIdx.x, lane = tid & 31, wid = tid >> 5;
    const int wm = wid >> 2, wn = wid & 3;
    const int nb = blockIdx.x;

    int mtile = blockIdx.y, e = 0;
    if (GATHER) {
        int flat = blockIdx.y, base = 0, cnt = 0;
        bool found = false;
        #pragma unroll
        for (int i = 0; i < NE; i++) {
            int c = g_cnt[i];
            int tiles = (c + 127) >> 7;
            if (!found && flat < base + tiles) { e = i; mtile = flat - base; cnt = c; found = true; }
            base += tiles;
        }
        if (!found) return;
        if (tid < 128) {
            int idx = mtile * 128 + tid;
            int pid = (idx < cnt) ? g_list[e * NT + idx] : -1;
            s_pid[tid] = pid;
            s_tok[tid] = (pid >= 0) ? (pid >> 1) : 0;
        }
        W += (size_t)e * HH * DD;
        bias += (size_t)e * HH;
        __syncthreads();
    }

    const uint32_t sb = smem_u32(smem) + TILES_OFF;

    // K-chunk 64: each row = 64 halves = 128B = 8 segments of 16B.
    // 4 threads/row; each thread covers segments {seg, seg+4}.
    const int seg = tid & 3;
    const int row = tid >> 2;
    size_t arow = GATHER ? (size_t)s_tok[row] : ((size_t)mtile * 128 + row);
    size_t brow = (size_t)nb * 128 + row;
    const __half* pA = A + arow * K + seg * 8;
    const __half* pB = W + brow * K + seg * 8;
    const uint32_t so = row * HROWB + seg * 16;

    float acc[2][4][4] = {};
    const int niter = K >> 6;

    #pragma unroll
    for (int s = 0; s < NSTAGE - 1; s++) {
        if (s < niter) {
            const uint32_t st = sb + s * HSTAGE_SZ;
            const int ko = s << 6;
            cp16(st + HOA + so,      pA + ko);
            cp16(st + HOA + so + 64, pA + ko + 32);
            cp16(st + HOB + so,      pB + ko);
            cp16(st + HOB + so + 64, pB + ko + 32);
        }
        CP_COMMIT();
    }

    for (int it = 0; it < niter; it++) {
        CP_WAIT2();
        __syncthreads();
        {
            const int s = it + NSTAGE - 1;
            if (s < niter) {
                const uint32_t st = sb + (s & (NSTAGE - 1)) * HSTAGE_SZ;
                const int ko = s << 6;
                cp16(st + HOA + so,      pA + ko);
                cp16(st + HOA + so + 64, pA + ko + 32);
                cp16(st + HOB + so,      pB + ko);
                cp16(st + HOB + so + 64, pB + ko + 32);
            }
            CP_COMMIT();
        }

        const uint32_t st = sb + (it & (NSTAGE - 1)) * HSTAGE_SZ;
        #pragma unroll
        for (int ks = 0; ks < 4; ks++) {
            uint32_t ah[2][4], bb[2][4];
            const int acol = (ks * 16 + (lane >> 4) * 8) * 2;
            #pragma unroll
            for (int mt = 0; mt < 2; mt++) {
                uint32_t ad = st + (wm * 32 + mt * 16 + (lane & 15)) * HROWB + acol;
                ldsm_x4(ah[mt], ad + HOA);
            }
            const int bcol = (ks * 16 + ((lane >> 3) & 1) * 8) * 2;
            #pragma unroll
            for (int pr = 0; pr < 2; pr++) {
                uint32_t bd = st + (wn * 32 + pr * 16 + ((lane >> 4) << 3) + (lane & 7)) * HROWB + bcol;
                ldsm_x4(bb[pr], bd + HOB);
            }
            #pragma unroll
            for (int mt = 0; mt < 2; mt++)
                #pragma unroll
                for (int nt = 0; nt < 4; nt++) {
                    const uint32_t* bp = &bb[nt >> 1][(nt & 1) * 2];
                    mma_f16(acc[mt][nt], ah[mt], bp);
                }
        }
    }

    #pragma unroll
    for (int mt = 0; mt < 2; mt++) {
        #pragma unroll
        for (int half = 0; half < 2; half++) {
            const int mloc = wm * 32 + mt * 16 + half * 8 + (lane >> 2);
            int pid = 0;
            if (GATHER) { pid = s_pid[mloc]; if (pid < 0) continue; }
            #pragma unroll
            for (int nt = 0; nt < 4; nt++) {
                const int c0 = nb * 128 + wn * 32 + nt * 8 + (lane & 3) * 2;
                float v0 = acc[mt][nt][half * 2 + 0] + bias[c0];
                float v1 = acc[mt][nt][half * 2 + 1] + bias[c0 + 1];
                if (MODE == HEPI_SCATTER) {
                    __half2* dst = (__half2*)(outh + (size_t)pid * HH + c0);
                    *dst = __floats2half2_rn(v0, v1);
                } else {
                    size_t base = (size_t)(mtile * 128 + mloc) * N + c0;
                    outf[base] = v0; outf[base + 1] = v1;
                }
            }
        }
    }
}

// ---------------- combine: moe = relu(w0*p0 + w1*p1) -> fp16 (half2) ---------
__global__ void combine_kernel() {
    int idx = blockIdx.x * blockDim.x + threadIdx.x;   // over NT*HH/2
    int t = idx >> 10;                                 // HH/2 = 1024
    int c = idx & 1023;
    float w0 = g_wval[2 * t], w1 = g_wval[2 * t + 1];
    const __half2* p = (const __half2*)g_pairh;
    float2 a = __half22float2(p[(size_t)t * HH + c]);
    float2 b = __half22float2(p[(size_t)t * HH + (HH / 2) + c]);
    float v0 = fmaxf(fmaf(w0, a.x, w1 * b.x), 0.f);
    float v1 = fmaxf(fmaf(w0, a.y, w1 * b.y), 0.f);
    ((__half2*)g_mh)[idx] = __floats2half2_rn(v0, v1);
}

// ---------------- launch ------------------------------------------------------
extern "C" void kernel_launch(void* const* d_in, const int* in_sizes, int n_in,
                              void* d_out, int out_size) {
    const float* x    = (const float*)d_in[0];
    const int*   ft   = (const int*)  d_in[1];
    const float* gw1  = (const float*)d_in[2];
    const float* gb1  = (const float*)d_in[3];
    const float* gw2  = (const float*)d_in[4];
    const float* gb2  = (const float*)d_in[5];
    const float* gw3  = (const float*)d_in[6];
    const float* gb3  = (const float*)d_in[7];
    const float* temb = (const float*)d_in[8];
    const float* tw   = (const float*)d_in[9];
    const float* tb   = (const float*)d_in[10];
    const float* ew   = (const float*)d_in[11];
    const float* eb   = (const float*)d_in[12];
    const float* ow   = (const float*)d_in[13];
    const float* ob   = (const float*)d_in[14];
    float* out = (float*)d_out;

    bf16 *xhi, *xlo, *h1hi, *h1lo, *w1hi, *w1lo, *w2hi, *w2lo;
    __half *xh, *ewh, *owh, *mh, *pairh;
    float *h2;
    cudaGetSymbolAddress((void**)&xhi, g_xhi);   cudaGetSymbolAddress((void**)&xlo, g_xlo);
    cudaGetSymbolAddress((void**)&h1hi, g_h1hi); cudaGetSymbolAddress((void**)&h1lo, g_h1lo);
    cudaGetSymbolAddress((void**)&w1hi, g_w1hi); cudaGetSymbolAddress((void**)&w1lo, g_w1lo);
    cudaGetSymbolAddress((void**)&w2hi, g_w2hi); cudaGetSymbolAddress((void**)&w2lo, g_w2lo);
    cudaGetSymbolAddress((void**)&xh, g_xh);
    cudaGetSymbolAddress((void**)&ewh, g_ewh);   cudaGetSymbolAddress((void**)&owh, g_owh);
    cudaGetSymbolAddress((void**)&mh, g_mh);     cudaGetSymbolAddress((void**)&pairh, g_pairh);
    cudaGetSymbolAddress((void**)&h2, g_h2);

    cudaFuncSetAttribute(mma_gemm<EPI_RELU_SPLIT>, cudaFuncAttributeMaxDynamicSharedMemorySize, SMEM_GEMM);
    cudaFuncSetAttribute(mma_gemm<EPI_RELU_F32>,   cudaFuncAttributeMaxDynamicSharedMemorySize, SMEM_GEMM);
    cudaFuncSetAttribute(h_gemm<HEPI_SCATTER, true>,  cudaFuncAttributeMaxDynamicSharedMemorySize, SMEM_HGEMM);
    cudaFuncSetAttribute(h_gemm<HEPI_F32,     false>, cudaFuncAttributeMaxDynamicSharedMemorySize, SMEM_HGEMM);

    // fused conversions + counter zeroing (single launch)
    prep_kernel<<<PREP_BLOCKS, 256>>>(x, gw1, gw2, ew, ow);

    // gating MLP (bf16 3-term, routing-grade precision)
    mma_gemm<EPI_RELU_SPLIT><<<dim3(GHA / 128, NT / 128), 512, SMEM_GEMM>>>(
        xhi, xlo, w1hi, w1lo, gb1, nullptr, h1hi, h1lo, GHA, DD);
    mma_gemm<EPI_RELU_F32><<<dim3(GHB / 128, NT / 128), 512, SMEM_GEMM>>>(
        h1hi, h1lo, w2hi, w2lo, gb2, h2, nullptr, nullptr, GHB, GHA);

    // routing
    gating_kernel<<<NT / 8, 256>>>(ft, gw3, gb3, temb, tw, tb);

    // expert grouped GEMM (fp16, gathered A, scattered fp16 C)
    h_gemm<HEPI_SCATTER, true><<<dim3(HH / 128, MAX_MTILES), 512, SMEM_HGEMM>>>(
        xh, ewh, eb, nullptr, pairh, HH, DD);

    // combine + relu -> fp16
    combine_kernel<<<(NT * HH / 2) / 256, 256>>>();

    // output projection (fp16)
    h_gemm<HEPI_F32, false><<<dim3(DD / 128, NT / 128), 512, SMEM_HGEMM>>>(
        mh, owh, ob, out, nullptr, DD, HH);
}

// round 10
// speedup vs baseline: 4.6450x; 1.0090x over previous
#include <cuda_runtime.h>
#include <cuda_bf16.h>
#include <cuda_fp16.h>
#include <cstdint>

#define NT   8192
#define DD   1024
#define GHA  512
#define GHB  256
#define NE   8
#define HH   2048
#define MAX_MTILES 136

typedef __nv_bfloat16 bf16;

// ---------------- scratch ---------------------------------------------------
__device__ bf16  g_xhi[NT * DD],  g_xlo[NT * DD];
__device__ bf16  g_h1hi[NT * GHA], g_h1lo[NT * GHA];
__device__ bf16  g_w1hi[GHA * DD], g_w1lo[GHA * DD];
__device__ bf16  g_w2hi[GHB * GHA], g_w2lo[GHB * GHA];
__device__ __half g_xh[NT * DD];
__device__ __half g_ewh[(size_t)NE * HH * DD];             // [E][H][D]
__device__ __half g_owh[(size_t)DD * HH];                  // [D][H]
__device__ __half g_mh[(size_t)NT * HH];
__device__ __half g_pairh[(size_t)NT * 2 * HH];
__device__ float g_logit[NT * NE];
__device__ float g_wval[NT * 2];
__device__ int   g_cnt[NE];
__device__ int   g_list[NE * NT];

// ---------------- PTX helpers (sm_80+ baseline only) ------------------------
__device__ __forceinline__ uint32_t smem_u32(const void* p) {
    uint32_t a;
    asm("{ .reg .u64 t; cvta.to.shared.u64 t, %1; cvt.u32.u64 %0, t; }" : "=r"(a) : "l"(p));
    return a;
}
__device__ __forceinline__ void cp16(uint32_t s, const void* g) {
    asm volatile("cp.async.cg.shared.global [%0], [%1], 16;" :: "r"(s), "l"(g));
}
#define CP_COMMIT() asm volatile("cp.async.commit_group;" ::: "memory")
#define CP_WAIT2()  asm volatile("cp.async.wait_group 2;" ::: "memory")

__device__ __forceinline__ void ldsm_x4(uint32_t* r, uint32_t a) {
    asm volatile("ldmatrix.sync.aligned.m8n8.x4.shared.b16 {%0,%1,%2,%3}, [%4];"
        : "=r"(r[0]), "=r"(r[1]), "=r"(r[2]), "=r"(r[3]) : "r"(a));
}
__device__ __forceinline__ void mma_bf16(float* c, const uint32_t* a, const uint32_t* b) {
    asm volatile("mma.sync.aligned.m16n8k16.row.col.f32.bf16.bf16.f32 "
        "{%0,%1,%2,%3}, {%4,%5,%6,%7}, {%8,%9}, {%0,%1,%2,%3};"
        : "+f"(c[0]), "+f"(c[1]), "+f"(c[2]), "+f"(c[3])
        : "r"(a[0]), "r"(a[1]), "r"(a[2]), "r"(a[3]), "r"(b[0]), "r"(b[1]));
}
__device__ __forceinline__ void mma_f16(float* c, const uint32_t* a, const uint32_t* b) {
    asm volatile("mma.sync.aligned.m16n8k16.row.col.f32.f16.f16.f32 "
        "{%0,%1,%2,%3}, {%4,%5,%6,%7}, {%8,%9}, {%0,%1,%2,%3};"
        : "+f"(c[0]), "+f"(c[1]), "+f"(c[2]), "+f"(c[3])
        : "r"(a[0]), "r"(a[1]), "r"(a[2]), "r"(a[3]), "r"(b[0]), "r"(b[1]));
}

// ---------------- fused prep kernel ------------------------------------------
#define PREP_BLOCKS 27264

__global__ void __launch_bounds__(256) prep_kernel(
    const float* __restrict__ x, const float* __restrict__ gw1,
    const float* __restrict__ gw2, const float* __restrict__ ew,
    const float* __restrict__ ow) {
    __shared__ float t[32][33];
    int b = blockIdx.x;
    const int tid = threadIdx.x;

    if (b < 8192) {
        if (b == 0 && tid < NE) g_cnt[tid] = 0;
        if (b < 64) {   // zero logits: 64 blocks x 256 thr x float4 = 256KB
            ((float4*)g_logit)[b * 256 + tid] = make_float4(0.f, 0.f, 0.f, 0.f);
        }
        int i4 = b * 256 + tid;
        float4 v = ((const float4*)x)[i4];
        float f[4] = {v.x, v.y, v.z, v.w};
        bf16 bh[4]; bf16 bl[4]; __half hh[4];
        #pragma unroll
        for (int k = 0; k < 4; k++) {
            bh[k] = __float2bfloat16(f[k]);
            bl[k] = __float2bfloat16(f[k] - __bfloat162float(bh[k]));
            hh[k] = __float2half(f[k]);
        }
        __nv_bfloat162* xhi2 = (__nv_bfloat162*)g_xhi;
        __nv_bfloat162* xlo2 = (__nv_bfloat162*)g_xlo;
        __half2* xh2 = (__half2*)g_xh;
        xhi2[2 * i4 + 0] = __nv_bfloat162(bh[0], bh[1]);
        xhi2[2 * i4 + 1] = __nv_bfloat162(bh[2], bh[3]);
        xlo2[2 * i4 + 0] = __nv_bfloat162(bl[0], bl[1]);
        xlo2[2 * i4 + 1] = __nv_bfloat162(bl[2], bl[3]);
        xh2[2 * i4 + 0] = __half2(hh[0], hh[1]);
        xh2[2 * i4 + 1] = __half2(hh[2], hh[3]);
        return;
    }
    b -= 8192;

    const float* in;
    bf16 *ohi = nullptr, *olo = nullptr;
    __half* oh = nullptr;
    int R, C, bx, by;
    size_t zoff = 0;
    bool half_mode;
    if (b < 512) {
        half_mode = false; in = gw1; ohi = g_w1hi; olo = g_w1lo;
        R = DD; C = GHA; bx = b % 16; by = b / 16;
    } else if (b < 640) {
        b -= 512;
        half_mode = false; in = gw2; ohi = g_w2hi; olo = g_w2lo;
        R = GHA; C = GHB; bx = b % 8; by = b / 8;
    } else if (b < 640 + 16384) {
        b -= 640;
        half_mode = true; in = ew; oh = g_ewh;
        R = DD; C = HH; bx = b % 64; by = (b / 64) % 32;
        zoff = (size_t)(b / (64 * 32)) * R * C;
    } else {
        b -= 640 + 16384;
        half_mode = true; in = ow; oh = g_owh;
        R = HH; C = DD; bx = b % 32; by = b / 32;
    }
    in += zoff;
    const int c0 = bx * 32, r0 = by * 32;
    const int tx = tid & 31, ty = tid >> 5;
    for (int i = ty; i < 32; i += 8)
        t[i][tx] = in[(size_t)(r0 + i) * C + c0 + tx];
    __syncthreads();
    if (half_mode) {
        oh += zoff;
        for (int i = ty; i < 32; i += 8)
            oh[(size_t)(c0 + i) * R + r0 + tx] = __float2half(t[tx][i]);
    } else {
        for (int i = ty; i < 32; i += 8) {
            float v = t[tx][i];
            bf16 h = __float2bfloat16(v);
            size_t o = (size_t)(c0 + i) * R + r0 + tx;
            ohi[o] = h;
            olo[o] = __float2bfloat16(v - __bfloat162float(h));
        }
    }
}

// ---------------- routing: logits + type bias -> top2 -> routing -------------
__global__ void __launch_bounds__(256) routing_kernel(
    const int* __restrict__ ftypes,
    const float* __restrict__ gb3, const float* __restrict__ temb,
    const float* __restrict__ tw, const float* __restrict__ tb) {
    __shared__ float s_tb3[3][NE];
    const int tid = threadIdx.x;
    if (tid < 3 * NE) {
        int ty = tid / NE, e = tid % NE;
        float s = 0.f;
        for (int j = 0; j < 128; j++) s += temb[ty * 128 + j] * tw[j * NE + e];
        s_tb3[ty][e] = s + gb3[e] + tb[e];
    }
    __syncthreads();
    const int t = blockIdx.x * 256 + tid;
    float4 l0 = ((const float4*)g_logit)[t * 2 + 0];
    float4 l1 = ((const float4*)g_logit)[t * 2 + 1];
    float logits[NE] = {l0.x, l0.y, l0.z, l0.w, l1.x, l1.y, l1.z, l1.w};
    int ftv = ftypes[t];
    #pragma unroll
    for (int e = 0; e < NE; e++) logits[e] += s_tb3[ftv][e];
    int i0 = 0;
    #pragma unroll
    for (int e = 1; e < NE; e++) if (logits[e] > logits[i0]) i0 = e;
    int i1 = (i0 == 0) ? 1 : 0;
    #pragma unroll
    for (int e = 0; e < NE; e++) {
        if (e == i0 || e == i1) continue;
        if (logits[e] > logits[i1]) i1 = e;
    }
    float r = expf(logits[i1] - logits[i0]);
    float inv = 1.f / (1.f + r);
    g_wval[t * 2 + 0] = inv;
    g_wval[t * 2 + 1] = r * inv;
    int s0 = atomicAdd(&g_cnt[i0], 1); g_list[i0 * NT + s0] = t * 2 + 0;
    int s1 = atomicAdd(&g_cnt[i1], 1); g_list[i1 * NT + s1] = t * 2 + 1;
}

// ================= bf16 3-term GEMM (gating layers), K-chunk 32 ==============
#define EPI_RELU_SPLIT 0
#define EPI_GATE       1

#define ROWB      80
#define TILES_OFF 2048
#define STAGE_SZ  40960
#define NSTAGE    4
#define OA_HI 0
#define OA_LO 10240
#define OB_HI 20480
#define OB_LO 30720
#define GATE_OFF  (TILES_OFF + NSTAGE * STAGE_SZ)
#define SMEM_GEMM GATE_OFF                       // 165888
#define SMEM_GATE (GATE_OFF + GHB * NE * 4)      // +8KB gw3 cache

template<int MODE>
__global__ void __launch_bounds__(512, 1) mma_gemm(
    const bf16* __restrict__ Ahi, const bf16* __restrict__ Alo,
    const bf16* __restrict__ Bhi, const bf16* __restrict__ Blo,
    const float* __restrict__ bias, const float* __restrict__ gw3,
    bf16* __restrict__ outhi, bf16* __restrict__ outlo,
    int N, int K) {
    extern __shared__ char smem[];
    const int tid = threadIdx.x, lane = tid & 31, wid = tid >> 5;
    const int wm = wid >> 2, wn = wid & 3;
    const int nb = blockIdx.x;
    const int mtile = blockIdx.y;

    float* s_g3 = (float*)(smem + GATE_OFF);
    if (MODE == EPI_GATE) {
        for (int i = tid; i < GHB * NE; i += 512) s_g3[i] = gw3[i];
    }

    const uint32_t sb = smem_u32(smem) + TILES_OFF;

    const int seg = tid & 3;
    const int row = tid >> 2;
    size_t arow = (size_t)mtile * 128 + row;
    size_t brow = (size_t)nb * 128 + row;
    const bf16* pAh = Ahi + arow * K + seg * 8;
    const bf16* pAl = Alo + arow * K + seg * 8;
    const bf16* pBh = Bhi + brow * K + seg * 8;
    const bf16* pBl = Blo + brow * K + seg * 8;
    const uint32_t so = row * ROWB + seg * 16;

    float acc[2][4][4] = {};
    const int niter = K >> 5;

    #pragma unroll
    for (int s = 0; s < NSTAGE - 1; s++) {
        if (s < niter) {
            const uint32_t st = sb + s * STAGE_SZ;
            const int ko = s << 5;
            cp16(st + OA_HI + so, pAh + ko);
            cp16(st + OA_LO + so, pAl + ko);
            cp16(st + OB_HI + so, pBh + ko);
            cp16(st + OB_LO + so, pBl + ko);
        }
        CP_COMMIT();
    }

    for (int it = 0; it < niter; it++) {
        CP_WAIT2();
        __syncthreads();
        {
            const int s = it + NSTAGE - 1;
            if (s < niter) {
                const uint32_t st = sb + (s & (NSTAGE - 1)) * STAGE_SZ;
                const int ko = s << 5;
                cp16(st + OA_HI + so, pAh + ko);
                cp16(st + OA_LO + so, pAl + ko);
                cp16(st + OB_HI + so, pBh + ko);
                cp16(st + OB_LO + so, pBl + ko);
            }
            CP_COMMIT();
        }

        const uint32_t st = sb + (it & (NSTAGE - 1)) * STAGE_SZ;
        #pragma unroll
        for (int ks = 0; ks < 2; ks++) {
            uint32_t ah[2][4], al[2][4], bh[2][4], bl[2][4];
            const int acol = (ks * 16 + (lane >> 4) * 8) * 2;
            #pragma unroll
            for (int mt = 0; mt < 2; mt++) {
                uint32_t ad = st + (wm * 32 + mt * 16 + (lane & 15)) * ROWB + acol;
                ldsm_x4(ah[mt], ad + OA_HI);
                ldsm_x4(al[mt], ad + OA_LO);
            }
            const int bcol = (ks * 16 + ((lane >> 3) & 1) * 8) * 2;
            #pragma unroll
            for (int pr = 0; pr < 2; pr++) {
                uint32_t bd = st + (wn * 32 + pr * 16 + ((lane >> 4) << 3) + (lane & 7)) * ROWB + bcol;
                ldsm_x4(bh[pr], bd + OB_HI);
                ldsm_x4(bl[pr], bd + OB_LO);
            }
            #pragma unroll
            for (int mt = 0; mt < 2; mt++)
                #pragma unroll
                for (int nt = 0; nt < 4; nt++) {
                    const uint32_t* bhp = &bh[nt >> 1][(nt & 1) * 2];
                    const uint32_t* blp = &bl[nt >> 1][(nt & 1) * 2];
                    mma_bf16(acc[mt][nt], ah[mt], bhp);
                    mma_bf16(acc[mt][nt], ah[mt], blp);
                    mma_bf16(acc[mt][nt], al[mt], bhp);
                }
        }
    }

    if (MODE == EPI_RELU_SPLIT) {
        #pragma unroll
        for (int mt = 0; mt < 2; mt++) {
            #pragma unroll
            for (int half = 0; half < 2; half++) {
                const int mloc = wm * 32 + mt * 16 + half * 8 + (lane >> 2);
                #pragma unroll
                for (int nt = 0; nt < 4; nt++) {
                    const int c0 = nb * 128 + wn * 32 + nt * 8 + (lane & 3) * 2;
                    float v0 = fmaxf(acc[mt][nt][half * 2 + 0] + bias[c0], 0.f);
                    float v1 = fmaxf(acc[mt][nt][half * 2 + 1] + bias[c0 + 1], 0.f);
                    size_t base = (size_t)(mtile * 128 + mloc) * N + c0;
                    bf16 h0 = __float2bfloat16(v0), h1 = __float2bfloat16(v1);
                    outhi[base] = h0; outhi[base + 1] = h1;
                    outlo[base] = __float2bfloat16(v0 - __bfloat162float(h0));
                    outlo[base + 1] = __float2bfloat16(v1 - __bfloat162float(h1));
                }
            }
        }
    } else {
        // fused gating: p[r][e] = sum_cols relu(acc+gb2[col]) * gw3[col][e]
        float p[4][8] = {};
        #pragma unroll
        for (int mt = 0; mt < 2; mt++)
            #pragma unroll
            for (int half = 0; half < 2; half++) {
                const int r = mt * 2 + half;
                #pragma unroll
                for (int nt = 0; nt < 4; nt++)
                    #pragma unroll
                    for (int j = 0; j < 2; j++) {
                        const int cl = wn * 32 + nt * 8 + (lane & 3) * 2 + j;   // local col
                        const int c0 = nb * 128 + cl;                           // global col
                        float v = fmaxf(acc[mt][nt][half * 2 + j] + bias[c0], 0.f);
                        float4 ga = ((const float4*)(s_g3 + c0 * NE))[0];
                        float4 gb = ((const float4*)(s_g3 + c0 * NE))[1];
                        p[r][0] = fmaf(v, ga.x, p[r][0]);
                        p[r][1] = fmaf(v, ga.y, p[r][1]);
                        p[r][2] = fmaf(v, ga.z, p[r][2]);
                        p[r][3] = fmaf(v, ga.w, p[r][3]);
                        p[r][4] = fmaf(v, gb.x, p[r][4]);
                        p[r][5] = fmaf(v, gb.y, p[r][5]);
                        p[r][6] = fmaf(v, gb.z, p[r][6]);
                        p[r][7] = fmaf(v, gb.w, p[r][7]);
                    }
            }
        #pragma unroll
        for (int r = 0; r < 4; r++)
            #pragma unroll
            for (int e = 0; e < NE; e++) {
                p[r][e] += __shfl_xor_sync(0xffffffffu, p[r][e], 1);
                p[r][e] += __shfl_xor_sync(0xffffffffu, p[r][e], 2);
            }
        if ((lane & 3) == 0) {
            #pragma unroll
            for (int r = 0; r < 4; r++) {
                const int mloc = wm * 32 + (r >> 1) * 16 + (r & 1) * 8 + (lane >> 2);
                const int tok = mtile * 128 + mloc;
                #pragma unroll
                for (int e = 0; e < NE; e++)
                    atomicAdd(&g_logit[tok * NE + e], p[r][e]);
            }
        }
    }
}

// ================= plain fp16 GEMM (expert + outproj), K-chunk 64 ============
#define HEPI_SCATTER 0
#define HEPI_F32     1

#define HROWB     144
#define HSTAGE_SZ 36864
#define HOA 0
#define HOB 18432
#define SMEM_HGEMM (TILES_OFF + NSTAGE * HSTAGE_SZ)   // 149504

template<int MODE, bool GATHER>
__global__ void __launch_bounds__(512, 1) h_gemm(
    const __half* __restrict__ A,
    const __half* __restrict__ W,
    const float* __restrict__ bias,
    float* __restrict__ outf, __half* __restrict__ outh, int N, int K) {
    extern __shared__ char smem[];
    int* s_pid = (int*)smem;
    int* s_tok = (int*)(smem + 512);
    const int tid = threadIdx.x, lane = tid & 31, wid = tid >> 5;
    const int wm = wid >> 2, wn = wid & 3;
    const int nb = blockIdx.x;

    int mtile = blockIdx.y, e = 0;
    if (GATHER) {
        int flat = blockIdx.y, base = 0, cnt = 0;
        bool found = false;
        #pragma unroll
        for (int i = 0; i < NE; i++) {
            int c = g_cnt[i];
            int tiles = (c + 127) >> 7;
            if (!found && flat < base + tiles) { e = i; mtile = flat - base; cnt = c; found = true; }
            base += tiles;
        }
        if (!found) return;
        if (tid < 128) {
            int idx = mtile * 128 + tid;
            int pid = (idx < cnt) ? g_list[e * NT + idx] : -1;
            s_pid[tid] = pid;
            s_tok[tid] = (pid >= 0) ? (pid >> 1) : 0;
        }
        W += (size_t)e * HH * DD;
        bias += (size_t)e * HH;
        __syncthreads();
    }

    const uint32_t sb = smem_u32(smem) + TILES_OFF;

    const int seg = tid & 3;
    const int row = tid >> 2;
    size_t arow = GATHER ? (size_t)s_tok[row] : ((size_t)mtile * 128 + row);
    size_t brow = (size_t)nb * 128 + row;
    const __half* pA = A + arow * K + seg * 8;
    const __half* pB = W + brow * K + seg * 8;
    const uint32_t so = row * HROWB + seg * 16;

    float acc[2][4][4] = {};
    const int niter = K >> 6;

    #pragma unroll
    for (int s = 0; s < NSTAGE - 1; s++) {
        if (s < niter) {
            const uint32_t st = sb + s * HSTAGE_SZ;
            const int ko = s << 6;
            cp16(st + HOA + so,      pA + ko);
            cp16(st + HOA + so + 64, pA + ko + 32);
            cp16(st + HOB + so,      pB + ko);
            cp16(st + HOB + so + 64, pB + ko + 32);
        }
        CP_COMMIT();
    }

    for (int it = 0; it < niter; it++) {
        CP_WAIT2();
        __syncthreads();
        {
            const int s = it + NSTAGE - 1;
            if (s < niter) {
                const uint32_t st = sb + (s & (NSTAGE - 1)) * HSTAGE_SZ;
                const int ko = s << 6;
                cp16(st + HOA + so,      pA + ko);
                cp16(st + HOA + so + 64, pA + ko + 32);
                cp16(st + HOB + so,      pB + ko);
                cp16(st + HOB + so + 64, pB + ko + 32);
            }
            CP_COMMIT();
        }

        const uint32_t st = sb + (it & (NSTAGE - 1)) * HSTAGE_SZ;
        #pragma unroll
        for (int ks = 0; ks < 4; ks++) {
            uint32_t ah[2][4], bb[2][4];
            const int acol = (ks * 16 + (lane >> 4) * 8) * 2;
            #pragma unroll
            for (int mt = 0; mt < 2; mt++) {
                uint32_t ad = st + (wm * 32 + mt * 16 + (lane & 15)) * HROWB + acol;
                ldsm_x4(ah[mt], ad + HOA);
            }
            const int bcol = (ks * 16 + ((lane >> 3) & 1) * 8) * 2;
            #pragma unroll
            for (int pr = 0; pr < 2; pr++) {
                uint32_t bd = st + (wn * 32 + pr * 16 + ((lane >> 4) << 3) + (lane & 7)) * HROWB + bcol;
                ldsm_x4(bb[pr], bd + HOB);
            }
            #pragma unroll
            for (int mt = 0; mt < 2; mt++)
                #pragma unroll
                for (int nt = 0; nt < 4; nt++) {
                    const uint32_t* bp = &bb[nt >> 1][(nt & 1) * 2];
                    mma_f16(acc[mt][nt], ah[mt], bp);
                }
        }
    }

    #pragma unroll
    for (int mt = 0; mt < 2; mt++) {
        #pragma unroll
        for (int half = 0; half < 2; half++) {
            const int mloc = wm * 32 + mt * 16 + half * 8 + (lane >> 2);
            int pid = 0;
            if (GATHER) { pid = s_pid[mloc]; if (pid < 0) continue; }
            #pragma unroll
            for (int nt = 0; nt < 4; nt++) {
                const int c0 = nb * 128 + wn * 32 + nt * 8 + (lane & 3) * 2;
                float v0 = acc[mt][nt][half * 2 + 0] + bias[c0];
                float v1 = acc[mt][nt][half * 2 + 1] + bias[c0 + 1];
                if (MODE == HEPI_SCATTER) {
                    __half2* dst = (__half2*)(outh + (size_t)pid * HH + c0);
                    *dst = __floats2half2_rn(v0, v1);
                } else {
                    size_t base = (size_t)(mtile * 128 + mloc) * N + c0;
                    outf[base] = v0; outf[base + 1] = v1;
                }
            }
        }
    }
}

// ---------------- combine: moe = relu(w0*p0 + w1*p1) -> fp16 (half2) ---------
__global__ void combine_kernel() {
    int idx = blockIdx.x * blockDim.x + threadIdx.x;   // over NT*HH/2
    int t = idx >> 10;
    int c = idx & 1023;
    float w0 = g_wval[2 * t], w1 = g_wval[2 * t + 1];
    const __half2* p = (const __half2*)g_pairh;
    float2 a = __half22float2(p[(size_t)t * HH + c]);
    float2 b = __half22float2(p[(size_t)t * HH + (HH / 2) + c]);
    float v0 = fmaxf(fmaf(w0, a.x, w1 * b.x), 0.f);
    float v1 = fmaxf(fmaf(w0, a.y, w1 * b.y), 0.f);
    ((__half2*)g_mh)[idx] = __floats2half2_rn(v0, v1);
}

// ---------------- launch ------------------------------------------------------
extern "C" void kernel_launch(void* const* d_in, const int* in_sizes, int n_in,
                              void* d_out, int out_size) {
    const float* x    = (const float*)d_in[0];
    const int*   ft   = (const int*)  d_in[1];
    const float* gw1  = (const float*)d_in[2];
    const float* gb1  = (const float*)d_in[3];
    const float* gw2  = (const float*)d_in[4];
    const float* gb2  = (const float*)d_in[5];
    const float* gw3  = (const float*)d_in[6];
    const float* gb3  = (const float*)d_in[7];
    const float* temb = (const float*)d_in[8];
    const float* tw   = (const float*)d_in[9];
    const float* tb   = (const float*)d_in[10];
    const float* ew   = (const float*)d_in[11];
    const float* eb   = (const float*)d_in[12];
    const float* ow   = (const float*)d_in[13];
    const float* ob   = (const float*)d_in[14];
    float* out = (float*)d_out;

    bf16 *xhi, *xlo, *h1hi, *h1lo, *w1hi, *w1lo, *w2hi, *w2lo;
    __half *xh, *ewh, *owh, *mh, *pairh;
    cudaGetSymbolAddress((void**)&xhi, g_xhi);   cudaGetSymbolAddress((void**)&xlo, g_xlo);
    cudaGetSymbolAddress((void**)&h1hi, g_h1hi); cudaGetSymbolAddress((void**)&h1lo, g_h1lo);
    cudaGetSymbolAddress((void**)&w1hi, g_w1hi); cudaGetSymbolAddress((void**)&w1lo, g_w1lo);
    cudaGetSymbolAddress((void**)&w2hi, g_w2hi); cudaGetSymbolAddress((void**)&w2lo, g_w2lo);
    cudaGetSymbolAddress((void**)&xh, g_xh);
    cudaGetSymbolAddress((void**)&ewh, g_ewh);   cudaGetSymbolAddress((void**)&owh, g_owh);
    cudaGetSymbolAddress((void**)&mh, g_mh);     cudaGetSymbolAddress((void**)&pairh, g_pairh);

    cudaFuncSetAttribute(mma_gemm<EPI_RELU_SPLIT>, cudaFuncAttributeMaxDynamicSharedMemorySize, SMEM_GEMM);
    cudaFuncSetAttribute(mma_gemm<EPI_GATE>,       cudaFuncAttributeMaxDynamicSharedMemorySize, SMEM_GATE);
    cudaFuncSetAttribute(h_gemm<HEPI_SCATTER, true>,  cudaFuncAttributeMaxDynamicSharedMemorySize, SMEM_HGEMM);
    cudaFuncSetAttribute(h_gemm<HEPI_F32,     false>, cudaFuncAttributeMaxDynamicSharedMemorySize, SMEM_HGEMM);

    // fused conversions + counter/logit zeroing
    prep_kernel<<<PREP_BLOCKS, 256>>>(x, gw1, gw2, ew, ow);

    // gating layer 1 (bf16 3-term) -> h1 split
    mma_gemm<EPI_RELU_SPLIT><<<dim3(GHA / 128, NT / 128), 512, SMEM_GEMM>>>(
        xhi, xlo, w1hi, w1lo, gb1, nullptr, h1hi, h1lo, GHA, DD);

    // gating layer 2 (bf16 3-term) + fused logit projection -> g_logit
    mma_gemm<EPI_GATE><<<dim3(GHB / 128, NT / 128), 512, SMEM_GATE>>>(
        h1hi, h1lo, w2hi, w2lo, gb2, gw3, nullptr, nullptr, GHB, GHA);

    // routing: type bias + top2 + lists
    routing_kernel<<<NT / 256, 256>>>(ft, gb3, temb, tw, tb);

    // expert grouped GEMM (fp16, gathered A, scattered fp16 C)
    h_gemm<HEPI_SCATTER, true><<<dim3(HH / 128, MAX_MTILES), 512, SMEM_HGEMM>>>(
        xh, ewh, eb, nullptr, pairh, HH, DD);

    // combine + relu -> fp16
    combine_kernel<<<(NT * HH / 2) / 256, 256>>>();

    // output projection (fp16)
    h_gemm<HEPI_F32, false><<<dim3(DD / 128, NT / 128), 512, SMEM_HGEMM>>>(
        mh, owh, ob, out, nullptr, DD, HH);
}

// round 11
// speedup vs baseline: 5.1515x; 1.1091x over previous
#include <cuda_runtime.h>
#include <cuda_bf16.h>
#include <cuda_fp16.h>
#include <cstdint>

#define NT   8192
#define DD   1024
#define GHA  512
#define GHB  256
#define NE   8
#define HH   2048
#define MAX_MTILES 136

typedef __nv_bfloat16 bf16;

// ---------------- scratch ---------------------------------------------------
__device__ bf16  g_xhi[NT * DD],  g_xlo[NT * DD];
__device__ bf16  g_h1hi[NT * GHA], g_h1lo[NT * GHA];
__device__ bf16  g_w1hi[GHA * DD], g_w1lo[GHA * DD];
__device__ bf16  g_w2hi[GHB * GHA], g_w2lo[GHB * GHA];
__device__ __half g_xh[NT * DD];
__device__ __half g_ewh[(size_t)NE * HH * DD];             // [E][H][D]
__device__ __half g_owh[(size_t)DD * HH];                  // [D][H]
__device__ __half g_mh[(size_t)NT * HH];
__device__ __half g_pairh[(size_t)NT * 2 * HH];
__device__ float g_logit[NT * NE];
__device__ float g_tb3[3 * NE];
__device__ float g_wval[NT * 2];
__device__ int   g_cnt[NE];
__device__ int   g_list[NE * NT];

// ---------------- PTX helpers (sm_80+ baseline only) ------------------------
__device__ __forceinline__ uint32_t smem_u32(const void* p) {
    uint32_t a;
    asm("{ .reg .u64 t; cvta.to.shared.u64 t, %1; cvt.u32.u64 %0, t; }" : "=r"(a) : "l"(p));
    return a;
}
__device__ __forceinline__ void cp16(uint32_t s, const void* g) {
    asm volatile("cp.async.cg.shared.global [%0], [%1], 16;" :: "r"(s), "l"(g));
}
#define CP_COMMIT() asm volatile("cp.async.commit_group;" ::: "memory")
#define CP_WAIT2()  asm volatile("cp.async.wait_group 2;" ::: "memory")
#define CP_WAIT0()  asm volatile("cp.async.wait_group 0;" ::: "memory")

__device__ __forceinline__ void ldsm_x4(uint32_t* r, uint32_t a) {
    asm volatile("ldmatrix.sync.aligned.m8n8.x4.shared.b16 {%0,%1,%2,%3}, [%4];"
        : "=r"(r[0]), "=r"(r[1]), "=r"(r[2]), "=r"(r[3]) : "r"(a));
}
__device__ __forceinline__ void mma_bf16(float* c, const uint32_t* a, const uint32_t* b) {
    asm volatile("mma.sync.aligned.m16n8k16.row.col.f32.bf16.bf16.f32 "
        "{%0,%1,%2,%3}, {%4,%5,%6,%7}, {%8,%9}, {%0,%1,%2,%3};"
        : "+f"(c[0]), "+f"(c[1]), "+f"(c[2]), "+f"(c[3])
        : "r"(a[0]), "r"(a[1]), "r"(a[2]), "r"(a[3]), "r"(b[0]), "r"(b[1]));
}
__device__ __forceinline__ void mma_f16(float* c, const uint32_t* a, const uint32_t* b) {
    asm volatile("mma.sync.aligned.m16n8k16.row.col.f32.f16.f16.f32 "
        "{%0,%1,%2,%3}, {%4,%5,%6,%7}, {%8,%9}, {%0,%1,%2,%3};"
        : "+f"(c[0]), "+f"(c[1]), "+f"(c[2]), "+f"(c[3])
        : "r"(a[0]), "r"(a[1]), "r"(a[2]), "r"(a[3]), "r"(b[0]), "r"(b[1]));
}

// ---------------- fused prep kernel ------------------------------------------
#define PREP_BLOCKS 27265   // last block computes the type-bias table

__global__ void __launch_bounds__(256) prep_kernel(
    const float* __restrict__ x, const float* __restrict__ gw1,
    const float* __restrict__ gw2, const float* __restrict__ ew,
    const float* __restrict__ ow,
    const float* __restrict__ gb3, const float* __restrict__ temb,
    const float* __restrict__ tw, const float* __restrict__ tb) {
    __shared__ float t[32][33];
    int b = blockIdx.x;
    const int tid = threadIdx.x;

    if (b == PREP_BLOCKS - 1) {
        // tb3[ty][e] = sum_j temb[ty][j]*tw[j][e] + gb3[e] + tb[e]
        if (tid < 192) {
            const int p = tid >> 3;           // pair 0..23
            const int s = tid & 7;
            const int ty = p / NE, e = p % NE;
            float sum = 0.f;
            #pragma unroll
            for (int k = 0; k < 16; k++) {
                int j = s + (k << 3);
                sum += temb[ty * 128 + j] * tw[j * NE + e];
            }
            #pragma unroll
            for (int off = 4; off; off >>= 1)
                sum += __shfl_down_sync(0xffffffffu, sum, off);
            if (s == 0) g_tb3[p] = sum + gb3[e] + tb[e];
        }
        return;
    }

    if (b < 8192) {
        if (b == 0 && tid < NE) g_cnt[tid] = 0;
        if (b < 64) {
            ((float4*)g_logit)[b * 256 + tid] = make_float4(0.f, 0.f, 0.f, 0.f);
        }
        int i4 = b * 256 + tid;
        float4 v = ((const float4*)x)[i4];
        float f[4] = {v.x, v.y, v.z, v.w};
        bf16 bh[4]; bf16 bl[4]; __half hh[4];
        #pragma unroll
        for (int k = 0; k < 4; k++) {
            bh[k] = __float2bfloat16(f[k]);
            bl[k] = __float2bfloat16(f[k] - __bfloat162float(bh[k]));
            hh[k] = __float2half(f[k]);
        }
        __nv_bfloat162* xhi2 = (__nv_bfloat162*)g_xhi;
        __nv_bfloat162* xlo2 = (__nv_bfloat162*)g_xlo;
        __half2* xh2 = (__half2*)g_xh;
        xhi2[2 * i4 + 0] = __nv_bfloat162(bh[0], bh[1]);
        xhi2[2 * i4 + 1] = __nv_bfloat162(bh[2], bh[3]);
        xlo2[2 * i4 + 0] = __nv_bfloat162(bl[0], bl[1]);
        xlo2[2 * i4 + 1] = __nv_bfloat162(bl[2], bl[3]);
        xh2[2 * i4 + 0] = __half2(hh[0], hh[1]);
        xh2[2 * i4 + 1] = __half2(hh[2], hh[3]);
        return;
    }
    b -= 8192;

    const float* in;
    bf16 *ohi = nullptr, *olo = nullptr;
    __half* oh = nullptr;
    int R, C, bx, by;
    size_t zoff = 0;
    bool half_mode;
    if (b < 512) {
        half_mode = false; in = gw1; ohi = g_w1hi; olo = g_w1lo;
        R = DD; C = GHA; bx = b % 16; by = b / 16;
    } else if (b < 640) {
        b -= 512;
        half_mode = false; in = gw2; ohi = g_w2hi; olo = g_w2lo;
        R = GHA; C = GHB; bx = b % 8; by = b / 8;
    } else if (b < 640 + 16384) {
        b -= 640;
        half_mode = true; in = ew; oh = g_ewh;
        R = DD; C = HH; bx = b % 64; by = (b / 64) % 32;
        zoff = (size_t)(b / (64 * 32)) * R * C;
    } else {
        b -= 640 + 16384;
        half_mode = true; in = ow; oh = g_owh;
        R = HH; C = DD; bx = b % 32; by = b / 32;
    }
    in += zoff;
    const int c0 = bx * 32, r0 = by * 32;
    const int tx = tid & 31, ty = tid >> 5;
    for (int i = ty; i < 32; i += 8)
        t[i][tx] = in[(size_t)(r0 + i) * C + c0 + tx];
    __syncthreads();
    if (half_mode) {
        oh += zoff;
        for (int i = ty; i < 32; i += 8)
            oh[(size_t)(c0 + i) * R + r0 + tx] = __float2half(t[tx][i]);
    } else {
        for (int i = ty; i < 32; i += 8) {
            float v = t[tx][i];
            bf16 h = __float2bfloat16(v);
            size_t o = (size_t)(c0 + i) * R + r0 + tx;
            ohi[o] = h;
            olo[o] = __float2bfloat16(v - __bfloat162float(h));
        }
    }
}

// ---------------- routing: logits + tb3 -> top2 -> routing lists -------------
__global__ void __launch_bounds__(256) routing_kernel(const int* __restrict__ ftypes) {
    __shared__ float s_tb3[3 * NE];
    const int tid = threadIdx.x;
    if (tid < 3 * NE) s_tb3[tid] = g_tb3[tid];
    __syncthreads();
    const int t = blockIdx.x * 256 + tid;
    float4 l0 = ((const float4*)g_logit)[t * 2 + 0];
    float4 l1 = ((const float4*)g_logit)[t * 2 + 1];
    float logits[NE] = {l0.x, l0.y, l0.z, l0.w, l1.x, l1.y, l1.z, l1.w};
    int ftv = ftypes[t];
    #pragma unroll
    for (int e = 0; e < NE; e++) logits[e] += s_tb3[ftv * NE + e];
    int i0 = 0;
    #pragma unroll
    for (int e = 1; e < NE; e++) if (logits[e] > logits[i0]) i0 = e;
    int i1 = (i0 == 0) ? 1 : 0;
    #pragma unroll
    for (int e = 0; e < NE; e++) {
        if (e == i0 || e == i1) continue;
        if (logits[e] > logits[i1]) i1 = e;
    }
    float r = expf(logits[i1] - logits[i0]);
    float inv = 1.f / (1.f + r);
    g_wval[t * 2 + 0] = inv;
    g_wval[t * 2 + 1] = r * inv;
    int s0 = atomicAdd(&g_cnt[i0], 1); g_list[i0 * NT + s0] = t * 2 + 0;
    int s1 = atomicAdd(&g_cnt[i1], 1); g_list[i1 * NT + s1] = t * 2 + 1;
}

// ================= bf16 3-term GEMM (gating layers), K-chunk 32 ==============
#define EPI_RELU_SPLIT 0
#define EPI_GATE       1

#define ROWB      80
#define TILES_OFF 2048
#define STAGE_SZ  40960
#define NSTAGE    4
#define OA_HI 0
#define OA_LO 10240
#define OB_HI 20480
#define OB_LO 30720
#define GATE_OFF  (TILES_OFF + NSTAGE * STAGE_SZ)
#define SMEM_GEMM GATE_OFF
#define SMEM_GATE (GATE_OFF + GHB * NE * 4)

template<int MODE>
__global__ void __launch_bounds__(512, 1) mma_gemm(
    const bf16* __restrict__ Ahi, const bf16* __restrict__ Alo,
    const bf16* __restrict__ Bhi, const bf16* __restrict__ Blo,
    const float* __restrict__ bias, const float* __restrict__ gw3,
    bf16* __restrict__ outhi, bf16* __restrict__ outlo,
    int N, int K) {
    extern __shared__ char smem[];
    const int tid = threadIdx.x, lane = tid & 31, wid = tid >> 5;
    const int wm = wid >> 2, wn = wid & 3;
    const int nb = blockIdx.x;
    const int mtile = blockIdx.y;

    float* s_g3 = (float*)(smem + GATE_OFF);
    if (MODE == EPI_GATE) {
        for (int i = tid; i < GHB * NE; i += 512) s_g3[i] = gw3[i];
    }

    const uint32_t sb = smem_u32(smem) + TILES_OFF;

    const int seg = tid & 3;
    const int row = tid >> 2;
    size_t arow = (size_t)mtile * 128 + row;
    size_t brow = (size_t)nb * 128 + row;
    const bf16* pAh = Ahi + arow * K + seg * 8;
    const bf16* pAl = Alo + arow * K + seg * 8;
    const bf16* pBh = Bhi + brow * K + seg * 8;
    const bf16* pBl = Blo + brow * K + seg * 8;
    const uint32_t so = row * ROWB + seg * 16;

    float acc[2][4][4] = {};
    const int niter = K >> 5;

    #pragma unroll
    for (int s = 0; s < NSTAGE - 1; s++) {
        if (s < niter) {
            const uint32_t st = sb + s * STAGE_SZ;
            const int ko = s << 5;
            cp16(st + OA_HI + so, pAh + ko);
            cp16(st + OA_LO + so, pAl + ko);
            cp16(st + OB_HI + so, pBh + ko);
            cp16(st + OB_LO + so, pBl + ko);
        }
        CP_COMMIT();
    }

    for (int it = 0; it < niter; it++) {
        CP_WAIT2();
        __syncthreads();
        {
            const int s = it + NSTAGE - 1;
            if (s < niter) {
                const uint32_t st = sb + (s & (NSTAGE - 1)) * STAGE_SZ;
                const int ko = s << 5;
                cp16(st + OA_HI + so, pAh + ko);
                cp16(st + OA_LO + so, pAl + ko);
                cp16(st + OB_HI + so, pBh + ko);
                cp16(st + OB_LO + so, pBl + ko);
            }
            CP_COMMIT();
        }

        const uint32_t st = sb + (it & (NSTAGE - 1)) * STAGE_SZ;
        #pragma unroll
        for (int ks = 0; ks < 2; ks++) {
            uint32_t ah[2][4], al[2][4], bh[2][4], bl[2][4];
            const int acol = (ks * 16 + (lane >> 4) * 8) * 2;
            #pragma unroll
            for (int mt = 0; mt < 2; mt++) {
                uint32_t ad = st + (wm * 32 + mt * 16 + (lane & 15)) * ROWB + acol;
                ldsm_x4(ah[mt], ad + OA_HI);
                ldsm_x4(al[mt], ad + OA_LO);
            }
            const int bcol = (ks * 16 + ((lane >> 3) & 1) * 8) * 2;
            #pragma unroll
            for (int pr = 0; pr < 2; pr++) {
                uint32_t bd = st + (wn * 32 + pr * 16 + ((lane >> 4) << 3) + (lane & 7)) * ROWB + bcol;
                ldsm_x4(bh[pr], bd + OB_HI);
                ldsm_x4(bl[pr], bd + OB_LO);
            }
            #pragma unroll
            for (int mt = 0; mt < 2; mt++)
                #pragma unroll
                for (int nt = 0; nt < 4; nt++) {
                    const uint32_t* bhp = &bh[nt >> 1][(nt & 1) * 2];
                    const uint32_t* blp = &bl[nt >> 1][(nt & 1) * 2];
                    mma_bf16(acc[mt][nt], ah[mt], bhp);
                    mma_bf16(acc[mt][nt], ah[mt], blp);
                    mma_bf16(acc[mt][nt], al[mt], bhp);
                }
        }
    }

    if (MODE == EPI_RELU_SPLIT) {
        #pragma unroll
        for (int mt = 0; mt < 2; mt++) {
            #pragma unroll
            for (int half = 0; half < 2; half++) {
                const int mloc = wm * 32 + mt * 16 + half * 8 + (lane >> 2);
                #pragma unroll
                for (int nt = 0; nt < 4; nt++) {
                    const int c0 = nb * 128 + wn * 32 + nt * 8 + (lane & 3) * 2;
                    float v0 = fmaxf(acc[mt][nt][half * 2 + 0] + bias[c0], 0.f);
                    float v1 = fmaxf(acc[mt][nt][half * 2 + 1] + bias[c0 + 1], 0.f);
                    size_t base = (size_t)(mtile * 128 + mloc) * N + c0;
                    bf16 h0 = __float2bfloat16(v0), h1 = __float2bfloat16(v1);
                    outhi[base] = h0; outhi[base + 1] = h1;
                    outlo[base] = __float2bfloat16(v0 - __bfloat162float(h0));
                    outlo[base + 1] = __float2bfloat16(v1 - __bfloat162float(h1));
                }
            }
        }
    } else {
        float p[4][8] = {};
        #pragma unroll
        for (int mt = 0; mt < 2; mt++)
            #pragma unroll
            for (int half = 0; half < 2; half++) {
                const int r = mt * 2 + half;
                #pragma unroll
                for (int nt = 0; nt < 4; nt++)
                    #pragma unroll
                    for (int j = 0; j < 2; j++) {
                        const int cl = wn * 32 + nt * 8 + (lane & 3) * 2 + j;
                        const int c0 = nb * 128 + cl;
                        float v = fmaxf(acc[mt][nt][half * 2 + j] + bias[c0], 0.f);
                        float4 ga = ((const float4*)(s_g3 + c0 * NE))[0];
                        float4 gb = ((const float4*)(s_g3 + c0 * NE))[1];
                        p[r][0] = fmaf(v, ga.x, p[r][0]);
                        p[r][1] = fmaf(v, ga.y, p[r][1]);
                        p[r][2] = fmaf(v, ga.z, p[r][2]);
                        p[r][3] = fmaf(v, ga.w, p[r][3]);
                        p[r][4] = fmaf(v, gb.x, p[r][4]);
                        p[r][5] = fmaf(v, gb.y, p[r][5]);
                        p[r][6] = fmaf(v, gb.z, p[r][6]);
                        p[r][7] = fmaf(v, gb.w, p[r][7]);
                    }
            }
        #pragma unroll
        for (int r = 0; r < 4; r++)
            #pragma unroll
            for (int e = 0; e < NE; e++) {
                p[r][e] += __shfl_xor_sync(0xffffffffu, p[r][e], 1);
                p[r][e] += __shfl_xor_sync(0xffffffffu, p[r][e], 2);
            }
        if ((lane & 3) == 0) {
            #pragma unroll
            for (int r = 0; r < 4; r++) {
                const int mloc = wm * 32 + (r >> 1) * 16 + (r & 1) * 8 + (lane >> 2);
                const int tok = mtile * 128 + mloc;
                #pragma unroll
                for (int e = 0; e < NE; e++)
                    atomicAdd(&g_logit[tok * NE + e], p[r][e]);
            }
        }
    }
}

// ================= plain fp16 GEMM (expert + outproj) ========================
// K-chunk 64, double-buffered, OCCUPANCY 2 (smem 75.8KB, regs forced <=64)
#define HEPI_SCATTER 0
#define HEPI_F32     1

#define HROWB     144
#define HSTAGE_SZ 36864
#define HNSTAGE   2
#define HOA 0
#define HOB 18432
#define SMEM_HGEMM (TILES_OFF + HNSTAGE * HSTAGE_SZ)   // 75776

template<int MODE, bool GATHER>
__global__ void __launch_bounds__(512, 2) h_gemm(
    const __half* __restrict__ A,
    const __half* __restrict__ W,
    const float* __restrict__ bias,
    float* __restrict__ outf, __half* __restrict__ outh, int N, int K) {
    extern __shared__ char smem[];
    int* s_pid = (int*)smem;
    int* s_tok = (int*)(smem + 512);
    const int tid = threadIdx.x, lane = tid & 31, wid = tid >> 5;
    const int wm = wid >> 2, wn = wid & 3;
    const int nb = blockIdx.x;

    int mtile = blockIdx.y, e = 0;
    if (GATHER) {
        int flat = blockIdx.y, base = 0, cnt = 0;
        bool found = false;
        #pragma unroll
        for (int i = 0; i < NE; i++) {
            int c = g_cnt[i];
            int tiles = (c + 127) >> 7;
            if (!found && flat < base + tiles) { e = i; mtile = flat - base; cnt = c; found = true; }
            base += tiles;
        }
        if (!found) return;
        if (tid < 128) {
            int idx = mtile * 128 + tid;
            int pid = (idx < cnt) ? g_list[e * NT + idx] : -1;
            s_pid[tid] = pid;
            s_tok[tid] = (pid >= 0) ? (pid >> 1) : 0;
        }
        W += (size_t)e * HH * DD;
        bias += (size_t)e * HH;
        __syncthreads();
    }

    const uint32_t sb = smem_u32(smem) + TILES_OFF;

    const int seg = tid & 3;
    const int row = tid >> 2;
    size_t arow = GATHER ? (size_t)s_tok[row] : ((size_t)mtile * 128 + row);
    size_t brow = (size_t)nb * 128 + row;
    const __half* pA = A + arow * K + seg * 8;
    const __half* pB = W + brow * K + seg * 8;
    const uint32_t so = row * HROWB + seg * 16;

    float acc[2][4][4] = {};
    const int niter = K >> 6;

    // prologue: stage 0
    {
        cp16(sb + HOA + so,      pA);
        cp16(sb + HOA + so + 64, pA + 32);
        cp16(sb + HOB + so,      pB);
        cp16(sb + HOB + so + 64, pB + 32);
        CP_COMMIT();
    }

    for (int it = 0; it < niter; it++) {
        CP_WAIT0();
        __syncthreads();
        {
            const int s = it + 1;
            if (s < niter) {
                const uint32_t st = sb + (s & 1) * HSTAGE_SZ;
                const int ko = s << 6;
                cp16(st + HOA + so,      pA + ko);
                cp16(st + HOA + so + 64, pA + ko + 32);
                cp16(st + HOB + so,      pB + ko);
                cp16(st + HOB + so + 64, pB + ko + 32);
            }
            CP_COMMIT();
        }

        const uint32_t st = sb + (it & 1) * HSTAGE_SZ;
        #pragma unroll
        for (int ks = 0; ks < 4; ks++) {
            uint32_t ah[2][4], bb[2][4];
            const int acol = (ks * 16 + (lane >> 4) * 8) * 2;
            #pragma unroll
            for (int mt = 0; mt < 2; mt++) {
                uint32_t ad = st + (wm * 32 + mt * 16 + (lane & 15)) * HROWB + acol;
                ldsm_x4(ah[mt], ad + HOA);
            }
            const int bcol = (ks * 16 + ((lane >> 3) & 1) * 8) * 2;
            #pragma unroll
            for (int pr = 0; pr < 2; pr++) {
                uint32_t bd = st + (wn * 32 + pr * 16 + ((lane >> 4) << 3) + (lane & 7)) * HROWB + bcol;
                ldsm_x4(bb[pr], bd + HOB);
            }
            #pragma unroll
            for (int mt = 0; mt < 2; mt++)
                #pragma unroll
                for (int nt = 0; nt < 4; nt++) {
                    const uint32_t* bp = &bb[nt >> 1][(nt & 1) * 2];
                    mma_f16(acc[mt][nt], ah[mt], bp);
                }
        }
        __syncthreads();
    }

    #pragma unroll
    for (int mt = 0; mt < 2; mt++) {
        #pragma unroll
        for (int half = 0; half < 2; half++) {
            const int mloc = wm * 32 + mt * 16 + half * 8 + (lane >> 2);
            int pid = 0;
            if (GATHER) { pid = s_pid[mloc]; if (pid < 0) continue; }
            #pragma unroll
            for (int nt = 0; nt < 4; nt++) {
                const int c0 = nb * 128 + wn * 32 + nt * 8 + (lane & 3) * 2;
                float v0 = acc[mt][nt][half * 2 + 0] + bias[c0];
                float v1 = acc[mt][nt][half * 2 + 1] + bias[c0 + 1];
                if (MODE == HEPI_SCATTER) {
                    __half2* dst = (__half2*)(outh + (size_t)pid * HH + c0);
                    *dst = __floats2half2_rn(v0, v1);
                } else {
                    size_t base = (size_t)(mtile * 128 + mloc) * N + c0;
                    outf[base] = v0; outf[base + 1] = v1;
                }
            }
        }
    }
}

// ---------------- combine: moe = relu(w0*p0 + w1*p1) -> fp16 (half2) ---------
__global__ void combine_kernel() {
    int idx = blockIdx.x * blockDim.x + threadIdx.x;   // over NT*HH/2
    int t = idx >> 10;
    int c = idx & 1023;
    float w0 = g_wval[2 * t], w1 = g_wval[2 * t + 1];
    const __half2* p = (const __half2*)g_pairh;
    float2 a = __half22float2(p[(size_t)t * HH + c]);
    float2 b = __half22float2(p[(size_t)t * HH + (HH / 2) + c]);
    float v0 = fmaxf(fmaf(w0, a.x, w1 * b.x), 0.f);
    float v1 = fmaxf(fmaf(w0, a.y, w1 * b.y), 0.f);
    ((__half2*)g_mh)[idx] = __floats2half2_rn(v0, v1);
}

// ---------------- launch ------------------------------------------------------
extern "C" void kernel_launch(void* const* d_in, const int* in_sizes, int n_in,
                              void* d_out, int out_size) {
    const float* x    = (const float*)d_in[0];
    const int*   ft   = (const int*)  d_in[1];
    const float* gw1  = (const float*)d_in[2];
    const float* gb1  = (const float*)d_in[3];
    const float* gw2  = (const float*)d_in[4];
    const float* gb2  = (const float*)d_in[5];
    const float* gw3  = (const float*)d_in[6];
    const float* gb3  = (const float*)d_in[7];
    const float* temb = (const float*)d_in[8];
    const float* tw   = (const float*)d_in[9];
    const float* tb   = (const float*)d_in[10];
    const float* ew   = (const float*)d_in[11];
    const float* eb   = (const float*)d_in[12];
    const float* ow   = (const float*)d_in[13];
    const float* ob   = (const float*)d_in[14];
    float* out = (float*)d_out;

    bf16 *xhi, *xlo, *h1hi, *h1lo, *w1hi, *w1lo, *w2hi, *w2lo;
    __half *xh, *ewh, *owh, *mh, *pairh;
    cudaGetSymbolAddress((void**)&xhi, g_xhi);   cudaGetSymbolAddress((void**)&xlo, g_xlo);
    cudaGetSymbolAddress((void**)&h1hi, g_h1hi); cudaGetSymbolAddress((void**)&h1lo, g_h1lo);
    cudaGetSymbolAddress((void**)&w1hi, g_w1hi); cudaGetSymbolAddress((void**)&w1lo, g_w1lo);
    cudaGetSymbolAddress((void**)&w2hi, g_w2hi); cudaGetSymbolAddress((void**)&w2lo, g_w2lo);
    cudaGetSymbolAddress((void**)&xh, g_xh);
    cudaGetSymbolAddress((void**)&ewh, g_ewh);   cudaGetSymbolAddress((void**)&owh, g_owh);
    cudaGetSymbolAddress((void**)&mh, g_mh);     cudaGetSymbolAddress((void**)&pairh, g_pairh);

    cudaFuncSetAttribute(mma_gemm<EPI_RELU_SPLIT>, cudaFuncAttributeMaxDynamicSharedMemorySize, SMEM_GEMM);
    cudaFuncSetAttribute(mma_gemm<EPI_GATE>,       cudaFuncAttributeMaxDynamicSharedMemorySize, SMEM_GATE);
    cudaFuncSetAttribute(h_gemm<HEPI_SCATTER, true>,  cudaFuncAttributeMaxDynamicSharedMemorySize, SMEM_HGEMM);
    cudaFuncSetAttribute(h_gemm<HEPI_F32,     false>, cudaFuncAttributeMaxDynamicSharedMemorySize, SMEM_HGEMM);

    // fused conversions + counter/logit zeroing + tb3 table
    prep_kernel<<<PREP_BLOCKS, 256>>>(x, gw1, gw2, ew, ow, gb3, temb, tw, tb);

    // gating layer 1 (bf16 3-term) -> h1 split
    mma_gemm<EPI_RELU_SPLIT><<<dim3(GHA / 128, NT / 128), 512, SMEM_GEMM>>>(
        xhi, xlo, w1hi, w1lo, gb1, nullptr, h1hi, h1lo, GHA, DD);

    // gating layer 2 (bf16 3-term) + fused logit projection -> g_logit
    mma_gemm<EPI_GATE><<<dim3(GHB / 128, NT / 128), 512, SMEM_GATE>>>(
        h1hi, h1lo, w2hi, w2lo, gb2, gw3, nullptr, nullptr, GHB, GHA);

    // routing: precomputed tb3 + top2 + lists
    routing_kernel<<<NT / 256, 256>>>(ft);

    // expert grouped GEMM (fp16, gathered A, scattered fp16 C)
    h_gemm<HEPI_SCATTER, true><<<dim3(HH / 128, MAX_MTILES), 512, SMEM_HGEMM>>>(
        xh, ewh, eb, nullptr, pairh, HH, DD);

    // combine + relu -> fp16
    combine_kernel<<<(NT * HH / 2) / 256, 256>>>();

    // output projection (fp16)
    h_gemm<HEPI_F32, false><<<dim3(DD / 128, NT / 128), 512, SMEM_HGEMM>>>(
        mh, owh, ob, out, nullptr, DD, HH);
}

// round 12
// speedup vs baseline: 5.2178x; 1.0129x over previous
#include <cuda_runtime.h>
#include <cuda_bf16.h>
#include <cuda_fp16.h>
#include <cstdint>

#define NT   8192
#define DD   1024
#define GHA  512
#define GHB  256
#define NE   8
#define HH   2048
#define MAX_MTILES 136

typedef __nv_bfloat16 bf16;

// ---------------- scratch ---------------------------------------------------
__device__ bf16  g_xhi[NT * DD],  g_xlo[NT * DD];
__device__ bf16  g_h1hi[NT * GHA], g_h1lo[NT * GHA];
__device__ bf16  g_w1hi[GHA * DD], g_w1lo[GHA * DD];
__device__ bf16  g_w2hi[GHB * GHA], g_w2lo[GHB * GHA];
__device__ __half g_xh[NT * DD];
__device__ __half g_ewh[(size_t)NE * HH * DD];             // [E][H][D]
__device__ __half g_owh[(size_t)DD * HH];                  // [D][H]
__device__ __half g_mh[(size_t)NT * HH];
__device__ __half g_pairh[(size_t)NT * 2 * HH];
__device__ float g_logit[NT * NE];
__device__ float g_tb3[3 * NE];
__device__ float g_wval[NT * 2];
__device__ int   g_cnt[NE];
__device__ int   g_list[NE * NT];

// ---------------- PTX helpers (sm_80+ baseline only) ------------------------
__device__ __forceinline__ uint32_t smem_u32(const void* p) {
    uint32_t a;
    asm("{ .reg .u64 t; cvta.to.shared.u64 t, %1; cvt.u32.u64 %0, t; }" : "=r"(a) : "l"(p));
    return a;
}
__device__ __forceinline__ void cp16(uint32_t s, const void* g) {
    asm volatile("cp.async.cg.shared.global [%0], [%1], 16;" :: "r"(s), "l"(g));
}
#define CP_COMMIT() asm volatile("cp.async.commit_group;" ::: "memory")
#define CP_WAIT0()  asm volatile("cp.async.wait_group 0;" ::: "memory")

__device__ __forceinline__ void ldsm_x4(uint32_t* r, uint32_t a) {
    asm volatile("ldmatrix.sync.aligned.m8n8.x4.shared.b16 {%0,%1,%2,%3}, [%4];"
        : "=r"(r[0]), "=r"(r[1]), "=r"(r[2]), "=r"(r[3]) : "r"(a));
}
__device__ __forceinline__ void mma_bf16(float* c, const uint32_t* a, const uint32_t* b) {
    asm volatile("mma.sync.aligned.m16n8k16.row.col.f32.bf16.bf16.f32 "
        "{%0,%1,%2,%3}, {%4,%5,%6,%7}, {%8,%9}, {%0,%1,%2,%3};"
        : "+f"(c[0]), "+f"(c[1]), "+f"(c[2]), "+f"(c[3])
        : "r"(a[0]), "r"(a[1]), "r"(a[2]), "r"(a[3]), "r"(b[0]), "r"(b[1]));
}
__device__ __forceinline__ void mma_f16(float* c, const uint32_t* a, const uint32_t* b) {
    asm volatile("mma.sync.aligned.m16n8k16.row.col.f32.f16.f16.f32 "
        "{%0,%1,%2,%3}, {%4,%5,%6,%7}, {%8,%9}, {%0,%1,%2,%3};"
        : "+f"(c[0]), "+f"(c[1]), "+f"(c[2]), "+f"(c[3])
        : "r"(a[0]), "r"(a[1]), "r"(a[2]), "r"(a[3]), "r"(b[0]), "r"(b[1]));
}

// ---------------- fused prep kernel ------------------------------------------
#define PREP_BLOCKS 27265

__global__ void __launch_bounds__(256) prep_kernel(
    const float* __restrict__ x, const float* __restrict__ gw1,
    const float* __restrict__ gw2, const float* __restrict__ ew,
    const float* __restrict__ ow,
    const float* __restrict__ gb3, const float* __restrict__ temb,
    const float* __restrict__ tw, const float* __restrict__ tb) {
    __shared__ float t[32][33];
    int b = blockIdx.x;
    const int tid = threadIdx.x;

    if (b == PREP_BLOCKS - 1) {
        if (tid < 192) {
            const int p = tid >> 3;
            const int s = tid & 7;
            const int ty = p / NE, e = p % NE;
            float sum = 0.f;
            #pragma unroll
            for (int k = 0; k < 16; k++) {
                int j = s + (k << 3);
                sum += temb[ty * 128 + j] * tw[j * NE + e];
            }
            #pragma unroll
            for (int off = 4; off; off >>= 1)
                sum += __shfl_down_sync(0xffffffffu, sum, off);
            if (s == 0) g_tb3[p] = sum + gb3[e] + tb[e];
        }
        return;
    }

    if (b < 8192) {
        if (b == 0 && tid < NE) g_cnt[tid] = 0;
        if (b < 64) {
            ((float4*)g_logit)[b * 256 + tid] = make_float4(0.f, 0.f, 0.f, 0.f);
        }
        int i4 = b * 256 + tid;
        float4 v = ((const float4*)x)[i4];
        float f[4] = {v.x, v.y, v.z, v.w};
        bf16 bh[4]; bf16 bl[4]; __half hh[4];
        #pragma unroll
        for (int k = 0; k < 4; k++) {
            bh[k] = __float2bfloat16(f[k]);
            bl[k] = __float2bfloat16(f[k] - __bfloat162float(bh[k]));
            hh[k] = __float2half(f[k]);
        }
        __nv_bfloat162* xhi2 = (__nv_bfloat162*)g_xhi;
        __nv_bfloat162* xlo2 = (__nv_bfloat162*)g_xlo;
        __half2* xh2 = (__half2*)g_xh;
        xhi2[2 * i4 + 0] = __nv_bfloat162(bh[0], bh[1]);
        xhi2[2 * i4 + 1] = __nv_bfloat162(bh[2], bh[3]);
        xlo2[2 * i4 + 0] = __nv_bfloat162(bl[0], bl[1]);
        xlo2[2 * i4 + 1] = __nv_bfloat162(bl[2], bl[3]);
        xh2[2 * i4 + 0] = __half2(hh[0], hh[1]);
        xh2[2 * i4 + 1] = __half2(hh[2], hh[3]);
        return;
    }
    b -= 8192;

    const float* in;
    bf16 *ohi = nullptr, *olo = nullptr;
    __half* oh = nullptr;
    int R, C, bx, by;
    size_t zoff = 0;
    bool half_mode;
    if (b < 512) {
        half_mode = false; in = gw1; ohi = g_w1hi; olo = g_w1lo;
        R = DD; C = GHA; bx = b % 16; by = b / 16;
    } else if (b < 640) {
        b -= 512;
        half_mode = false; in = gw2; ohi = g_w2hi; olo = g_w2lo;
        R = GHA; C = GHB; bx = b % 8; by = b / 8;
    } else if (b < 640 + 16384) {
        b -= 640;
        half_mode = true; in = ew; oh = g_ewh;
        R = DD; C = HH; bx = b % 64; by = (b / 64) % 32;
        zoff = (size_t)(b / (64 * 32)) * R * C;
    } else {
        b -= 640 + 16384;
        half_mode = true; in = ow; oh = g_owh;
        R = HH; C = DD; bx = b % 32; by = b / 32;
    }
    in += zoff;
    const int c0 = bx * 32, r0 = by * 32;
    const int tx = tid & 31, ty = tid >> 5;
    for (int i = ty; i < 32; i += 8)
        t[i][tx] = in[(size_t)(r0 + i) * C + c0 + tx];
    __syncthreads();
    if (half_mode) {
        oh += zoff;
        for (int i = ty; i < 32; i += 8)
            oh[(size_t)(c0 + i) * R + r0 + tx] = __float2half(t[tx][i]);
    } else {
        for (int i = ty; i < 32; i += 8) {
            float v = t[tx][i];
            bf16 h = __float2bfloat16(v);
            size_t o = (size_t)(c0 + i) * R + r0 + tx;
            ohi[o] = h;
            olo[o] = __float2bfloat16(v - __bfloat162float(h));
        }
    }
}

// ---------------- routing: two-level atomics ---------------------------------
__global__ void __launch_bounds__(256) routing_kernel(const int* __restrict__ ftypes) {
    __shared__ float s_tb3[3 * NE];
    __shared__ int s_cnt[NE];
    __shared__ int s_base[NE];
    const int tid = threadIdx.x;
    if (tid < 3 * NE) s_tb3[tid] = g_tb3[tid];
    if (tid < NE) s_cnt[tid] = 0;
    __syncthreads();
    const int t = blockIdx.x * 256 + tid;
    float4 l0 = ((const float4*)g_logit)[t * 2 + 0];
    float4 l1 = ((const float4*)g_logit)[t * 2 + 1];
    float logits[NE] = {l0.x, l0.y, l0.z, l0.w, l1.x, l1.y, l1.z, l1.w};
    int ftv = ftypes[t];
    #pragma unroll
    for (int e = 0; e < NE; e++) logits[e] += s_tb3[ftv * NE + e];
    int i0 = 0;
    #pragma unroll
    for (int e = 1; e < NE; e++) if (logits[e] > logits[i0]) i0 = e;
    int i1 = (i0 == 0) ? 1 : 0;
    #pragma unroll
    for (int e = 0; e < NE; e++) {
        if (e == i0 || e == i1) continue;
        if (logits[e] > logits[i1]) i1 = e;
    }
    float r = expf(logits[i1] - logits[i0]);
    float inv = 1.f / (1.f + r);
    g_wval[t * 2 + 0] = inv;
    g_wval[t * 2 + 1] = r * inv;
    int p0 = atomicAdd(&s_cnt[i0], 1);
    int p1 = atomicAdd(&s_cnt[i1], 1);
    __syncthreads();
    if (tid < NE) s_base[tid] = atomicAdd(&g_cnt[tid], s_cnt[tid]);
    __syncthreads();
    g_list[i0 * NT + s_base[i0] + p0] = t * 2 + 0;
    g_list[i1 * NT + s_base[i1] + p1] = t * 2 + 1;
}

// ================= bf16 3-term GEMM (gating), 2-stage, occ 2 =================
#define EPI_RELU_SPLIT 0
#define EPI_GATE       1

#define ROWB      80
#define TILES_OFF 2048
#define STAGE_SZ  40960
#define NSTAGE    2
#define OA_HI 0
#define OA_LO 10240
#define OB_HI 20480
#define OB_LO 30720
#define GATE_OFF  (TILES_OFF + NSTAGE * STAGE_SZ)
#define SMEM_GEMM GATE_OFF                       // 83968
#define SMEM_GATE (GATE_OFF + GHB * NE * 4)      // 92160

template<int MODE>
__global__ void __launch_bounds__(512, 2) mma_gemm(
    const bf16* __restrict__ Ahi, const bf16* __restrict__ Alo,
    const bf16* __restrict__ Bhi, const bf16* __restrict__ Blo,
    const float* __restrict__ bias, const float* __restrict__ gw3,
    bf16* __restrict__ outhi, bf16* __restrict__ outlo,
    int N, int K) {
    extern __shared__ char smem[];
    const int tid = threadIdx.x, lane = tid & 31, wid = tid >> 5;
    const int wm = wid >> 2, wn = wid & 3;
    const int nb = blockIdx.x;
    const int mtile = blockIdx.y;

    float* s_g3 = (float*)(smem + GATE_OFF);
    if (MODE == EPI_GATE) {
        for (int i = tid; i < GHB * NE; i += 512) s_g3[i] = gw3[i];
    }

    const uint32_t sb = smem_u32(smem) + TILES_OFF;

    const int seg = tid & 3;
    const int row = tid >> 2;
    size_t arow = (size_t)mtile * 128 + row;
    size_t brow = (size_t)nb * 128 + row;
    const bf16* pAh = Ahi + arow * K + seg * 8;
    const bf16* pAl = Alo + arow * K + seg * 8;
    const bf16* pBh = Bhi + brow * K + seg * 8;
    const bf16* pBl = Blo + brow * K + seg * 8;
    const uint32_t so = row * ROWB + seg * 16;

    float acc[2][4][4] = {};
    const int niter = K >> 5;

    // prologue: stage 0
    {
        cp16(sb + OA_HI + so, pAh);
        cp16(sb + OA_LO + so, pAl);
        cp16(sb + OB_HI + so, pBh);
        cp16(sb + OB_LO + so, pBl);
        CP_COMMIT();
    }

    for (int it = 0; it < niter; it++) {
        CP_WAIT0();
        __syncthreads();
        {
            const int s = it + 1;
            if (s < niter) {
                const uint32_t st = sb + (s & 1) * STAGE_SZ;
                const int ko = s << 5;
                cp16(st + OA_HI + so, pAh + ko);
                cp16(st + OA_LO + so, pAl + ko);
                cp16(st + OB_HI + so, pBh + ko);
                cp16(st + OB_LO + so, pBl + ko);
            }
            CP_COMMIT();
        }

        const uint32_t st = sb + (it & 1) * STAGE_SZ;
        #pragma unroll
        for (int ks = 0; ks < 2; ks++) {
            uint32_t ah[2][4], al[2][4], bx[2][4];
            const int acol = (ks * 16 + (lane >> 4) * 8) * 2;
            #pragma unroll
            for (int mt = 0; mt < 2; mt++) {
                uint32_t ad = st + (wm * 32 + mt * 16 + (lane & 15)) * ROWB + acol;
                ldsm_x4(ah[mt], ad + OA_HI);
                ldsm_x4(al[mt], ad + OA_LO);
            }
            const int bcol = (ks * 16 + ((lane >> 3) & 1) * 8) * 2;
            // B_hi pass: ah*bh + al*bh
            #pragma unroll
            for (int pr = 0; pr < 2; pr++) {
                uint32_t bd = st + (wn * 32 + pr * 16 + ((lane >> 4) << 3) + (lane & 7)) * ROWB + bcol;
                ldsm_x4(bx[pr], bd + OB_HI);
            }
            #pragma unroll
            for (int mt = 0; mt < 2; mt++)
                #pragma unroll
                for (int nt = 0; nt < 4; nt++) {
                    const uint32_t* bp = &bx[nt >> 1][(nt & 1) * 2];
                    mma_bf16(acc[mt][nt], ah[mt], bp);
                    mma_bf16(acc[mt][nt], al[mt], bp);
                }
            // B_lo pass: ah*bl (reuse bx registers)
            #pragma unroll
            for (int pr = 0; pr < 2; pr++) {
                uint32_t bd = st + (wn * 32 + pr * 16 + ((lane >> 4) << 3) + (lane & 7)) * ROWB + bcol;
                ldsm_x4(bx[pr], bd + OB_LO);
            }
            #pragma unroll
            for (int mt = 0; mt < 2; mt++)
                #pragma unroll
                for (int nt = 0; nt < 4; nt++) {
                    const uint32_t* bp = &bx[nt >> 1][(nt & 1) * 2];
                    mma_bf16(acc[mt][nt], ah[mt], bp);
                }
        }
        __syncthreads();
    }

    if (MODE == EPI_RELU_SPLIT) {
        #pragma unroll
        for (int mt = 0; mt < 2; mt++) {
            #pragma unroll
            for (int half = 0; half < 2; half++) {
                const int mloc = wm * 32 + mt * 16 + half * 8 + (lane >> 2);
                #pragma unroll
                for (int nt = 0; nt < 4; nt++) {
                    const int c0 = nb * 128 + wn * 32 + nt * 8 + (lane & 3) * 2;
                    float v0 = fmaxf(acc[mt][nt][half * 2 + 0] + bias[c0], 0.f);
                    float v1 = fmaxf(acc[mt][nt][half * 2 + 1] + bias[c0 + 1], 0.f);
                    size_t base = (size_t)(mtile * 128 + mloc) * N + c0;
                    bf16 h0 = __float2bfloat16(v0), h1 = __float2bfloat16(v1);
                    outhi[base] = h0; outhi[base + 1] = h1;
                    outlo[base] = __float2bfloat16(v0 - __bfloat162float(h0));
                    outlo[base + 1] = __float2bfloat16(v1 - __bfloat162float(h1));
                }
            }
        }
    } else {
        float p[4][8] = {};
        #pragma unroll
        for (int mt = 0; mt < 2; mt++)
            #pragma unroll
            for (int half = 0; half < 2; half++) {
                const int r = mt * 2 + half;
                #pragma unroll
                for (int nt = 0; nt < 4; nt++)
                    #pragma unroll
                    for (int j = 0; j < 2; j++) {
                        const int cl = wn * 32 + nt * 8 + (lane & 3) * 2 + j;
                        const int c0 = nb * 128 + cl;
                        float v = fmaxf(acc[mt][nt][half * 2 + j] + bias[c0], 0.f);
                        float4 ga = ((const float4*)(s_g3 + c0 * NE))[0];
                        float4 gb = ((const float4*)(s_g3 + c0 * NE))[1];
                        p[r][0] = fmaf(v, ga.x, p[r][0]);
                        p[r][1] = fmaf(v, ga.y, p[r][1]);
                        p[r][2] = fmaf(v, ga.z, p[r][2]);
                        p[r][3] = fmaf(v, ga.w, p[r][3]);
                        p[r][4] = fmaf(v, gb.x, p[r][4]);
                        p[r][5] = fmaf(v, gb.y, p[r][5]);
                        p[r][6] = fmaf(v, gb.z, p[r][6]);
                        p[r][7] = fmaf(v, gb.w, p[r][7]);
                    }
            }
        #pragma unroll
        for (int r = 0; r < 4; r++)
            #pragma unroll
            for (int e = 0; e < NE; e++) {
                p[r][e] += __shfl_xor_sync(0xffffffffu, p[r][e], 1);
                p[r][e] += __shfl_xor_sync(0xffffffffu, p[r][e], 2);
            }
        if ((lane & 3) == 0) {
            #pragma unroll
            for (int r = 0; r < 4; r++) {
                const int mloc = wm * 32 + (r >> 1) * 16 + (r & 1) * 8 + (lane >> 2);
                const int tok = mtile * 128 + mloc;
                #pragma unroll
                for (int e = 0; e < NE; e++)
                    atomicAdd(&g_logit[tok * NE + e], p[r][e]);
            }
        }
    }
}

// ================= plain fp16 GEMM (expert + outproj), occ 2 =================
#define HEPI_SCATTER 0
#define HEPI_F32     1

#define HROWB     144
#define HSTAGE_SZ 36864
#define HOA 0
#define HOB 18432
#define SMEM_HGEMM (TILES_OFF + 2 * HSTAGE_SZ)   // 75776

template<int MODE, bool GATHER>
__global__ void __launch_bounds__(512, 2) h_gemm(
    const __half* __restrict__ A,
    const __half* __restrict__ W,
    const float* __restrict__ bias,
    float* __restrict__ outf, __half* __restrict__ outh, int N, int K) {
    extern __shared__ char smem[];
    int* s_pid = (int*)smem;
    int* s_tok = (int*)(smem + 512);
    const int tid = threadIdx.x, lane = tid & 31, wid = tid >> 5;
    const int wm = wid >> 2, wn = wid & 3;
    const int nb = blockIdx.x;

    int mtile = blockIdx.y, e = 0;
    if (GATHER) {
        int flat = blockIdx.y, base = 0, cnt = 0;
        bool found = false;
        #pragma unroll
        for (int i = 0; i < NE; i++) {
            int c = g_cnt[i];
            int tiles = (c + 127) >> 7;
            if (!found && flat < base + tiles) { e = i; mtile = flat - base; cnt = c; found = true; }
            base += tiles;
        }
        if (!found) return;
        if (tid < 128) {
            int idx = mtile * 128 + tid;
            int pid = (idx < cnt) ? g_list[e * NT + idx] : -1;
            s_pid[tid] = pid;
            s_tok[tid] = (pid >= 0) ? (pid >> 1) : 0;
        }
        W += (size_t)e * HH * DD;
        bias += (size_t)e * HH;
        __syncthreads();
    }

    const uint32_t sb = smem_u32(smem) + TILES_OFF;

    const int seg = tid & 3;
    const int row = tid >> 2;
    size_t arow = GATHER ? (size_t)s_tok[row] : ((size_t)mtile * 128 + row);
    size_t brow = (size_t)nb * 128 + row;
    const __half* pA = A + arow * K + seg * 8;
    const __half* pB = W + brow * K + seg * 8;
    const uint32_t so = row * HROWB + seg * 16;

    float acc[2][4][4] = {};
    const int niter = K >> 6;

    {
        cp16(sb + HOA + so,      pA);
        cp16(sb + HOA + so + 64, pA + 32);
        cp16(sb + HOB + so,      pB);
        cp16(sb + HOB + so + 64, pB + 32);
        CP_COMMIT();
    }

    for (int it = 0; it < niter; it++) {
        CP_WAIT0();
        __syncthreads();
        {
            const int s = it + 1;
            if (s < niter) {
                const uint32_t st = sb + (s & 1) * HSTAGE_SZ;
                const int ko = s << 6;
                cp16(st + HOA + so,      pA + ko);
                cp16(st + HOA + so + 64, pA + ko + 32);
                cp16(st + HOB + so,      pB + ko);
                cp16(st + HOB + so + 64, pB + ko + 32);
            }
            CP_COMMIT();
        }

        const uint32_t st = sb + (it & 1) * HSTAGE_SZ;
        #pragma unroll
        for (int ks = 0; ks < 4; ks++) {
            uint32_t ah[2][4], bb[2][4];
            const int acol = (ks * 16 + (lane >> 4) * 8) * 2;
            #pragma unroll
            for (int mt = 0; mt < 2; mt++) {
                uint32_t ad = st + (wm * 32 + mt * 16 + (lane & 15)) * HROWB + acol;
                ldsm_x4(ah[mt], ad + HOA);
            }
            const int bcol = (ks * 16 + ((lane >> 3) & 1) * 8) * 2;
            #pragma unroll
            for (int pr = 0; pr < 2; pr++) {
                uint32_t bd = st + (wn * 32 + pr * 16 + ((lane >> 4) << 3) + (lane & 7)) * HROWB + bcol;
                ldsm_x4(bb[pr], bd + HOB);
            }
            #pragma unroll
            for (int mt = 0; mt < 2; mt++)
                #pragma unroll
                for (int nt = 0; nt < 4; nt++) {
                    const uint32_t* bp = &bb[nt >> 1][(nt & 1) * 2];
                    mma_f16(acc[mt][nt], ah[mt], bp);
                }
        }
        __syncthreads();
    }

    #pragma unroll
    for (int mt = 0; mt < 2; mt++) {
        #pragma unroll
        for (int half = 0; half < 2; half++) {
            const int mloc = wm * 32 + mt * 16 + half * 8 + (lane >> 2);
            int pid = 0;
            if (GATHER) { pid = s_pid[mloc]; if (pid < 0) continue; }
            #pragma unroll
            for (int nt = 0; nt < 4; nt++) {
                const int c0 = nb * 128 + wn * 32 + nt * 8 + (lane & 3) * 2;
                float v0 = acc[mt][nt][half * 2 + 0] + bias[c0];
                float v1 = acc[mt][nt][half * 2 + 1] + bias[c0 + 1];
                if (MODE == HEPI_SCATTER) {
                    __half2* dst = (__half2*)(outh + (size_t)pid * HH + c0);
                    *dst = __floats2half2_rn(v0, v1);
                } else {
                    size_t base = (size_t)(mtile * 128 + mloc) * N + c0;
                    outf[base] = v0; outf[base + 1] = v1;
                }
            }
        }
    }
}

// ---------------- combine: moe = relu(w0*p0 + w1*p1) -> fp16 (half2) ---------
__global__ void combine_kernel() {
    int idx = blockIdx.x * blockDim.x + threadIdx.x;   // over NT*HH/2
    int t = idx >> 10;
    int c = idx & 1023;
    float w0 = g_wval[2 * t], w1 = g_wval[2 * t + 1];
    const __half2* p = (const __half2*)g_pairh;
    float2 a = __half22float2(p[(size_t)t * HH + c]);
    float2 b = __half22float2(p[(size_t)t * HH + (HH / 2) + c]);
    float v0 = fmaxf(fmaf(w0, a.x, w1 * b.x), 0.f);
    float v1 = fmaxf(fmaf(w0, a.y, w1 * b.y), 0.f);
    ((__half2*)g_mh)[idx] = __floats2half2_rn(v0, v1);
}

// ---------------- launch ------------------------------------------------------
extern "C" void kernel_launch(void* const* d_in, const int* in_sizes, int n_in,
                              void* d_out, int out_size) {
    const float* x    = (const float*)d_in[0];
    const int*   ft   = (const int*)  d_in[1];
    const float* gw1  = (const float*)d_in[2];
    const float* gb1  = (const float*)d_in[3];
    const float* gw2  = (const float*)d_in[4];
    const float* gb2  = (const float*)d_in[5];
    const float* gw3  = (const float*)d_in[6];
    const float* gb3  = (const float*)d_in[7];
    const float* temb = (const float*)d_in[8];
    const float* tw   = (const float*)d_in[9];
    const float* tb   = (const float*)d_in[10];
    const float* ew   = (const float*)d_in[11];
    const float* eb   = (const float*)d_in[12];
    const float* ow   = (const float*)d_in[13];
    const float* ob   = (const float*)d_in[14];
    float* out = (float*)d_out;

    bf16 *xhi, *xlo, *h1hi, *h1lo, *w1hi, *w1lo, *w2hi, *w2lo;
    __half *xh, *ewh, *owh, *mh, *pairh;
    cudaGetSymbolAddress((void**)&xhi, g_xhi);   cudaGetSymbolAddress((void**)&xlo, g_xlo);
    cudaGetSymbolAddress((void**)&h1hi, g_h1hi); cudaGetSymbolAddress((void**)&h1lo, g_h1lo);
    cudaGetSymbolAddress((void**)&w1hi, g_w1hi); cudaGetSymbolAddress((void**)&w1lo, g_w1lo);
    cudaGetSymbolAddress((void**)&w2hi, g_w2hi); cudaGetSymbolAddress((void**)&w2lo, g_w2lo);
    cudaGetSymbolAddress((void**)&xh, g_xh);
    cudaGetSymbolAddress((void**)&ewh, g_ewh);   cudaGetSymbolAddress((void**)&owh, g_owh);
    cudaGetSymbolAddress((void**)&mh, g_mh);     cudaGetSymbolAddress((void**)&pairh, g_pairh);

    cudaFuncSetAttribute(mma_gemm<EPI_RELU_SPLIT>, cudaFuncAttributeMaxDynamicSharedMemorySize, SMEM_GEMM);
    cudaFuncSetAttribute(mma_gemm<EPI_GATE>,       cudaFuncAttributeMaxDynamicSharedMemorySize, SMEM_GATE);
    cudaFuncSetAttribute(h_gemm<HEPI_SCATTER, true>,  cudaFuncAttributeMaxDynamicSharedMemorySize, SMEM_HGEMM);
    cudaFuncSetAttribute(h_gemm<HEPI_F32,     false>, cudaFuncAttributeMaxDynamicSharedMemorySize, SMEM_HGEMM);

    // fused conversions + counter/logit zeroing + tb3 table
    prep_kernel<<<PREP_BLOCKS, 256>>>(x, gw1, gw2, ew, ow, gb3, temb, tw, tb);

    // gating layer 1 (bf16 3-term) -> h1 split
    mma_gemm<EPI_RELU_SPLIT><<<dim3(GHA / 128, NT / 128), 512, SMEM_GEMM>>>(
        xhi, xlo, w1hi, w1lo, gb1, nullptr, h1hi, h1lo, GHA, DD);

    // gating layer 2 (bf16 3-term) + fused logit projection -> g_logit
    mma_gemm<EPI_GATE><<<dim3(GHB / 128, NT / 128), 512, SMEM_GATE>>>(
        h1hi, h1lo, w2hi, w2lo, gb2, gw3, nullptr, nullptr, GHB, GHA);

    // routing: precomputed tb3 + top2 + two-level atomics
    routing_kernel<<<NT / 256, 256>>>(ft);

    // expert grouped GEMM (fp16, gathered A, scattered fp16 C)
    h_gemm<HEPI_SCATTER, true><<<dim3(HH / 128, MAX_MTILES), 512, SMEM_HGEMM>>>(
        xh, ewh, eb, nullptr, pairh, HH, DD);

    // combine + relu -> fp16
    combine_kernel<<<(NT * HH / 2) / 256, 256>>>();

    // output projection (fp16)
    h_gemm<HEPI_F32, false><<<dim3(DD / 128, NT / 128), 512, SMEM_HGEMM>>>(
        mh, owh, ob, out, nullptr, DD, HH);
}

// round 13
// speedup vs baseline: 5.2209x; 1.0006x over previous
#include <cuda_runtime.h>
#include <cuda_bf16.h>
#include <cuda_fp16.h>
#include <cstdint>

#define NT   8192
#define DD   1024
#define GHA  512
#define GHB  256
#define NE   8
#define HH   2048
#define MAX_MTILES 136

typedef __nv_bfloat16 bf16;

// ---------------- scratch ---------------------------------------------------
__device__ bf16  g_xhi[NT * DD],  g_xlo[NT * DD];
__device__ bf16  g_h1hi[NT * GHA], g_h1lo[NT * GHA];
__device__ bf16  g_w1hi[GHA * DD], g_w1lo[GHA * DD];
__device__ bf16  g_w2hi[GHB * GHA], g_w2lo[GHB * GHA];
__device__ __half g_xh[NT * DD];
__device__ __half g_ewh[(size_t)NE * HH * DD];             // [E][H][D]
__device__ __half g_owh[(size_t)DD * HH];                  // [D][H]
__device__ __half g_mh[(size_t)NT * HH];
__device__ __half g_pairh[(size_t)NT * 2 * HH];
__device__ float g_logit[NT * NE];
__device__ float g_tb3[3 * NE];
__device__ float g_wval[NT * 2];
__device__ int   g_cnt[NE];
__device__ int   g_list[NE * NT];

// ---------------- PTX helpers (sm_80+ baseline only) ------------------------
__device__ __forceinline__ uint32_t smem_u32(const void* p) {
    uint32_t a;
    asm("{ .reg .u64 t; cvta.to.shared.u64 t, %1; cvt.u32.u64 %0, t; }" : "=r"(a) : "l"(p));
    return a;
}
__device__ __forceinline__ void cp16(uint32_t s, const void* g) {
    asm volatile("cp.async.cg.shared.global [%0], [%1], 16;" :: "r"(s), "l"(g));
}
#define CP_COMMIT() asm volatile("cp.async.commit_group;" ::: "memory")
#define CP_WAIT1()  asm volatile("cp.async.wait_group 1;" ::: "memory")
#define CP_WAIT0()  asm volatile("cp.async.wait_group 0;" ::: "memory")

__device__ __forceinline__ void ldsm_x4(uint32_t* r, uint32_t a) {
    asm volatile("ldmatrix.sync.aligned.m8n8.x4.shared.b16 {%0,%1,%2,%3}, [%4];"
        : "=r"(r[0]), "=r"(r[1]), "=r"(r[2]), "=r"(r[3]) : "r"(a));
}
__device__ __forceinline__ void mma_bf16(float* c, const uint32_t* a, const uint32_t* b) {
    asm volatile("mma.sync.aligned.m16n8k16.row.col.f32.bf16.bf16.f32 "
        "{%0,%1,%2,%3}, {%4,%5,%6,%7}, {%8,%9}, {%0,%1,%2,%3};"
        : "+f"(c[0]), "+f"(c[1]), "+f"(c[2]), "+f"(c[3])
        : "r"(a[0]), "r"(a[1]), "r"(a[2]), "r"(a[3]), "r"(b[0]), "r"(b[1]));
}
__device__ __forceinline__ void mma_f16(float* c, const uint32_t* a, const uint32_t* b) {
    asm volatile("mma.sync.aligned.m16n8k16.row.col.f32.f16.f16.f32 "
        "{%0,%1,%2,%3}, {%4,%5,%6,%7}, {%8,%9}, {%0,%1,%2,%3};"
        : "+f"(c[0]), "+f"(c[1]), "+f"(c[2]), "+f"(c[3])
        : "r"(a[0]), "r"(a[1]), "r"(a[2]), "r"(a[3]), "r"(b[0]), "r"(b[1]));
}

// ---------------- fused prep kernel ------------------------------------------
#define PREP_BLOCKS 27265

__global__ void __launch_bounds__(256) prep_kernel(
    const float* __restrict__ x, const float* __restrict__ gw1,
    const float* __restrict__ gw2, const float* __restrict__ ew,
    const float* __restrict__ ow,
    const float* __restrict__ gb3, const float* __restrict__ temb,
    const float* __restrict__ tw, const float* __restrict__ tb) {
    __shared__ float t[32][33];
    int b = blockIdx.x;
    const int tid = threadIdx.x;

    if (b == PREP_BLOCKS - 1) {
        if (tid < 192) {
            const int p = tid >> 3;
            const int s = tid & 7;
            const int ty = p / NE, e = p % NE;
            float sum = 0.f;
            #pragma unroll
            for (int k = 0; k < 16; k++) {
                int j = s + (k << 3);
                sum += temb[ty * 128 + j] * tw[j * NE + e];
            }
            #pragma unroll
            for (int off = 4; off; off >>= 1)
                sum += __shfl_down_sync(0xffffffffu, sum, off);
            if (s == 0) g_tb3[p] = sum + gb3[e] + tb[e];
        }
        return;
    }

    if (b < 8192) {
        if (b == 0 && tid < NE) g_cnt[tid] = 0;
        if (b < 64) {
            ((float4*)g_logit)[b * 256 + tid] = make_float4(0.f, 0.f, 0.f, 0.f);
        }
        int i4 = b * 256 + tid;
        float4 v = ((const float4*)x)[i4];
        float f[4] = {v.x, v.y, v.z, v.w};
        bf16 bh[4]; bf16 bl[4]; __half hh[4];
        #pragma unroll
        for (int k = 0; k < 4; k++) {
            bh[k] = __float2bfloat16(f[k]);
            bl[k] = __float2bfloat16(f[k] - __bfloat162float(bh[k]));
            hh[k] = __float2half(f[k]);
        }
        __nv_bfloat162* xhi2 = (__nv_bfloat162*)g_xhi;
        __nv_bfloat162* xlo2 = (__nv_bfloat162*)g_xlo;
        __half2* xh2 = (__half2*)g_xh;
        xhi2[2 * i4 + 0] = __nv_bfloat162(bh[0], bh[1]);
        xhi2[2 * i4 + 1] = __nv_bfloat162(bh[2], bh[3]);
        xlo2[2 * i4 + 0] = __nv_bfloat162(bl[0], bl[1]);
        xlo2[2 * i4 + 1] = __nv_bfloat162(bl[2], bl[3]);
        xh2[2 * i4 + 0] = __half2(hh[0], hh[1]);
        xh2[2 * i4 + 1] = __half2(hh[2], hh[3]);
        return;
    }
    b -= 8192;

    const float* in;
    bf16 *ohi = nullptr, *olo = nullptr;
    __half* oh = nullptr;
    int R, C, bx, by;
    size_t zoff = 0;
    bool half_mode;
    if (b < 512) {
        half_mode = false; in = gw1; ohi = g_w1hi; olo = g_w1lo;
        R = DD; C = GHA; bx = b % 16; by = b / 16;
    } else if (b < 640) {
        b -= 512;
        half_mode = false; in = gw2; ohi = g_w2hi; olo = g_w2lo;
        R = GHA; C = GHB; bx = b % 8; by = b / 8;
    } else if (b < 640 + 16384) {
        b -= 640;
        half_mode = true; in = ew; oh = g_ewh;
        R = DD; C = HH; bx = b % 64; by = (b / 64) % 32;
        zoff = (size_t)(b / (64 * 32)) * R * C;
    } else {
        b -= 640 + 16384;
        half_mode = true; in = ow; oh = g_owh;
        R = HH; C = DD; bx = b % 32; by = b / 32;
    }
    in += zoff;
    const int c0 = bx * 32, r0 = by * 32;
    const int tx = tid & 31, ty = tid >> 5;
    for (int i = ty; i < 32; i += 8)
        t[i][tx] = in[(size_t)(r0 + i) * C + c0 + tx];
    __syncthreads();
    if (half_mode) {
        oh += zoff;
        for (int i = ty; i < 32; i += 8)
            oh[(size_t)(c0 + i) * R + r0 + tx] = __float2half(t[tx][i]);
    } else {
        for (int i = ty; i < 32; i += 8) {
            float v = t[tx][i];
            bf16 h = __float2bfloat16(v);
            size_t o = (size_t)(c0 + i) * R + r0 + tx;
            ohi[o] = h;
            olo[o] = __float2bfloat16(v - __bfloat162float(h));
        }
    }
}

// ---------------- routing: two-level atomics ---------------------------------
__global__ void __launch_bounds__(256) routing_kernel(const int* __restrict__ ftypes) {
    __shared__ float s_tb3[3 * NE];
    __shared__ int s_cnt[NE];
    __shared__ int s_base[NE];
    const int tid = threadIdx.x;
    if (tid < 3 * NE) s_tb3[tid] = g_tb3[tid];
    if (tid < NE) s_cnt[tid] = 0;
    __syncthreads();
    const int t = blockIdx.x * 256 + tid;
    float4 l0 = ((const float4*)g_logit)[t * 2 + 0];
    float4 l1 = ((const float4*)g_logit)[t * 2 + 1];
    float logits[NE] = {l0.x, l0.y, l0.z, l0.w, l1.x, l1.y, l1.z, l1.w};
    int ftv = ftypes[t];
    #pragma unroll
    for (int e = 0; e < NE; e++) logits[e] += s_tb3[ftv * NE + e];
    int i0 = 0;
    #pragma unroll
    for (int e = 1; e < NE; e++) if (logits[e] > logits[i0]) i0 = e;
    int i1 = (i0 == 0) ? 1 : 0;
    #pragma unroll
    for (int e = 0; e < NE; e++) {
        if (e == i0 || e == i1) continue;
        if (logits[e] > logits[i1]) i1 = e;
    }
    float r = expf(logits[i1] - logits[i0]);
    float inv = 1.f / (1.f + r);
    g_wval[t * 2 + 0] = inv;
    g_wval[t * 2 + 1] = r * inv;
    int p0 = atomicAdd(&s_cnt[i0], 1);
    int p1 = atomicAdd(&s_cnt[i1], 1);
    __syncthreads();
    if (tid < NE) s_base[tid] = atomicAdd(&g_cnt[tid], s_cnt[tid]);
    __syncthreads();
    g_list[i0 * NT + s_base[i0] + p0] = t * 2 + 0;
    g_list[i1 * NT + s_base[i1] + p1] = t * 2 + 1;
}

// ================= bf16 3-term GEMM (gating), 2-stage, occ 2 =================
#define EPI_RELU_SPLIT 0
#define EPI_GATE       1

#define ROWB      80
#define TILES_OFF 2048
#define STAGE_SZ  40960
#define OA_HI 0
#define OA_LO 10240
#define OB_HI 20480
#define OB_LO 30720
#define GATE_OFF  (TILES_OFF + 2 * STAGE_SZ)
#define SMEM_GEMM GATE_OFF                       // 83968
#define SMEM_GATE (GATE_OFF + GHB * NE * 4)      // 92160

template<int MODE>
__global__ void __launch_bounds__(512, 2) mma_gemm(
    const bf16* __restrict__ Ahi, const bf16* __restrict__ Alo,
    const bf16* __restrict__ Bhi, const bf16* __restrict__ Blo,
    const float* __restrict__ bias, const float* __restrict__ gw3,
    bf16* __restrict__ outhi, bf16* __restrict__ outlo,
    int N, int K) {
    extern __shared__ char smem[];
    const int tid = threadIdx.x, lane = tid & 31, wid = tid >> 5;
    const int wm = wid >> 2, wn = wid & 3;
    const int nb = blockIdx.x;
    const int mtile = blockIdx.y;

    float* s_g3 = (float*)(smem + GATE_OFF);
    if (MODE == EPI_GATE) {
        for (int i = tid; i < GHB * NE; i += 512) s_g3[i] = gw3[i];
    }

    const uint32_t sb = smem_u32(smem) + TILES_OFF;

    const int seg = tid & 3;
    const int row = tid >> 2;
    size_t arow = (size_t)mtile * 128 + row;
    size_t brow = (size_t)nb * 128 + row;
    const bf16* pAh = Ahi + arow * K + seg * 8;
    const bf16* pAl = Alo + arow * K + seg * 8;
    const bf16* pBh = Bhi + brow * K + seg * 8;
    const bf16* pBl = Blo + brow * K + seg * 8;
    const uint32_t so = row * ROWB + seg * 16;

    float acc[2][4][4] = {};
    const int niter = K >> 5;

    {
        cp16(sb + OA_HI + so, pAh);
        cp16(sb + OA_LO + so, pAl);
        cp16(sb + OB_HI + so, pBh);
        cp16(sb + OB_LO + so, pBl);
        CP_COMMIT();
    }

    for (int it = 0; it < niter; it++) {
        CP_WAIT0();
        __syncthreads();
        {
            const int s = it + 1;
            if (s < niter) {
                const uint32_t st = sb + (s & 1) * STAGE_SZ;
                const int ko = s << 5;
                cp16(st + OA_HI + so, pAh + ko);
                cp16(st + OA_LO + so, pAl + ko);
                cp16(st + OB_HI + so, pBh + ko);
                cp16(st + OB_LO + so, pBl + ko);
            }
            CP_COMMIT();
        }

        const uint32_t st = sb + (it & 1) * STAGE_SZ;
        #pragma unroll
        for (int ks = 0; ks < 2; ks++) {
            uint32_t ah[2][4], al[2][4], bx[2][4];
            const int acol = (ks * 16 + (lane >> 4) * 8) * 2;
            #pragma unroll
            for (int mt = 0; mt < 2; mt++) {
                uint32_t ad = st + (wm * 32 + mt * 16 + (lane & 15)) * ROWB + acol;
                ldsm_x4(ah[mt], ad + OA_HI);
                ldsm_x4(al[mt], ad + OA_LO);
            }
            const int bcol = (ks * 16 + ((lane >> 3) & 1) * 8) * 2;
            #pragma unroll
            for (int pr = 0; pr < 2; pr++) {
                uint32_t bd = st + (wn * 32 + pr * 16 + ((lane >> 4) << 3) + (lane & 7)) * ROWB + bcol;
                ldsm_x4(bx[pr], bd + OB_HI);
            }
            #pragma unroll
            for (int mt = 0; mt < 2; mt++)
                #pragma unroll
                for (int nt = 0; nt < 4; nt++) {
                    const uint32_t* bp = &bx[nt >> 1][(nt & 1) * 2];
                    mma_bf16(acc[mt][nt], ah[mt], bp);
                    mma_bf16(acc[mt][nt], al[mt], bp);
                }
            #pragma unroll
            for (int pr = 0; pr < 2; pr++) {
                uint32_t bd = st + (wn * 32 + pr * 16 + ((lane >> 4) << 3) + (lane & 7)) * ROWB + bcol;
                ldsm_x4(bx[pr], bd + OB_LO);
            }
            #pragma unroll
            for (int mt = 0; mt < 2; mt++)
                #pragma unroll
                for (int nt = 0; nt < 4; nt++) {
                    const uint32_t* bp = &bx[nt >> 1][(nt & 1) * 2];
                    mma_bf16(acc[mt][nt], ah[mt], bp);
                }
        }
        __syncthreads();
    }

    if (MODE == EPI_RELU_SPLIT) {
        #pragma unroll
        for (int mt = 0; mt < 2; mt++) {
            #pragma unroll
            for (int half = 0; half < 2; half++) {
                const int mloc = wm * 32 + mt * 16 + half * 8 + (lane >> 2);
                #pragma unroll
                for (int nt = 0; nt < 4; nt++) {
                    const int c0 = nb * 128 + wn * 32 + nt * 8 + (lane & 3) * 2;
                    float v0 = fmaxf(acc[mt][nt][half * 2 + 0] + bias[c0], 0.f);
                    float v1 = fmaxf(acc[mt][nt][half * 2 + 1] + bias[c0 + 1], 0.f);
                    size_t base = (size_t)(mtile * 128 + mloc) * N + c0;
                    bf16 h0 = __float2bfloat16(v0), h1 = __float2bfloat16(v1);
                    outhi[base] = h0; outhi[base + 1] = h1;
                    outlo[base] = __float2bfloat16(v0 - __bfloat162float(h0));
                    outlo[base + 1] = __float2bfloat16(v1 - __bfloat162float(h1));
                }
            }
        }
    } else {
        float p[4][8] = {};
        #pragma unroll
        for (int mt = 0; mt < 2; mt++)
            #pragma unroll
            for (int half = 0; half < 2; half++) {
                const int r = mt * 2 + half;
                #pragma unroll
                for (int nt = 0; nt < 4; nt++)
                    #pragma unroll
                    for (int j = 0; j < 2; j++) {
                        const int cl = wn * 32 + nt * 8 + (lane & 3) * 2 + j;
                        const int c0 = nb * 128 + cl;
                        float v = fmaxf(acc[mt][nt][half * 2 + j] + bias[c0], 0.f);
                        float4 ga = ((const float4*)(s_g3 + c0 * NE))[0];
                        float4 gb = ((const float4*)(s_g3 + c0 * NE))[1];
                        p[r][0] = fmaf(v, ga.x, p[r][0]);
                        p[r][1] = fmaf(v, ga.y, p[r][1]);
                        p[r][2] = fmaf(v, ga.z, p[r][2]);
                        p[r][3] = fmaf(v, ga.w, p[r][3]);
                        p[r][4] = fmaf(v, gb.x, p[r][4]);
                        p[r][5] = fmaf(v, gb.y, p[r][5]);
                        p[r][6] = fmaf(v, gb.z, p[r][6]);
                        p[r][7] = fmaf(v, gb.w, p[r][7]);
                    }
            }
        #pragma unroll
        for (int r = 0; r < 4; r++)
            #pragma unroll
            for (int e = 0; e < NE; e++) {
                p[r][e] += __shfl_xor_sync(0xffffffffu, p[r][e], 1);
                p[r][e] += __shfl_xor_sync(0xffffffffu, p[r][e], 2);
            }
        if ((lane & 3) == 0) {
            #pragma unroll
            for (int r = 0; r < 4; r++) {
                const int mloc = wm * 32 + (r >> 1) * 16 + (r & 1) * 8 + (lane >> 2);
                const int tok = mtile * 128 + mloc;
                #pragma unroll
                for (int e = 0; e < NE; e++)
                    atomicAdd(&g_logit[tok * NE + e], p[r][e]);
            }
        }
    }
}

// ========== plain fp16 GEMM (expert + outproj), 3-stage WAIT1, occ 2 =========
#define HEPI_SCATTER 0
#define HEPI_F32     1

#define HROWB     144
#define HSTAGE_SZ 36864
#define HNSTAGE   3
#define HOA 0
#define HOB 18432
#define SMEM_HGEMM (TILES_OFF + HNSTAGE * HSTAGE_SZ)   // 112640

template<int MODE, bool GATHER>
__global__ void __launch_bounds__(512, 2) h_gemm(
    const __half* __restrict__ A,
    const __half* __restrict__ W,
    const float* __restrict__ bias,
    float* __restrict__ outf, __half* __restrict__ outh, int N, int K) {
    extern __shared__ char smem[];
    int* s_pid = (int*)smem;
    int* s_tok = (int*)(smem + 512);
    const int tid = threadIdx.x, lane = tid & 31, wid = tid >> 5;
    const int wm = wid >> 2, wn = wid & 3;
    const int nb = blockIdx.x;

    int mtile = blockIdx.y, e = 0;
    if (GATHER) {
        int flat = blockIdx.y, base = 0, cnt = 0;
        bool found = false;
        #pragma unroll
        for (int i = 0; i < NE; i++) {
            int c = g_cnt[i];
            int tiles = (c + 127) >> 7;
            if (!found && flat < base + tiles) { e = i; mtile = flat - base; cnt = c; found = true; }
            base += tiles;
        }
        if (!found) return;
        if (tid < 128) {
            int idx = mtile * 128 + tid;
            int pid = (idx < cnt) ? g_list[e * NT + idx] : -1;
            s_pid[tid] = pid;
            s_tok[tid] = (pid >= 0) ? (pid >> 1) : 0;
        }
        W += (size_t)e * HH * DD;
        bias += (size_t)e * HH;
        __syncthreads();
    }

    const uint32_t sb = smem_u32(smem) + TILES_OFF;

    const int seg = tid & 3;
    const int row = tid >> 2;
    size_t arow = GATHER ? (size_t)s_tok[row] : ((size_t)mtile * 128 + row);
    size_t brow = (size_t)nb * 128 + row;
    const __half* pA = A + arow * K + seg * 8;
    const __half* pB = W + brow * K + seg * 8;
    const uint32_t so = row * HROWB + seg * 16;

    float acc[2][4][4] = {};
    const int niter = K >> 6;

    // prologue: stages 0, 1
    #pragma unroll
    for (int s = 0; s < 2; s++) {
        if (s < niter) {
            const uint32_t st = sb + s * HSTAGE_SZ;
            const int ko = s << 6;
            cp16(st + HOA + so,      pA + ko);
            cp16(st + HOA + so + 64, pA + ko + 32);
            cp16(st + HOB + so,      pB + ko);
            cp16(st + HOB + so + 64, pB + ko + 32);
        }
        CP_COMMIT();
    }

    int cur = 0, nxt2 = 2;          // (it % 3) and ((it+2) % 3)
    for (int it = 0; it < niter; it++) {
        CP_WAIT1();
        __syncthreads();
        {
            const int s = it + 2;
            if (s < niter) {
                const uint32_t st = sb + nxt2 * HSTAGE_SZ;
                const int ko = s << 6;
                cp16(st + HOA + so,      pA + ko);
                cp16(st + HOA + so + 64, pA + ko + 32);
                cp16(st + HOB + so,      pB + ko);
                cp16(st + HOB + so + 64, pB + ko + 32);
            }
            CP_COMMIT();
        }

        const uint32_t st = sb + cur * HSTAGE_SZ;
        #pragma unroll
        for (int ks = 0; ks < 4; ks++) {
            uint32_t ah[2][4], bb[2][4];
            const int acol = (ks * 16 + (lane >> 4) * 8) * 2;
            #pragma unroll
            for (int mt = 0; mt < 2; mt++) {
                uint32_t ad = st + (wm * 32 + mt * 16 + (lane & 15)) * HROWB + acol;
                ldsm_x4(ah[mt], ad + HOA);
            }
            const int bcol = (ks * 16 + ((lane >> 3) & 1) * 8) * 2;
            #pragma unroll
            for (int pr = 0; pr < 2; pr++) {
                uint32_t bd = st + (wn * 32 + pr * 16 + ((lane >> 4) << 3) + (lane & 7)) * HROWB + bcol;
                ldsm_x4(bb[pr], bd + HOB);
            }
            #pragma unroll
            for (int mt = 0; mt < 2; mt++)
                #pragma unroll
                for (int nt = 0; nt < 4; nt++) {
                    const uint32_t* bp = &bb[nt >> 1][(nt & 1) * 2];
                    mma_f16(acc[mt][nt], ah[mt], bp);
                }
        }
        cur = (cur == 2) ? 0 : cur + 1;
        nxt2 = (nxt2 == 2) ? 0 : nxt2 + 1;
    }

    #pragma unroll
    for (int mt = 0; mt < 2; mt++) {
        #pragma unroll
        for (int half = 0; half < 2; half++) {
            const int mloc = wm * 32 + mt * 16 + half * 8 + (lane >> 2);
            int pid = 0;
            if (GATHER) { pid = s_pid[mloc]; if (pid < 0) continue; }
            #pragma unroll
            for (int nt = 0; nt < 4; nt++) {
                const int c0 = nb * 128 + wn * 32 + nt * 8 + (lane & 3) * 2;
                float v0 = acc[mt][nt][half * 2 + 0] + bias[c0];
                float v1 = acc[mt][nt][half * 2 + 1] + bias[c0 + 1];
                if (MODE == HEPI_SCATTER) {
                    __half2* dst = (__half2*)(outh + (size_t)pid * HH + c0);
                    *dst = __floats2half2_rn(v0, v1);
                } else {
                    size_t base = (size_t)(mtile * 128 + mloc) * N + c0;
                    outf[base] = v0; outf[base + 1] = v1;
                }
            }
        }
    }
}

// ---------------- combine: moe = relu(w0*p0 + w1*p1) -> fp16 (half2) ---------
__global__ void combine_kernel() {
    int idx = blockIdx.x * blockDim.x + threadIdx.x;   // over NT*HH/2
    int t = idx >> 10;
    int c = idx & 1023;
    float w0 = g_wval[2 * t], w1 = g_wval[2 * t + 1];
    const __half2* p = (const __half2*)g_pairh;
    float2 a = __half22float2(p[(size_t)t * HH + c]);
    float2 b = __half22float2(p[(size_t)t * HH + (HH / 2) + c]);
    float v0 = fmaxf(fmaf(w0, a.x, w1 * b.x), 0.f);
    float v1 = fmaxf(fmaf(w0, a.y, w1 * b.y), 0.f);
    ((__half2*)g_mh)[idx] = __floats2half2_rn(v0, v1);
}

// ---------------- launch ------------------------------------------------------
extern "C" void kernel_launch(void* const* d_in, const int* in_sizes, int n_in,
                              void* d_out, int out_size) {
    const float* x    = (const float*)d_in[0];
    const int*   ft   = (const int*)  d_in[1];
    const float* gw1  = (const float*)d_in[2];
    const float* gb1  = (const float*)d_in[3];
    const float* gw2  = (const float*)d_in[4];
    const float* gb2  = (const float*)d_in[5];
    const float* gw3  = (const float*)d_in[6];
    const float* gb3  = (const float*)d_in[7];
    const float* temb = (const float*)d_in[8];
    const float* tw   = (const float*)d_in[9];
    const float* tb   = (const float*)d_in[10];
    const float* ew   = (const float*)d_in[11];
    const float* eb   = (const float*)d_in[12];
    const float* ow   = (const float*)d_in[13];
    const float* ob   = (const float*)d_in[14];
    float* out = (float*)d_out;

    bf16 *xhi, *xlo, *h1hi, *h1lo, *w1hi, *w1lo, *w2hi, *w2lo;
    __half *xh, *ewh, *owh, *mh, *pairh;
    cudaGetSymbolAddress((void**)&xhi, g_xhi);   cudaGetSymbolAddress((void**)&xlo, g_xlo);
    cudaGetSymbolAddress((void**)&h1hi, g_h1hi); cudaGetSymbolAddress((void**)&h1lo, g_h1lo);
    cudaGetSymbolAddress((void**)&w1hi, g_w1hi); cudaGetSymbolAddress((void**)&w1lo, g_w1lo);
    cudaGetSymbolAddress((void**)&w2hi, g_w2hi); cudaGetSymbolAddress((void**)&w2lo, g_w2lo);
    cudaGetSymbolAddress((void**)&xh, g_xh);
    cudaGetSymbolAddress((void**)&ewh, g_ewh);   cudaGetSymbolAddress((void**)&owh, g_owh);
    cudaGetSymbolAddress((void**)&mh, g_mh);     cudaGetSymbolAddress((void**)&pairh, g_pairh);

    cudaFuncSetAttribute(mma_gemm<EPI_RELU_SPLIT>, cudaFuncAttributeMaxDynamicSharedMemorySize, SMEM_GEMM);
    cudaFuncSetAttribute(mma_gemm<EPI_GATE>,       cudaFuncAttributeMaxDynamicSharedMemorySize, SMEM_GATE);
    cudaFuncSetAttribute(h_gemm<HEPI_SCATTER, true>,  cudaFuncAttributeMaxDynamicSharedMemorySize, SMEM_HGEMM);
    cudaFuncSetAttribute(h_gemm<HEPI_F32,     false>, cudaFuncAttributeMaxDynamicSharedMemorySize, SMEM_HGEMM);

    // fused conversions + counter/logit zeroing + tb3 table
    prep_kernel<<<PREP_BLOCKS, 256>>>(x, gw1, gw2, ew, ow, gb3, temb, tw, tb);

    // gating layer 1 (bf16 3-term) -> h1 split
    mma_gemm<EPI_RELU_SPLIT><<<dim3(GHA / 128, NT / 128), 512, SMEM_GEMM>>>(
        xhi, xlo, w1hi, w1lo, gb1, nullptr, h1hi, h1lo, GHA, DD);

    // gating layer 2 (bf16 3-term) + fused logit projection -> g_logit
    mma_gemm<EPI_GATE><<<dim3(GHB / 128, NT / 128), 512, SMEM_GATE>>>(
        h1hi, h1lo, w2hi, w2lo, gb2, gw3, nullptr, nullptr, GHB, GHA);

    // routing: precomputed tb3 + top2 + two-level atomics
    routing_kernel<<<NT / 256, 256>>>(ft);

    // expert grouped GEMM (fp16, gathered A, scattered fp16 C)
    h_gemm<HEPI_SCATTER, true><<<dim3(HH / 128, MAX_MTILES), 512, SMEM_HGEMM>>>(
        xh, ewh, eb, nullptr, pairh, HH, DD);

    // combine + relu -> fp16
    combine_kernel<<<(NT * HH / 2) / 256, 256>>>();

    // output projection (fp16)
    h_gemm<HEPI_F32, false><<<dim3(DD / 128, NT / 128), 512, SMEM_HGEMM>>>(
        mh, owh, ob, out, nullptr, DD, HH);
}